// round 7
// baseline (speedup 1.0000x reference)
#include <cuda_runtime.h>
#include <cuda_fp16.h>
#include <math.h>
#include <stdint.h>

#define NN 50000
#define EE 800000
#define HSTR 136   // fp16 A-tile stride (halves)
#define KSTR 136   // fp16 B-tile stride (halves)
#define ESTR 40    // edge-feature tile stride (halves)
#define TSTR 72    // t_emb tile stride (halves)

// ---- static device scratch ----
__device__ __half g_Psrch[NN * 128];
__device__ __half g_Pdsth[NN * 128];
__device__ float4 g_msg4 [NN * 32];
__device__ float  g_coord[NN * 3];
__device__ float  g_deg  [NN];
// pre-transposed fp16 weights [n][k]
__device__ __half g_We2h[128 * 128];
__device__ __half g_Wx1h[128 * 128];
__device__ __half g_Wh1h[128 * 256];
__device__ __half g_Wh2h[128 * 128];
__device__ __half g_W1ah[128 * 128];
__device__ __half g_W1bh[128 * 128];
__device__ __half g_W1th[128 * 64];
__device__ __half g_WeEh[128 * 16];    // [n][k]: k0=wd, k1..8=We1e, rest 0

__device__ __forceinline__ float silu_f(float v) {
    return v / (1.f + __expf(-v));
}
__device__ __forceinline__ void red_add_v4(float* p, float a, float b, float c, float d) {
    asm volatile("red.global.add.v4.f32 [%0], {%1,%2,%3,%4};"
                 :: "l"(p), "f"(a), "f"(b), "f"(c), "f"(d) : "memory");
}
__device__ __forceinline__ void red_add_f(float* p, float a) {
    asm volatile("red.global.add.f32 [%0], %1;" :: "l"(p), "f"(a) : "memory");
}
__device__ __forceinline__ uint32_t packh2(float a, float b) {
    __half2 h = __floats2half2_rn(a, b);
    return *(uint32_t*)&h;
}
__device__ __forceinline__ void mma_f16(float c[4], const uint32_t a[4], const uint32_t b[2]) {
    asm volatile("mma.sync.aligned.m16n8k16.row.col.f32.f16.f16.f32 "
                 "{%0,%1,%2,%3}, {%4,%5,%6,%7}, {%8,%9}, {%0,%1,%2,%3};"
                 : "+f"(c[0]), "+f"(c[1]), "+f"(c[2]), "+f"(c[3])
                 : "r"(a[0]), "r"(a[1]), "r"(a[2]), "r"(a[3]),
                   "r"(b[0]), "r"(b[1]));
}
__device__ __forceinline__ void ldsm4(uint32_t r[4], uint32_t addr) {
    asm volatile("ldmatrix.sync.aligned.m8n8.x4.shared.b16 {%0,%1,%2,%3}, [%4];"
                 : "=r"(r[0]), "=r"(r[1]), "=r"(r[2]), "=r"(r[3]) : "r"(addr));
}
__device__ __forceinline__ uint32_t s2u(const void* p) {
    return (uint32_t)__cvta_generic_to_shared(p);
}

// stage pre-transposed fp16 weight [128][srcK] slice -> smem [n][KSTR]
__device__ __forceinline__ void stage_wt(const __half* __restrict__ src, int srcK,
                                         int kOff, uint16_t* __restrict__ WsB, int tid) {
    int n = tid >> 1, kh = (tid & 1) * 64;
    const uint16_t* s = (const uint16_t*)src + (size_t)n * srcK + kOff + kh;
    uint16_t* d = WsB + n * KSTR + kh;
#pragma unroll
    for (int q = 0; q < 8; q++)
        *(uint4*)(d + 8 * q) = *(const uint4*)(s + 8 * q);
}
__device__ __forceinline__ void stage_wt64(const __half* __restrict__ src,
                                           uint16_t* __restrict__ WsB, int tid) {
    int n = tid >> 1, kh = (tid & 1) * 32;
    const uint16_t* s = (const uint16_t*)src + (size_t)n * 64 + kh;
    uint16_t* d = WsB + n * KSTR + kh;
#pragma unroll
    for (int q = 0; q < 4; q++)
        *(uint4*)(d + 8 * q) = *(const uint4*)(s + 8 * q);
}

// warp fp16 GEMM via ldmatrix: C[32x64 per warp] += A[128xK] * B(n-major)[N][K]
template<int AS, int BS>
__device__ __forceinline__ void mma_gemm16(const uint16_t* __restrict__ Hs,
                                           const uint16_t* __restrict__ Ws,
                                           int K, int m0, int n0, int lane,
                                           float acc[2][8][4]) {
    int lrow = lane & 7, lmi = lane >> 3;
    // A: matrix mi: bit0 = row-half(+8), bit1 = k-half(+8)
    uint32_t abase = s2u(Hs) +
        (uint32_t)(((m0 + (lmi & 1) * 8 + lrow) * AS + (lmi >> 1) * 8) * 2);
    // B: matrix mi: bit0 = k-half(+8), bit1 = n(+8  -> j+1)
    uint32_t bbase = s2u(Ws) +
        (uint32_t)(((n0 + (lmi >> 1) * 8 + lrow) * BS + (lmi & 1) * 8) * 2);
#pragma unroll
    for (int k0 = 0; k0 < K; k0 += 16) {
        uint32_t b[4][4];
#pragma unroll
        for (int jp = 0; jp < 4; jp++)
            ldsm4(b[jp], bbase + (uint32_t)((16 * jp * BS + k0) * 2));
        uint32_t a[2][4];
#pragma unroll
        for (int mt = 0; mt < 2; mt++)
            ldsm4(a[mt], abase + (uint32_t)((16 * mt * AS + k0) * 2));
#pragma unroll
        for (int mt = 0; mt < 2; mt++)
#pragma unroll
            for (int j = 0; j < 8; j++)
                mma_f16(acc[mt][j], a[mt], &b[j >> 1][(j & 1) * 2]);
    }
}

// ---- zero accumulators ----
__global__ void kZero() {
    float* msg = (float*)g_msg4;
    long total = (long)NN * 128 + NN * 3 + NN;
    for (long i = blockIdx.x * (long)blockDim.x + threadIdx.x; i < total;
         i += (long)gridDim.x * blockDim.x) {
        if (i < (long)NN * 128)             msg[i] = 0.f;
        else if (i < (long)NN * 128 + NN*3) g_coord[i - (long)NN * 128] = 0.f;
        else                                g_deg[i - (long)NN * 128 - NN * 3] = 0.f;
    }
}

// ---- weight transpose + fp16 convert (once per launch) ----
__global__ void kW(const float* __restrict__ We1, const float* __restrict__ We2,
                   const float* __restrict__ Wx1,
                   const float* __restrict__ Wh1, const float* __restrict__ Wh2) {
    int i = blockIdx.x * blockDim.x + threadIdx.x;
    if (i < 16384) {
        int n = i >> 7, k = i & 127;
        g_We2h[i] = __float2half_rn(We2[k * 128 + n]);
        g_Wx1h[i] = __float2half_rn(Wx1[k * 128 + n]);
        g_Wh2h[i] = __float2half_rn(Wh2[k * 128 + n]);
    } else if (i < 49152) {
        int j = i - 16384;
        int n = j >> 8, k = j & 255;
        g_Wh1h[j] = __float2half_rn(Wh1[k * 128 + n]);
    } else if (i < 65536) {
        int j = i - 49152;
        int n = j >> 7, k = j & 127;
        g_W1ah[j] = __float2half_rn(We1[k * 128 + n]);
    } else if (i < 81920) {
        int j = i - 65536;
        int n = j >> 7, k = j & 127;
        g_W1bh[j] = __float2half_rn(We1[(128 + k) * 128 + n]);
    } else if (i < 90112) {
        int j = i - 81920;
        int n = j >> 6, k = j & 63;
        g_W1th[j] = __float2half_rn(We1[(265 + k) * 128 + n]);
    } else if (i < 92160) {
        int j = i - 90112;
        int n = j >> 4, k = j & 15;
        float v = 0.f;
        if (k == 0)      v = We1[256 * 128 + n];
        else if (k <= 8) v = We1[(256 + k) * 128 + n];
        g_WeEh[j] = __float2half_rn(v);
    }
}

// =====================================================================
// Kernel A: per-node precompute (fp16 mma)
// =====================================================================
__global__ __launch_bounds__(256, 2) void kA(const float* __restrict__ h,
                                             const float* __restrict__ temb,
                                             const float* __restrict__ be1) {
    extern __shared__ float sm[];
    uint16_t* HsB = (uint16_t*)sm;
    uint16_t* WsB = HsB + 128 * HSTR;
    uint16_t* Ts  = WsB + 128 * KSTR;
    int tid = threadIdx.x;
    int lane = tid & 31, w = tid >> 5;
    int g4 = lane >> 2, t4 = lane & 3;
    int m0 = (w & 3) * 32, n0 = (w >> 2) * 64;
    int tile0 = blockIdx.x * 128;

    {
        int n = tid >> 1, kh = (tid & 1) * 64;
        int gn = tile0 + n;
        uint16_t* d = HsB + (size_t)n * HSTR + kh;
#pragma unroll
        for (int q = 0; q < 8; q++) {
            float4 v0 = make_float4(0.f,0.f,0.f,0.f), v1 = v0;
            if (gn < NN) {
                v0 = *(const float4*)(h + (size_t)gn * 128 + kh + q * 8);
                v1 = *(const float4*)(h + (size_t)gn * 128 + kh + q * 8 + 4);
            }
            uint4 u;
            u.x = packh2(v0.x, v0.y); u.y = packh2(v0.z, v0.w);
            u.z = packh2(v1.x, v1.y); u.w = packh2(v1.z, v1.w);
            *(uint4*)(d + 8 * q) = u;
        }
    }
    {
        int n = tid >> 1, kh = (tid & 1) * 32;
        int gn = tile0 + n;
        uint16_t* d = Ts + (size_t)n * TSTR + kh;
#pragma unroll
        for (int q = 0; q < 4; q++) {
            float4 v0 = make_float4(0.f,0.f,0.f,0.f), v1 = v0;
            if (gn < NN) {
                v0 = *(const float4*)(temb + (size_t)gn * 64 + kh + q * 8);
                v1 = *(const float4*)(temb + (size_t)gn * 64 + kh + q * 8 + 4);
            }
            uint4 u;
            u.x = packh2(v0.x, v0.y); u.y = packh2(v0.z, v0.w);
            u.z = packh2(v1.x, v1.y); u.w = packh2(v1.z, v1.w);
            *(uint4*)(d + 8 * q) = u;
        }
    }
    stage_wt(g_W1ah, 128, 0, WsB, tid);
    __syncthreads();

    float acc[2][8][4];
#pragma unroll
    for (int mt = 0; mt < 2; mt++)
#pragma unroll
        for (int j = 0; j < 8; j++)
#pragma unroll
            for (int q = 0; q < 4; q++) acc[mt][j][q] = 0.f;
    mma_gemm16<HSTR,KSTR>(HsB, WsB, 128, m0, n0, lane, acc);
    __syncthreads();
    stage_wt64(g_W1th, WsB, tid);
    __syncthreads();
    mma_gemm16<TSTR,KSTR>(Ts, WsB, 64, m0, n0, lane, acc);

#pragma unroll
    for (int mt = 0; mt < 2; mt++) {
        int rA = m0 + 16 * mt + g4;
        int gnA = tile0 + rA, gnB = gnA + 8;
#pragma unroll
        for (int j = 0; j < 8; j++) {
            int c = n0 + 8 * j + 2 * t4;
            float2 bb = *(const float2*)(be1 + c);
            if (gnA < NN)
                *(uint32_t*)((uint16_t*)g_Psrch + (size_t)gnA * 128 + c) =
                    packh2(acc[mt][j][0] + bb.x, acc[mt][j][1] + bb.y);
            if (gnB < NN)
                *(uint32_t*)((uint16_t*)g_Psrch + (size_t)gnB * 128 + c) =
                    packh2(acc[mt][j][2] + bb.x, acc[mt][j][3] + bb.y);
        }
    }
    __syncthreads();
    stage_wt(g_W1bh, 128, 0, WsB, tid);
    __syncthreads();
#pragma unroll
    for (int mt = 0; mt < 2; mt++)
#pragma unroll
        for (int j = 0; j < 8; j++)
#pragma unroll
            for (int q = 0; q < 4; q++) acc[mt][j][q] = 0.f;
    mma_gemm16<HSTR,KSTR>(HsB, WsB, 128, m0, n0, lane, acc);
#pragma unroll
    for (int mt = 0; mt < 2; mt++) {
        int rA = m0 + 16 * mt + g4;
        int gnA = tile0 + rA, gnB = gnA + 8;
#pragma unroll
        for (int j = 0; j < 8; j++) {
            int c = n0 + 8 * j + 2 * t4;
            if (gnA < NN)
                *(uint32_t*)((uint16_t*)g_Pdsth + (size_t)gnA * 128 + c) =
                    packh2(acc[mt][j][0], acc[mt][j][1]);
            if (gnB < NN)
                *(uint32_t*)((uint16_t*)g_Pdsth + (size_t)gnB * 128 + c) =
                    packh2(acc[mt][j][2], acc[mt][j][3]);
        }
    }
}

// =====================================================================
// Kernel B: fused edge pipeline, 128 edges per block
// =====================================================================
__global__ __launch_bounds__(256, 2) void kB(const float* __restrict__ x,
                                             const float* __restrict__ ea,
                                             const int* __restrict__ eidx,
                                             const float* __restrict__ be2,
                                             const float* __restrict__ Watt,
                                             const float* __restrict__ batt,
                                             const float* __restrict__ bx1,
                                             const float* __restrict__ Wx2,
                                             const float* __restrict__ bx2) {
    extern __shared__ float sm[];
    uint16_t* HsB = (uint16_t*)sm;
    uint16_t* WsB = HsB + 128 * HSTR;
    uint16_t* Es  = WsB + 128 * KSTR;
    uint16_t* Wes = Es + 128 * ESTR;
    float* red_s  = (float*)(Wes + 128 * ESTR);
    float* watt_s = red_s + 256;
    float* be2_s  = watt_s + 128;
    float* bx1_s  = be2_s + 128;
    float* wx2_s  = bx1_s + 128;
    float* att_s  = wx2_s + 128;
    float* diff_s = att_s + 128;
    int* src_s = (int*)(diff_s + 384);
    int* dst_s = src_s + 128;

    int tid = threadIdx.x;
    int lane = tid & 31, w = tid >> 5;
    int g4 = lane >> 2, t4 = lane & 3;
    int m0 = (w & 3) * 32, n0 = (w >> 2) * 64;
    int e0 = blockIdx.x * 128;

    if (tid < 128) {
        int e = e0 + tid;
        int s = eidx[e], d = eidx[EE + e];
        src_s[tid] = s; dst_s[tid] = d;
        float dx = x[s * 3 + 0] - x[d * 3 + 0];
        float dy = x[s * 3 + 1] - x[d * 3 + 1];
        float dz = x[s * 3 + 2] - x[d * 3 + 2];
        diff_s[tid * 3 + 0] = dx; diff_s[tid * 3 + 1] = dy; diff_s[tid * 3 + 2] = dz;
        float dsq = dx * dx + dy * dy + dz * dz;
        watt_s[tid] = Watt[tid];
        be2_s[tid]  = be2[tid];
        bx1_s[tid]  = bx1[tid];
        wx2_s[tid]  = Wx2[tid];
        float4 a0 = *(const float4*)(ea + (size_t)e * 8);
        float4 a1 = *(const float4*)(ea + (size_t)e * 8 + 4);
        uint4 u0, u1;
        u0.x = packh2(dsq,  a0.x); u0.y = packh2(a0.y, a0.z);
        u0.z = packh2(a0.w, a1.x); u0.w = packh2(a1.y, a1.z);
        u1.x = packh2(a1.w, 0.f);  u1.y = 0u; u1.z = 0u; u1.w = 0u;
        *(uint4*)(Es + tid * ESTR) = u0;
        *(uint4*)(Es + tid * ESTR + 8) = u1;
    }
    {
        int n = tid >> 1, half = tid & 1;
        *(uint4*)(Wes + n * ESTR + half * 8) =
            *(const uint4*)((const uint16_t*)g_WeEh + n * 16 + half * 8);
    }
    stage_wt(g_We2h, 128, 0, WsB, tid);
    __syncthreads();

    {   // gather Ps_sum = Psrc[src] + Pdst[dst] (fp16) -> HsB
        int e = tid >> 1, j0 = (tid & 1) * 64;
        int s = src_s[e], d = dst_s[e];
        const uint4* ps = (const uint4*)((const uint16_t*)g_Psrch + (size_t)s * 128 + j0);
        const uint4* pd = (const uint4*)((const uint16_t*)g_Pdsth + (size_t)d * 128 + j0);
        uint16_t* dp = HsB + (size_t)e * HSTR + j0;
#pragma unroll
        for (int q = 0; q < 8; q++) {
            uint4 a = ps[q], b = pd[q];
            uint4 r;
            *(__half2*)&r.x = __hadd2(*(__half2*)&a.x, *(__half2*)&b.x);
            *(__half2*)&r.y = __hadd2(*(__half2*)&a.y, *(__half2*)&b.y);
            *(__half2*)&r.z = __hadd2(*(__half2*)&a.z, *(__half2*)&b.z);
            *(__half2*)&r.w = __hadd2(*(__half2*)&a.w, *(__half2*)&b.w);
            *(uint4*)(dp + 8 * q) = r;
        }
    }
    __syncthreads();

    float acc[2][8][4];
#pragma unroll
    for (int mt = 0; mt < 2; mt++)
#pragma unroll
        for (int j = 0; j < 8; j++)
#pragma unroll
            for (int q = 0; q < 4; q++) acc[mt][j][q] = 0.f;
    mma_gemm16<ESTR,ESTR>(Es, Wes, 16, m0, n0, lane, acc);

    // epilogue0: hidden = silu(acc + Ps_sum), in place in HsB
#pragma unroll
    for (int mt = 0; mt < 2; mt++) {
        int rA = m0 + 16 * mt + g4, rB = rA + 8;
#pragma unroll
        for (int j = 0; j < 8; j++) {
            int c = n0 + 8 * j + 2 * t4;
            uint32_t ua = *(uint32_t*)(HsB + (size_t)rA * HSTR + c);
            uint32_t ub = *(uint32_t*)(HsB + (size_t)rB * HSTR + c);
            float2 fa = __half22float2(*(__half2*)&ua);
            float2 fb = __half22float2(*(__half2*)&ub);
            *(uint32_t*)(HsB + (size_t)rA * HSTR + c) =
                packh2(silu_f(acc[mt][j][0] + fa.x), silu_f(acc[mt][j][1] + fa.y));
            *(uint32_t*)(HsB + (size_t)rB * HSTR + c) =
                packh2(silu_f(acc[mt][j][2] + fb.x), silu_f(acc[mt][j][3] + fb.y));
        }
    }
    __syncthreads();

    // GEMM1: m = hidden @ We2
#pragma unroll
    for (int mt = 0; mt < 2; mt++)
#pragma unroll
        for (int j = 0; j < 8; j++)
#pragma unroll
            for (int q = 0; q < 4; q++) acc[mt][j][q] = 0.f;
    mma_gemm16<HSTR,KSTR>(HsB, WsB, 128, m0, n0, lane, acc);

    float pA[2], pB[2];
#pragma unroll
    for (int mt = 0; mt < 2; mt++) {
        pA[mt] = 0.f; pB[mt] = 0.f;
#pragma unroll
        for (int j = 0; j < 8; j++) {
            int c = n0 + 8 * j + 2 * t4;
            float b0 = be2_s[c], b1 = be2_s[c + 1];
            float w0 = watt_s[c], w1 = watt_s[c + 1];
            acc[mt][j][0] += b0; acc[mt][j][1] += b1;
            acc[mt][j][2] += b0; acc[mt][j][3] += b1;
            pA[mt] = fmaf(acc[mt][j][0], w0, fmaf(acc[mt][j][1], w1, pA[mt]));
            pB[mt] = fmaf(acc[mt][j][2], w0, fmaf(acc[mt][j][3], w1, pB[mt]));
        }
        pA[mt] += __shfl_xor_sync(0xffffffffu, pA[mt], 1);
        pA[mt] += __shfl_xor_sync(0xffffffffu, pA[mt], 2);
        pB[mt] += __shfl_xor_sync(0xffffffffu, pB[mt], 1);
        pB[mt] += __shfl_xor_sync(0xffffffffu, pB[mt], 2);
        if (t4 == 0) {
            red_s[(m0 + 16 * mt + g4) * 2 + (w >> 2)] = pA[mt];
            red_s[(m0 + 16 * mt + g4 + 8) * 2 + (w >> 2)] = pB[mt];
        }
    }
    __syncthreads();
    if (tid < 128) {
        float s = red_s[tid * 2] + red_s[tid * 2 + 1] + batt[0];
        att_s[tid] = 1.f / (1.f + __expf(-s));
    }
    __syncthreads();

#pragma unroll
    for (int mt = 0; mt < 2; mt++) {
        int rA = m0 + 16 * mt + g4;
        float aA = att_s[rA], aB = att_s[rA + 8];
#pragma unroll
        for (int j = 0; j < 8; j++) {
            int c = n0 + 8 * j + 2 * t4;
            *(uint32_t*)(HsB + (size_t)rA * HSTR + c) =
                packh2(acc[mt][j][0] * aA, acc[mt][j][1] * aA);
            *(uint32_t*)(HsB + (size_t)(rA + 8) * HSTR + c) =
                packh2(acc[mt][j][2] * aB, acc[mt][j][3] * aB);
        }
    }
    stage_wt(g_Wx1h, 128, 0, WsB, tid);
    __syncthreads();

    {   // scatter msg_agg
        int r = tid >> 1, j0 = (tid & 1) * 64;
        int d = dst_s[r];
        const uint16_t* hp = HsB + (size_t)r * HSTR + j0;
        float* p = (float*)g_msg4 + (size_t)d * 128 + j0;
#pragma unroll
        for (int q = 0; q < 8; q++) {
            uint4 raw = *(const uint4*)(hp + 8 * q);
            float2 f0 = __half22float2(*(__half2*)&raw.x);
            float2 f1 = __half22float2(*(__half2*)&raw.y);
            float2 f2 = __half22float2(*(__half2*)&raw.z);
            float2 f3 = __half22float2(*(__half2*)&raw.w);
            red_add_v4(p + 8 * q,     f0.x, f0.y, f1.x, f1.y);
            red_add_v4(p + 8 * q + 4, f2.x, f2.y, f3.x, f3.y);
        }
    }

    // GEMM2
#pragma unroll
    for (int mt = 0; mt < 2; mt++)
#pragma unroll
        for (int j = 0; j < 8; j++)
#pragma unroll
            for (int q = 0; q < 4; q++) acc[mt][j][q] = 0.f;
    mma_gemm16<HSTR,KSTR>(HsB, WsB, 128, m0, n0, lane, acc);

#pragma unroll
    for (int mt = 0; mt < 2; mt++) {
        pA[mt] = 0.f; pB[mt] = 0.f;
#pragma unroll
        for (int j = 0; j < 8; j++) {
            int c = n0 + 8 * j + 2 * t4;
            float b0 = bx1_s[c], b1 = bx1_s[c + 1];
            float w0 = wx2_s[c], w1 = wx2_s[c + 1];
            float g0 = silu_f(acc[mt][j][0] + b0);
            float g1 = silu_f(acc[mt][j][1] + b1);
            float g2 = silu_f(acc[mt][j][2] + b0);
            float g3 = silu_f(acc[mt][j][3] + b1);
            pA[mt] = fmaf(g0, w0, fmaf(g1, w1, pA[mt]));
            pB[mt] = fmaf(g2, w0, fmaf(g3, w1, pB[mt]));
        }
        pA[mt] += __shfl_xor_sync(0xffffffffu, pA[mt], 1);
        pA[mt] += __shfl_xor_sync(0xffffffffu, pA[mt], 2);
        pB[mt] += __shfl_xor_sync(0xffffffffu, pB[mt], 1);
        pB[mt] += __shfl_xor_sync(0xffffffffu, pB[mt], 2);
        if (t4 == 0) {
            red_s[(m0 + 16 * mt + g4) * 2 + (w >> 2)] = pA[mt];
            red_s[(m0 + 16 * mt + g4 + 8) * 2 + (w >> 2)] = pB[mt];
        }
    }
    __syncthreads();
    if (tid < 128) {
        float s = red_s[tid * 2] + red_s[tid * 2 + 1] + bx2[0];
        float cw = tanhf(s);
        int d = dst_s[tid];
        red_add_f(g_coord + (size_t)d * 3 + 0, diff_s[tid * 3 + 0] * cw);
        red_add_f(g_coord + (size_t)d * 3 + 1, diff_s[tid * 3 + 1] * cw);
        red_add_f(g_coord + (size_t)d * 3 + 2, diff_s[tid * 3 + 2] * cw);
        red_add_f(g_deg + d, 1.0f);
    }
}

// =====================================================================
// Kernel C: node update (fp16 mma)
// =====================================================================
__global__ __launch_bounds__(256, 2) void kC(const float* __restrict__ h,
                                             const float* __restrict__ bh1,
                                             const float* __restrict__ bh2,
                                             float* __restrict__ out) {
    extern __shared__ float sm[];
    uint16_t* HsB = (uint16_t*)sm;
    uint16_t* WsB = HsB + 128 * HSTR;
    int tid = threadIdx.x;
    int lane = tid & 31, w = tid >> 5;
    int g4 = lane >> 2, t4 = lane & 3;
    int m0 = (w & 3) * 32, n0 = (w >> 2) * 64;
    int tile0 = blockIdx.x * 128;

    float acc[2][8][4];
#pragma unroll
    for (int mt = 0; mt < 2; mt++)
#pragma unroll
        for (int j = 0; j < 8; j++)
#pragma unroll
            for (int q = 0; q < 4; q++) acc[mt][j][q] = 0.f;

    for (int pass = 0; pass < 2; pass++) {
        const float* src = pass ? (const float*)g_msg4 : h;
        if (pass) __syncthreads();
        {
            int n = tid >> 1, kh = (tid & 1) * 64;
            int gn = tile0 + n;
            uint16_t* d = HsB + (size_t)n * HSTR + kh;
#pragma unroll
            for (int q = 0; q < 8; q++) {
                float4 v0 = make_float4(0.f, 0.f, 0.f, 0.f);
                float4 v1 = make_float4(0.f, 0.f, 0.f, 0.f);
                if (gn < NN) {
                    v0 = *(const float4*)(src + (size_t)gn * 128 + kh + q * 8);
                    v1 = *(const float4*)(src + (size_t)gn * 128 + kh + q * 8 + 4);
                }
                uint4 u;
                u.x = packh2(v0.x, v0.y); u.y = packh2(v0.z, v0.w);
                u.z = packh2(v1.x, v1.y); u.w = packh2(v1.z, v1.w);
                *(uint4*)(d + 8 * q) = u;
            }
        }
        stage_wt(g_Wh1h, 256, pass * 128, WsB, tid);
        __syncthreads();
        mma_gemm16<HSTR,KSTR>(HsB, WsB, 128, m0, n0, lane, acc);
    }

    __syncthreads();
#pragma unroll
    for (int mt = 0; mt < 2; mt++) {
        int rA = m0 + 16 * mt + g4;
#pragma unroll
        for (int j = 0; j < 8; j++) {
            int c = n0 + 8 * j + 2 * t4;
            float2 bb = *(const float2*)(bh1 + c);
            *(uint32_t*)(HsB + (size_t)rA * HSTR + c) =
                packh2(silu_f(acc[mt][j][0] + bb.x), silu_f(acc[mt][j][1] + bb.y));
            *(uint32_t*)(HsB + (size_t)(rA + 8) * HSTR + c) =
                packh2(silu_f(acc[mt][j][2] + bb.x), silu_f(acc[mt][j][3] + bb.y));
        }
    }
    stage_wt(g_Wh2h, 128, 0, WsB, tid);
    __syncthreads();

#pragma unroll
    for (int mt = 0; mt < 2; mt++)
#pragma unroll
        for (int j = 0; j < 8; j++)
#pragma unroll
            for (int q = 0; q < 4; q++) acc[mt][j][q] = 0.f;
    mma_gemm16<HSTR,KSTR>(HsB, WsB, 128, m0, n0, lane, acc);

#pragma unroll
    for (int mt = 0; mt < 2; mt++) {
        int rA = m0 + 16 * mt + g4;
        int gnA = tile0 + rA, gnB = gnA + 8;
#pragma unroll
        for (int j = 0; j < 8; j++) {
            int c = n0 + 8 * j + 2 * t4;
            float2 bb = *(const float2*)(bh2 + c);
            if (gnA < NN) {
                float2 hv = *(const float2*)(h + (size_t)gnA * 128 + c);
                *(float2*)(out + (size_t)gnA * 128 + c) =
                    make_float2(hv.x + acc[mt][j][0] + bb.x,
                                hv.y + acc[mt][j][1] + bb.y);
            }
            if (gnB < NN) {
                float2 hv = *(const float2*)(h + (size_t)gnB * 128 + c);
                *(float2*)(out + (size_t)gnB * 128 + c) =
                    make_float2(hv.x + acc[mt][j][2] + bb.x,
                                hv.y + acc[mt][j][3] + bb.y);
            }
        }
    }
}

// ---- x_out ----
__global__ void kX(const float* __restrict__ x, float* __restrict__ out) {
    int n = blockIdx.x * blockDim.x + threadIdx.x;
    if (n < NN) {
        float inv = 1.f / (g_deg[n] + 1.f);
        float* o = out + (size_t)NN * 128 + (size_t)n * 3;
        o[0] = x[n * 3 + 0] + g_coord[n * 3 + 0] * inv;
        o[1] = x[n * 3 + 1] + g_coord[n * 3 + 1] * inv;
        o[2] = x[n * 3 + 2] + g_coord[n * 3 + 2] * inv;
    }
}

extern "C" void kernel_launch(void* const* d_in, const int* in_sizes, int n_in,
                              void* d_out, int out_size) {
    const float* h    = (const float*)d_in[0];
    const float* x    = (const float*)d_in[1];
    const float* ea   = (const float*)d_in[2];
    const float* temb = (const float*)d_in[3];
    const float* We1w = (const float*)d_in[4];
    const float* We1b = (const float*)d_in[5];
    const float* We2w = (const float*)d_in[6];
    const float* We2b = (const float*)d_in[7];
    const float* Wattw = (const float*)d_in[8];
    const float* Wattb = (const float*)d_in[9];
    const float* Wx1w = (const float*)d_in[10];
    const float* Wx1b = (const float*)d_in[11];
    const float* Wx2w = (const float*)d_in[12];
    const float* Wx2b = (const float*)d_in[13];
    const float* Wh1w = (const float*)d_in[14];
    const float* Wh1b = (const float*)d_in[15];
    const float* Wh2w = (const float*)d_in[16];
    const float* Wh2b = (const float*)d_in[17];
    const int*   eidx = (const int*)d_in[18];
    float* out = (float*)d_out;

    const int smA = 128 * (HSTR + KSTR + TSTR) * 2;
    const int smB = 128 * (HSTR + KSTR) * 2 + 128 * ESTR * 2 * 2 +
                    (256 + 128 * 5 + 384) * 4 + 256 * 4 + 512;
    const int smC = 128 * (HSTR + KSTR) * 2;
    cudaFuncSetAttribute(kA, cudaFuncAttributeMaxDynamicSharedMemorySize, smA);
    cudaFuncSetAttribute(kB, cudaFuncAttributeMaxDynamicSharedMemorySize, smB);
    cudaFuncSetAttribute(kC, cudaFuncAttributeMaxDynamicSharedMemorySize, smC);

    kZero<<<2048, 256>>>();
    kW<<<360, 256>>>(We1w, We2w, Wx1w, Wh1w, Wh2w);
    kA<<<(NN + 127) / 128, 256, smA>>>(h, temb, We1b);
    kB<<<EE / 128, 256, smB>>>(x, ea, eidx, We2b,
                               Wattw, Wattb, Wx1b, Wx2w, Wx2b);
    kC<<<(NN + 127) / 128, 256, smC>>>(h, Wh1b, Wh2b, out);
    kX<<<(NN + 255) / 256, 256>>>(x, out);
}

// round 8
// speedup vs baseline: 1.0613x; 1.0613x over previous
#include <cuda_runtime.h>
#include <cuda_fp16.h>
#include <math.h>
#include <stdint.h>

#define NN 50000
#define EE 800000
#define HSTR 136   // fp16 A-tile stride (halves)
#define KSTR 136   // fp16 B-tile stride (halves)
#define ESTR 40    // edge-feature tile stride (halves)
#define TSTR 72    // t_emb tile stride (halves)

// sigma layout: logical hidden col c -> physical p
//   p = (c&64) + 16*t4 + 2*j + b   where c = (c&64) + 8j + 2*t4 + b
// inverse (physical p -> logical c) used when permuting weight k-rows.
__device__ __host__ __forceinline__ int iperm_c(int p) {
    int r = p & 63;
    return (p & 64) + 8 * ((r >> 1) & 7) + 2 * (r >> 4) + (r & 1);
}

// ---- static device scratch ----
__device__ __half g_Psrch[NN * 128];   // sigma-ordered columns
__device__ __half g_Pdsth[NN * 128];   // sigma-ordered columns
__device__ float4 g_msg4 [NN * 32];    // sigma-ordered columns
__device__ float  g_coord[NN * 3];
__device__ float  g_deg  [NN];
// pre-transposed fp16 weights [n][k]
__device__ __half g_We2h[128 * 128];   // k sigma-permuted
__device__ __half g_Wx1h[128 * 128];   // k sigma-permuted
__device__ __half g_Wh1h[128 * 256];   // k in [128,256) sigma-permuted
__device__ __half g_Wh2h[128 * 128];   // k sigma-permuted
__device__ __half g_W1ah[128 * 128];
__device__ __half g_W1bh[128 * 128];
__device__ __half g_W1th[128 * 64];
__device__ __half g_WeEh[128 * 16];    // [n][k]: k0=wd, k1..8=We1e, rest 0

__device__ __forceinline__ float silu_f(float v) {
    return v / (1.f + __expf(-v));
}
__device__ __forceinline__ void red_add_v4(float* p, float a, float b, float c, float d) {
    asm volatile("red.global.add.v4.f32 [%0], {%1,%2,%3,%4};"
                 :: "l"(p), "f"(a), "f"(b), "f"(c), "f"(d) : "memory");
}
__device__ __forceinline__ void red_add_f(float* p, float a) {
    asm volatile("red.global.add.f32 [%0], %1;" :: "l"(p), "f"(a) : "memory");
}
__device__ __forceinline__ uint32_t packh2(float a, float b) {
    __half2 h = __floats2half2_rn(a, b);
    return *(uint32_t*)&h;
}
__device__ __forceinline__ void mma_f16(float c[4], const uint32_t a[4], const uint32_t b[2]) {
    asm volatile("mma.sync.aligned.m16n8k16.row.col.f32.f16.f16.f32 "
                 "{%0,%1,%2,%3}, {%4,%5,%6,%7}, {%8,%9}, {%0,%1,%2,%3};"
                 : "+f"(c[0]), "+f"(c[1]), "+f"(c[2]), "+f"(c[3])
                 : "r"(a[0]), "r"(a[1]), "r"(a[2]), "r"(a[3]),
                   "r"(b[0]), "r"(b[1]));
}
__device__ __forceinline__ void ldsm4(uint32_t r[4], uint32_t addr) {
    asm volatile("ldmatrix.sync.aligned.m8n8.x4.shared.b16 {%0,%1,%2,%3}, [%4];"
                 : "=r"(r[0]), "=r"(r[1]), "=r"(r[2]), "=r"(r[3]) : "r"(addr));
}
__device__ __forceinline__ uint32_t s2u(const void* p) {
    return (uint32_t)__cvta_generic_to_shared(p);
}

// stage pre-transposed fp16 weight [128][srcK] slice -> smem [n][KSTR]
__device__ __forceinline__ void stage_wt(const __half* __restrict__ src, int srcK,
                                         int kOff, uint16_t* __restrict__ WsB, int tid) {
    int n = tid >> 1, kh = (tid & 1) * 64;
    const uint16_t* s = (const uint16_t*)src + (size_t)n * srcK + kOff + kh;
    uint16_t* d = WsB + n * KSTR + kh;
#pragma unroll
    for (int q = 0; q < 8; q++)
        *(uint4*)(d + 8 * q) = *(const uint4*)(s + 8 * q);
}
__device__ __forceinline__ void stage_wt64(const __half* __restrict__ src,
                                           uint16_t* __restrict__ WsB, int tid) {
    int n = tid >> 1, kh = (tid & 1) * 32;
    const uint16_t* s = (const uint16_t*)src + (size_t)n * 64 + kh;
    uint16_t* d = WsB + n * KSTR + kh;
#pragma unroll
    for (int q = 0; q < 4; q++)
        *(uint4*)(d + 8 * q) = *(const uint4*)(s + 8 * q);
}

// warp fp16 GEMM via ldmatrix: C[32x64 per warp] += A[128xK] * B(n-major)[N][K]
template<int AS, int BS>
__device__ __forceinline__ void mma_gemm16(const uint16_t* __restrict__ Hs,
                                           const uint16_t* __restrict__ Ws,
                                           int K, int m0, int n0, int lane,
                                           float acc[2][8][4]) {
    int lrow = lane & 7, lmi = lane >> 3;
    uint32_t abase = s2u(Hs) +
        (uint32_t)(((m0 + (lmi & 1) * 8 + lrow) * AS + (lmi >> 1) * 8) * 2);
    uint32_t bbase = s2u(Ws) +
        (uint32_t)(((n0 + (lmi >> 1) * 8 + lrow) * BS + (lmi & 1) * 8) * 2);
#pragma unroll
    for (int k0 = 0; k0 < K; k0 += 16) {
        uint32_t b[4][4];
#pragma unroll
        for (int jp = 0; jp < 4; jp++)
            ldsm4(b[jp], bbase + (uint32_t)((16 * jp * BS + k0) * 2));
        uint32_t a[2][4];
#pragma unroll
        for (int mt = 0; mt < 2; mt++)
            ldsm4(a[mt], abase + (uint32_t)((16 * mt * AS + k0) * 2));
#pragma unroll
        for (int mt = 0; mt < 2; mt++)
#pragma unroll
            for (int j = 0; j < 8; j++)
                mma_f16(acc[mt][j], a[mt], &b[j >> 1][(j & 1) * 2]);
    }
}

// ---- zero accumulators ----
__global__ void kZero() {
    float* msg = (float*)g_msg4;
    long total = (long)NN * 128 + NN * 3 + NN;
    for (long i = blockIdx.x * (long)blockDim.x + threadIdx.x; i < total;
         i += (long)gridDim.x * blockDim.x) {
        if (i < (long)NN * 128)             msg[i] = 0.f;
        else if (i < (long)NN * 128 + NN*3) g_coord[i - (long)NN * 128] = 0.f;
        else                                g_deg[i - (long)NN * 128 - NN * 3] = 0.f;
    }
}

// ---- weight transpose + fp16 convert (once per launch) ----
__global__ void kW(const float* __restrict__ We1, const float* __restrict__ We2,
                   const float* __restrict__ Wx1,
                   const float* __restrict__ Wh1, const float* __restrict__ Wh2) {
    int i = blockIdx.x * blockDim.x + threadIdx.x;
    if (i < 16384) {
        int n = i >> 7, p = i & 127;
        int k = iperm_c(p);   // sigma-permuted k rows
        g_We2h[i] = __float2half_rn(We2[k * 128 + n]);
        g_Wx1h[i] = __float2half_rn(Wx1[k * 128 + n]);
        g_Wh2h[i] = __float2half_rn(Wh2[k * 128 + n]);
    } else if (i < 49152) {
        int j = i - 16384;
        int n = j >> 8, k = j & 255;
        int kk = (k < 128) ? k : (128 + iperm_c(k - 128));  // msg half permuted
        g_Wh1h[j] = __float2half_rn(Wh1[kk * 128 + n]);
    } else if (i < 65536) {
        int j = i - 49152;
        int n = j >> 7, k = j & 127;
        g_W1ah[j] = __float2half_rn(We1[k * 128 + n]);
    } else if (i < 81920) {
        int j = i - 65536;
        int n = j >> 7, k = j & 127;
        g_W1bh[j] = __float2half_rn(We1[(128 + k) * 128 + n]);
    } else if (i < 90112) {
        int j = i - 81920;
        int n = j >> 6, k = j & 63;
        g_W1th[j] = __float2half_rn(We1[(265 + k) * 128 + n]);
    } else if (i < 92160) {
        int j = i - 90112;
        int n = j >> 4, k = j & 15;
        float v = 0.f;
        if (k == 0)      v = We1[256 * 128 + n];
        else if (k <= 8) v = We1[(256 + k) * 128 + n];
        g_WeEh[j] = __float2half_rn(v);
    }
}

// =====================================================================
// Kernel A: per-node precompute (fp16 mma), stores sigma-ordered P
// =====================================================================
__global__ __launch_bounds__(256, 2) void kA(const float* __restrict__ h,
                                             const float* __restrict__ temb,
                                             const float* __restrict__ be1) {
    extern __shared__ float sm[];
    uint16_t* HsB = (uint16_t*)sm;
    uint16_t* WsB = HsB + 128 * HSTR;
    uint16_t* Ts  = WsB + 128 * KSTR;
    int tid = threadIdx.x;
    int lane = tid & 31, w = tid >> 5;
    int g4 = lane >> 2, t4 = lane & 3;
    int m0 = (w & 3) * 32, n0 = (w >> 2) * 64;
    int tile0 = blockIdx.x * 128;

    {
        int n = tid >> 1, kh = (tid & 1) * 64;
        int gn = tile0 + n;
        uint16_t* d = HsB + (size_t)n * HSTR + kh;
#pragma unroll
        for (int q = 0; q < 8; q++) {
            float4 v0 = make_float4(0.f,0.f,0.f,0.f), v1 = v0;
            if (gn < NN) {
                v0 = *(const float4*)(h + (size_t)gn * 128 + kh + q * 8);
                v1 = *(const float4*)(h + (size_t)gn * 128 + kh + q * 8 + 4);
            }
            uint4 u;
            u.x = packh2(v0.x, v0.y); u.y = packh2(v0.z, v0.w);
            u.z = packh2(v1.x, v1.y); u.w = packh2(v1.z, v1.w);
            *(uint4*)(d + 8 * q) = u;
        }
    }
    {
        int n = tid >> 1, kh = (tid & 1) * 32;
        int gn = tile0 + n;
        uint16_t* d = Ts + (size_t)n * TSTR + kh;
#pragma unroll
        for (int q = 0; q < 4; q++) {
            float4 v0 = make_float4(0.f,0.f,0.f,0.f), v1 = v0;
            if (gn < NN) {
                v0 = *(const float4*)(temb + (size_t)gn * 64 + kh + q * 8);
                v1 = *(const float4*)(temb + (size_t)gn * 64 + kh + q * 8 + 4);
            }
            uint4 u;
            u.x = packh2(v0.x, v0.y); u.y = packh2(v0.z, v0.w);
            u.z = packh2(v1.x, v1.y); u.w = packh2(v1.z, v1.w);
            *(uint4*)(d + 8 * q) = u;
        }
    }
    stage_wt(g_W1ah, 128, 0, WsB, tid);
    __syncthreads();

    float acc[2][8][4];
#pragma unroll
    for (int mt = 0; mt < 2; mt++)
#pragma unroll
        for (int j = 0; j < 8; j++)
#pragma unroll
            for (int q = 0; q < 4; q++) acc[mt][j][q] = 0.f;
    mma_gemm16<HSTR,KSTR>(HsB, WsB, 128, m0, n0, lane, acc);
    __syncthreads();
    stage_wt64(g_W1th, WsB, tid);
    __syncthreads();
    mma_gemm16<TSTR,KSTR>(Ts, WsB, 64, m0, n0, lane, acc);

    {   // store Psrc (+be1), sigma-ordered, 128-bit coalesced
        int off = n0 + 16 * t4;
#pragma unroll
        for (int mt = 0; mt < 2; mt++) {
            int rA = m0 + 16 * mt + g4;
            int gnA = tile0 + rA, gnB = gnA + 8;
            uint32_t wa[8], wb[8];
#pragma unroll
            for (int j = 0; j < 8; j++) {
                int c = n0 + 8 * j + 2 * t4;
                float2 bb = *(const float2*)(be1 + c);
                wa[j] = packh2(acc[mt][j][0] + bb.x, acc[mt][j][1] + bb.y);
                wb[j] = packh2(acc[mt][j][2] + bb.x, acc[mt][j][3] + bb.y);
            }
            if (gnA < NN) {
                uint16_t* p = (uint16_t*)g_Psrch + (size_t)gnA * 128 + off;
                *(uint4*)p       = make_uint4(wa[0], wa[1], wa[2], wa[3]);
                *(uint4*)(p + 8) = make_uint4(wa[4], wa[5], wa[6], wa[7]);
            }
            if (gnB < NN) {
                uint16_t* p = (uint16_t*)g_Psrch + (size_t)gnB * 128 + off;
                *(uint4*)p       = make_uint4(wb[0], wb[1], wb[2], wb[3]);
                *(uint4*)(p + 8) = make_uint4(wb[4], wb[5], wb[6], wb[7]);
            }
        }
    }
    __syncthreads();
    stage_wt(g_W1bh, 128, 0, WsB, tid);
    __syncthreads();
#pragma unroll
    for (int mt = 0; mt < 2; mt++)
#pragma unroll
        for (int j = 0; j < 8; j++)
#pragma unroll
            for (int q = 0; q < 4; q++) acc[mt][j][q] = 0.f;
    mma_gemm16<HSTR,KSTR>(HsB, WsB, 128, m0, n0, lane, acc);
    {   // store Pdst, sigma-ordered
        int off = n0 + 16 * t4;
#pragma unroll
        for (int mt = 0; mt < 2; mt++) {
            int rA = m0 + 16 * mt + g4;
            int gnA = tile0 + rA, gnB = gnA + 8;
            uint32_t wa[8], wb[8];
#pragma unroll
            for (int j = 0; j < 8; j++) {
                wa[j] = packh2(acc[mt][j][0], acc[mt][j][1]);
                wb[j] = packh2(acc[mt][j][2], acc[mt][j][3]);
            }
            if (gnA < NN) {
                uint16_t* p = (uint16_t*)g_Pdsth + (size_t)gnA * 128 + off;
                *(uint4*)p       = make_uint4(wa[0], wa[1], wa[2], wa[3]);
                *(uint4*)(p + 8) = make_uint4(wa[4], wa[5], wa[6], wa[7]);
            }
            if (gnB < NN) {
                uint16_t* p = (uint16_t*)g_Pdsth + (size_t)gnB * 128 + off;
                *(uint4*)p       = make_uint4(wb[0], wb[1], wb[2], wb[3]);
                *(uint4*)(p + 8) = make_uint4(wb[4], wb[5], wb[6], wb[7]);
            }
        }
    }
}

// =====================================================================
// Kernel B: fused edge pipeline, 128 edges per block (sigma layout)
// =====================================================================
__global__ __launch_bounds__(256, 2) void kB(const float* __restrict__ x,
                                             const float* __restrict__ ea,
                                             const int* __restrict__ eidx,
                                             const float* __restrict__ be2,
                                             const float* __restrict__ Watt,
                                             const float* __restrict__ batt,
                                             const float* __restrict__ bx1,
                                             const float* __restrict__ Wx2,
                                             const float* __restrict__ bx2) {
    extern __shared__ float sm[];
    uint16_t* HsB = (uint16_t*)sm;
    uint16_t* WsB = HsB + 128 * HSTR;
    uint16_t* Es  = WsB + 128 * KSTR;
    uint16_t* Wes = Es + 128 * ESTR;
    float* red_s  = (float*)(Wes + 128 * ESTR);
    float* watt_s = red_s + 256;
    float* be2_s  = watt_s + 128;
    float* bx1_s  = be2_s + 128;
    float* wx2_s  = bx1_s + 128;
    float* att_s  = wx2_s + 128;
    float* diff_s = att_s + 128;
    int* src_s = (int*)(diff_s + 384);
    int* dst_s = src_s + 128;

    int tid = threadIdx.x;
    int lane = tid & 31, w = tid >> 5;
    int g4 = lane >> 2, t4 = lane & 3;
    int m0 = (w & 3) * 32, n0 = (w >> 2) * 64;
    int e0 = blockIdx.x * 128;

    if (tid < 128) {
        int e = e0 + tid;
        int s = eidx[e], d = eidx[EE + e];
        src_s[tid] = s; dst_s[tid] = d;
        float dx = x[s * 3 + 0] - x[d * 3 + 0];
        float dy = x[s * 3 + 1] - x[d * 3 + 1];
        float dz = x[s * 3 + 2] - x[d * 3 + 2];
        diff_s[tid * 3 + 0] = dx; diff_s[tid * 3 + 1] = dy; diff_s[tid * 3 + 2] = dz;
        float dsq = dx * dx + dy * dy + dz * dz;
        watt_s[tid] = Watt[tid];
        be2_s[tid]  = be2[tid];
        bx1_s[tid]  = bx1[tid];
        wx2_s[tid]  = Wx2[tid];
        float4 a0 = *(const float4*)(ea + (size_t)e * 8);
        float4 a1 = *(const float4*)(ea + (size_t)e * 8 + 4);
        uint4 u0, u1;
        u0.x = packh2(dsq,  a0.x); u0.y = packh2(a0.y, a0.z);
        u0.z = packh2(a0.w, a1.x); u0.w = packh2(a1.y, a1.z);
        u1.x = packh2(a1.w, 0.f);  u1.y = 0u; u1.z = 0u; u1.w = 0u;
        *(uint4*)(Es + tid * ESTR) = u0;
        *(uint4*)(Es + tid * ESTR + 8) = u1;
    }
    {
        int n = tid >> 1, half = tid & 1;
        *(uint4*)(Wes + n * ESTR + half * 8) =
            *(const uint4*)((const uint16_t*)g_WeEh + n * 16 + half * 8);
    }
    stage_wt(g_We2h, 128, 0, WsB, tid);
    __syncthreads();

    {   // gather Ps_sum = Psrc[src] + Pdst[dst] (already sigma-ordered rows)
        int e = tid >> 1, j0 = (tid & 1) * 64;
        int s = src_s[e], d = dst_s[e];
        const uint4* ps = (const uint4*)((const uint16_t*)g_Psrch + (size_t)s * 128 + j0);
        const uint4* pd = (const uint4*)((const uint16_t*)g_Pdsth + (size_t)d * 128 + j0);
        uint16_t* dp = HsB + (size_t)e * HSTR + j0;
#pragma unroll
        for (int q = 0; q < 8; q++) {
            uint4 a = ps[q], b = pd[q];
            uint4 r;
            *(__half2*)&r.x = __hadd2(*(__half2*)&a.x, *(__half2*)&b.x);
            *(__half2*)&r.y = __hadd2(*(__half2*)&a.y, *(__half2*)&b.y);
            *(__half2*)&r.z = __hadd2(*(__half2*)&a.z, *(__half2*)&b.z);
            *(__half2*)&r.w = __hadd2(*(__half2*)&a.w, *(__half2*)&b.w);
            *(uint4*)(dp + 8 * q) = r;
        }
    }
    __syncthreads();

    float acc[2][8][4];
#pragma unroll
    for (int mt = 0; mt < 2; mt++)
#pragma unroll
        for (int j = 0; j < 8; j++)
#pragma unroll
            for (int q = 0; q < 4; q++) acc[mt][j][q] = 0.f;
    mma_gemm16<ESTR,ESTR>(Es, Wes, 16, m0, n0, lane, acc);

    // epilogue0: hidden = silu(acc + Ps_sum), vectorized via sigma layout
    {
        int off = n0 + 16 * t4;
#pragma unroll
        for (int mt = 0; mt < 2; mt++) {
            int rA = m0 + 16 * mt + g4, rB = rA + 8;
            uint16_t* pa = HsB + (size_t)rA * HSTR + off;
            uint16_t* pb = HsB + (size_t)rB * HSTR + off;
            uint4 a0 = *(uint4*)pa, a1 = *(uint4*)(pa + 8);
            uint4 b0 = *(uint4*)pb, b1 = *(uint4*)(pb + 8);
            uint32_t aw[8] = {a0.x,a0.y,a0.z,a0.w,a1.x,a1.y,a1.z,a1.w};
            uint32_t bw[8] = {b0.x,b0.y,b0.z,b0.w,b1.x,b1.y,b1.z,b1.w};
            uint32_t oa[8], ob[8];
#pragma unroll
            for (int j = 0; j < 8; j++) {
                float2 fa = __half22float2(*(__half2*)&aw[j]);
                float2 fb = __half22float2(*(__half2*)&bw[j]);
                oa[j] = packh2(silu_f(acc[mt][j][0] + fa.x), silu_f(acc[mt][j][1] + fa.y));
                ob[j] = packh2(silu_f(acc[mt][j][2] + fb.x), silu_f(acc[mt][j][3] + fb.y));
            }
            *(uint4*)pa       = make_uint4(oa[0], oa[1], oa[2], oa[3]);
            *(uint4*)(pa + 8) = make_uint4(oa[4], oa[5], oa[6], oa[7]);
            *(uint4*)pb       = make_uint4(ob[0], ob[1], ob[2], ob[3]);
            *(uint4*)(pb + 8) = make_uint4(ob[4], ob[5], ob[6], ob[7]);
        }
    }
    __syncthreads();

    // GEMM1: m = hidden @ We2 (sigma-consistent)
#pragma unroll
    for (int mt = 0; mt < 2; mt++)
#pragma unroll
        for (int j = 0; j < 8; j++)
#pragma unroll
            for (int q = 0; q < 4; q++) acc[mt][j][q] = 0.f;
    mma_gemm16<HSTR,KSTR>(HsB, WsB, 128, m0, n0, lane, acc);

    float pA[2], pB[2];
#pragma unroll
    for (int mt = 0; mt < 2; mt++) {
        pA[mt] = 0.f; pB[mt] = 0.f;
#pragma unroll
        for (int j = 0; j < 8; j++) {
            int c = n0 + 8 * j + 2 * t4;
            float b0 = be2_s[c], b1 = be2_s[c + 1];
            float w0 = watt_s[c], w1 = watt_s[c + 1];
            acc[mt][j][0] += b0; acc[mt][j][1] += b1;
            acc[mt][j][2] += b0; acc[mt][j][3] += b1;
            pA[mt] = fmaf(acc[mt][j][0], w0, fmaf(acc[mt][j][1], w1, pA[mt]));
            pB[mt] = fmaf(acc[mt][j][2], w0, fmaf(acc[mt][j][3], w1, pB[mt]));
        }
        pA[mt] += __shfl_xor_sync(0xffffffffu, pA[mt], 1);
        pA[mt] += __shfl_xor_sync(0xffffffffu, pA[mt], 2);
        pB[mt] += __shfl_xor_sync(0xffffffffu, pB[mt], 1);
        pB[mt] += __shfl_xor_sync(0xffffffffu, pB[mt], 2);
        if (t4 == 0) {
            red_s[(m0 + 16 * mt + g4) * 2 + (w >> 2)] = pA[mt];
            red_s[(m0 + 16 * mt + g4 + 8) * 2 + (w >> 2)] = pB[mt];
        }
    }
    __syncthreads();
    if (tid < 128) {
        float s = red_s[tid * 2] + red_s[tid * 2 + 1] + batt[0];
        att_s[tid] = 1.f / (1.f + __expf(-s));
    }
    __syncthreads();

    // gate + store m (sigma layout, 128-bit)
    {
        int off = n0 + 16 * t4;
#pragma unroll
        for (int mt = 0; mt < 2; mt++) {
            int rA = m0 + 16 * mt + g4, rB = rA + 8;
            float aA = att_s[rA], aB = att_s[rB];
            uint32_t oa[8], ob[8];
#pragma unroll
            for (int j = 0; j < 8; j++) {
                oa[j] = packh2(acc[mt][j][0] * aA, acc[mt][j][1] * aA);
                ob[j] = packh2(acc[mt][j][2] * aB, acc[mt][j][3] * aB);
            }
            uint16_t* pa = HsB + (size_t)rA * HSTR + off;
            uint16_t* pb = HsB + (size_t)rB * HSTR + off;
            *(uint4*)pa       = make_uint4(oa[0], oa[1], oa[2], oa[3]);
            *(uint4*)(pa + 8) = make_uint4(oa[4], oa[5], oa[6], oa[7]);
            *(uint4*)pb       = make_uint4(ob[0], ob[1], ob[2], ob[3]);
            *(uint4*)(pb + 8) = make_uint4(ob[4], ob[5], ob[6], ob[7]);
        }
    }
    stage_wt(g_Wx1h, 128, 0, WsB, tid);
    __syncthreads();

    {   // scatter msg_agg (sigma-ordered msg)
        int r = tid >> 1, j0 = (tid & 1) * 64;
        int d = dst_s[r];
        const uint16_t* hp = HsB + (size_t)r * HSTR + j0;
        float* p = (float*)g_msg4 + (size_t)d * 128 + j0;
#pragma unroll
        for (int q = 0; q < 8; q++) {
            uint4 raw = *(const uint4*)(hp + 8 * q);
            float2 f0 = __half22float2(*(__half2*)&raw.x);
            float2 f1 = __half22float2(*(__half2*)&raw.y);
            float2 f2 = __half22float2(*(__half2*)&raw.z);
            float2 f3 = __half22float2(*(__half2*)&raw.w);
            red_add_v4(p + 8 * q,     f0.x, f0.y, f1.x, f1.y);
            red_add_v4(p + 8 * q + 4, f2.x, f2.y, f3.x, f3.y);
        }
    }

    // GEMM2: g = silu(m @ Wx1 + bx1); coordw partial = g @ Wx2
#pragma unroll
    for (int mt = 0; mt < 2; mt++)
#pragma unroll
        for (int j = 0; j < 8; j++)
#pragma unroll
            for (int q = 0; q < 4; q++) acc[mt][j][q] = 0.f;
    mma_gemm16<HSTR,KSTR>(HsB, WsB, 128, m0, n0, lane, acc);

#pragma unroll
    for (int mt = 0; mt < 2; mt++) {
        pA[mt] = 0.f; pB[mt] = 0.f;
#pragma unroll
        for (int j = 0; j < 8; j++) {
            int c = n0 + 8 * j + 2 * t4;
            float b0 = bx1_s[c], b1 = bx1_s[c + 1];
            float w0 = wx2_s[c], w1 = wx2_s[c + 1];
            float g0 = silu_f(acc[mt][j][0] + b0);
            float g1 = silu_f(acc[mt][j][1] + b1);
            float g2 = silu_f(acc[mt][j][2] + b0);
            float g3 = silu_f(acc[mt][j][3] + b1);
            pA[mt] = fmaf(g0, w0, fmaf(g1, w1, pA[mt]));
            pB[mt] = fmaf(g2, w0, fmaf(g3, w1, pB[mt]));
        }
        pA[mt] += __shfl_xor_sync(0xffffffffu, pA[mt], 1);
        pA[mt] += __shfl_xor_sync(0xffffffffu, pA[mt], 2);
        pB[mt] += __shfl_xor_sync(0xffffffffu, pB[mt], 1);
        pB[mt] += __shfl_xor_sync(0xffffffffu, pB[mt], 2);
        if (t4 == 0) {
            red_s[(m0 + 16 * mt + g4) * 2 + (w >> 2)] = pA[mt];
            red_s[(m0 + 16 * mt + g4 + 8) * 2 + (w >> 2)] = pB[mt];
        }
    }
    __syncthreads();
    if (tid < 128) {
        float s = red_s[tid * 2] + red_s[tid * 2 + 1] + bx2[0];
        float cw = tanhf(s);
        int d = dst_s[tid];
        red_add_f(g_coord + (size_t)d * 3 + 0, diff_s[tid * 3 + 0] * cw);
        red_add_f(g_coord + (size_t)d * 3 + 1, diff_s[tid * 3 + 1] * cw);
        red_add_f(g_coord + (size_t)d * 3 + 2, diff_s[tid * 3 + 2] * cw);
        red_add_f(g_deg + d, 1.0f);
    }
}

// =====================================================================
// Kernel C: node update (fp16 mma, sigma layout internally)
// =====================================================================
__global__ __launch_bounds__(256, 2) void kC(const float* __restrict__ h,
                                             const float* __restrict__ bh1,
                                             const float* __restrict__ bh2,
                                             float* __restrict__ out) {
    extern __shared__ float sm[];
    uint16_t* HsB = (uint16_t*)sm;
    uint16_t* WsB = HsB + 128 * HSTR;
    int tid = threadIdx.x;
    int lane = tid & 31, w = tid >> 5;
    int g4 = lane >> 2, t4 = lane & 3;
    int m0 = (w & 3) * 32, n0 = (w >> 2) * 64;
    int tile0 = blockIdx.x * 128;

    float acc[2][8][4];
#pragma unroll
    for (int mt = 0; mt < 2; mt++)
#pragma unroll
        for (int j = 0; j < 8; j++)
#pragma unroll
            for (int q = 0; q < 4; q++) acc[mt][j][q] = 0.f;

    for (int pass = 0; pass < 2; pass++) {
        const float* src = pass ? (const float*)g_msg4 : h;
        if (pass) __syncthreads();
        {
            int n = tid >> 1, kh = (tid & 1) * 64;
            int gn = tile0 + n;
            uint16_t* d = HsB + (size_t)n * HSTR + kh;
#pragma unroll
            for (int q = 0; q < 8; q++) {
                float4 v0 = make_float4(0.f, 0.f, 0.f, 0.f);
                float4 v1 = make_float4(0.f, 0.f, 0.f, 0.f);
                if (gn < NN) {
                    v0 = *(const float4*)(src + (size_t)gn * 128 + kh + q * 8);
                    v1 = *(const float4*)(src + (size_t)gn * 128 + kh + q * 8 + 4);
                }
                uint4 u;
                u.x = packh2(v0.x, v0.y); u.y = packh2(v0.z, v0.w);
                u.z = packh2(v1.x, v1.y); u.w = packh2(v1.z, v1.w);
                *(uint4*)(d + 8 * q) = u;
            }
        }
        stage_wt(g_Wh1h, 256, pass * 128, WsB, tid);
        __syncthreads();
        mma_gemm16<HSTR,KSTR>(HsB, WsB, 128, m0, n0, lane, acc);
    }

    __syncthreads();
    {   // g = silu(acc + bh1) -> HsB (sigma layout, 128-bit stores)
        int off = n0 + 16 * t4;
#pragma unroll
        for (int mt = 0; mt < 2; mt++) {
            int rA = m0 + 16 * mt + g4, rB = rA + 8;
            uint32_t oa[8], ob[8];
#pragma unroll
            for (int j = 0; j < 8; j++) {
                int c = n0 + 8 * j + 2 * t4;
                float2 bb = *(const float2*)(bh1 + c);
                oa[j] = packh2(silu_f(acc[mt][j][0] + bb.x), silu_f(acc[mt][j][1] + bb.y));
                ob[j] = packh2(silu_f(acc[mt][j][2] + bb.x), silu_f(acc[mt][j][3] + bb.y));
            }
            uint16_t* pa = HsB + (size_t)rA * HSTR + off;
            uint16_t* pb = HsB + (size_t)rB * HSTR + off;
            *(uint4*)pa       = make_uint4(oa[0], oa[1], oa[2], oa[3]);
            *(uint4*)(pa + 8) = make_uint4(oa[4], oa[5], oa[6], oa[7]);
            *(uint4*)pb       = make_uint4(ob[0], ob[1], ob[2], ob[3]);
            *(uint4*)(pb + 8) = make_uint4(ob[4], ob[5], ob[6], ob[7]);
        }
    }
    stage_wt(g_Wh2h, 128, 0, WsB, tid);
    __syncthreads();

#pragma unroll
    for (int mt = 0; mt < 2; mt++)
#pragma unroll
        for (int j = 0; j < 8; j++)
#pragma unroll
            for (int q = 0; q < 4; q++) acc[mt][j][q] = 0.f;
    mma_gemm16<HSTR,KSTR>(HsB, WsB, 128, m0, n0, lane, acc);

    // out = h + acc + bh2 (logical order, unchanged)
#pragma unroll
    for (int mt = 0; mt < 2; mt++) {
        int rA = m0 + 16 * mt + g4;
        int gnA = tile0 + rA, gnB = gnA + 8;
#pragma unroll
        for (int j = 0; j < 8; j++) {
            int c = n0 + 8 * j + 2 * t4;
            float2 bb = *(const float2*)(bh2 + c);
            if (gnA < NN) {
                float2 hv = *(const float2*)(h + (size_t)gnA * 128 + c);
                *(float2*)(out + (size_t)gnA * 128 + c) =
                    make_float2(hv.x + acc[mt][j][0] + bb.x,
                                hv.y + acc[mt][j][1] + bb.y);
            }
            if (gnB < NN) {
                float2 hv = *(const float2*)(h + (size_t)gnB * 128 + c);
                *(float2*)(out + (size_t)gnB * 128 + c) =
                    make_float2(hv.x + acc[mt][j][2] + bb.x,
                                hv.y + acc[mt][j][3] + bb.y);
            }
        }
    }
}

// ---- x_out ----
__global__ void kX(const float* __restrict__ x, float* __restrict__ out) {
    int n = blockIdx.x * blockDim.x + threadIdx.x;
    if (n < NN) {
        float inv = 1.f / (g_deg[n] + 1.f);
        float* o = out + (size_t)NN * 128 + (size_t)n * 3;
        o[0] = x[n * 3 + 0] + g_coord[n * 3 + 0] * inv;
        o[1] = x[n * 3 + 1] + g_coord[n * 3 + 1] * inv;
        o[2] = x[n * 3 + 2] + g_coord[n * 3 + 2] * inv;
    }
}

extern "C" void kernel_launch(void* const* d_in, const int* in_sizes, int n_in,
                              void* d_out, int out_size) {
    const float* h    = (const float*)d_in[0];
    const float* x    = (const float*)d_in[1];
    const float* ea   = (const float*)d_in[2];
    const float* temb = (const float*)d_in[3];
    const float* We1w = (const float*)d_in[4];
    const float* We1b = (const float*)d_in[5];
    const float* We2w = (const float*)d_in[6];
    const float* We2b = (const float*)d_in[7];
    const float* Wattw = (const float*)d_in[8];
    const float* Wattb = (const float*)d_in[9];
    const float* Wx1w = (const float*)d_in[10];
    const float* Wx1b = (const float*)d_in[11];
    const float* Wx2w = (const float*)d_in[12];
    const float* Wx2b = (const float*)d_in[13];
    const float* Wh1w = (const float*)d_in[14];
    const float* Wh1b = (const float*)d_in[15];
    const float* Wh2w = (const float*)d_in[16];
    const float* Wh2b = (const float*)d_in[17];
    const int*   eidx = (const int*)d_in[18];
    float* out = (float*)d_out;

    const int smA = 128 * (HSTR + KSTR + TSTR) * 2;
    const int smB = 128 * (HSTR + KSTR) * 2 + 128 * ESTR * 2 * 2 +
                    (256 + 128 * 5 + 384) * 4 + 256 * 4 + 512;
    const int smC = 128 * (HSTR + KSTR) * 2;
    cudaFuncSetAttribute(kA, cudaFuncAttributeMaxDynamicSharedMemorySize, smA);
    cudaFuncSetAttribute(kB, cudaFuncAttributeMaxDynamicSharedMemorySize, smB);
    cudaFuncSetAttribute(kC, cudaFuncAttributeMaxDynamicSharedMemorySize, smC);

    kZero<<<2048, 256>>>();
    kW<<<360, 256>>>(We1w, We2w, Wx1w, Wh1w, Wh2w);
    kA<<<(NN + 127) / 128, 256, smA>>>(h, temb, We1b);
    kB<<<EE / 128, 256, smB>>>(x, ea, eidx, We2b,
                               Wattw, Wattb, Wx1b, Wx2w, Wx2b);
    kC<<<(NN + 127) / 128, 256, smC>>>(h, Wh1b, Wh2b, out);
    kX<<<(NN + 255) / 256, 256>>>(x, out);
}

// round 9
// speedup vs baseline: 1.1145x; 1.0501x over previous
#include <cuda_runtime.h>
#include <cuda_fp16.h>
#include <math.h>
#include <stdint.h>

#define NN 50000
#define EE 800000
#define HSTR 136   // fp16 A-tile stride (halves)
#define KSTR 136   // fp16 B-tile stride (halves)
#define ESTR 40    // edge-feature tile stride (halves)
#define TSTR 72    // t_emb tile stride (halves)

// sigma layout: logical hidden col c -> physical p
__device__ __host__ __forceinline__ int iperm_c(int p) {
    int r = p & 63;
    return (p & 64) + 8 * ((r >> 1) & 7) + 2 * (r >> 4) + (r & 1);
}

// ---- static device scratch ----
__device__ __half g_Psrch[NN * 128];   // sigma-ordered columns
__device__ __half g_Pdsth[NN * 128];
__device__ float4 g_msg4 [NN * 32];    // sigma-ordered columns
__device__ float  g_coord[NN * 3];
__device__ float  g_deg  [NN];
// pre-transposed fp16 weights [n][k]
__device__ __half g_We2h[128 * 128];   // k sigma-permuted
__device__ __half g_Wx1h[128 * 128];   // k sigma-permuted
__device__ __half g_Wh1h[128 * 256];   // k in [128,256) sigma-permuted
__device__ __half g_Wh2h[128 * 128];   // k sigma-permuted
__device__ __half g_W1ah[128 * 128];
__device__ __half g_W1bh[128 * 128];
__device__ __half g_W1th[128 * 64];
__device__ __half g_WeEh[128 * 16];

__device__ __forceinline__ float silu_f(float v) {
    return v / (1.f + __expf(-v));
}
__device__ __forceinline__ void red_add_v4(float* p, float a, float b, float c, float d) {
    asm volatile("red.global.add.v4.f32 [%0], {%1,%2,%3,%4};"
                 :: "l"(p), "f"(a), "f"(b), "f"(c), "f"(d) : "memory");
}
__device__ __forceinline__ void red_add_f(float* p, float a) {
    asm volatile("red.global.add.f32 [%0], %1;" :: "l"(p), "f"(a) : "memory");
}
__device__ __forceinline__ uint32_t packh2(float a, float b) {
    __half2 h = __floats2half2_rn(a, b);
    return *(uint32_t*)&h;
}
__device__ __forceinline__ void mma_f16(float c[4], const uint32_t a[4], const uint32_t b[2]) {
    asm volatile("mma.sync.aligned.m16n8k16.row.col.f32.f16.f16.f32 "
                 "{%0,%1,%2,%3}, {%4,%5,%6,%7}, {%8,%9}, {%0,%1,%2,%3};"
                 : "+f"(c[0]), "+f"(c[1]), "+f"(c[2]), "+f"(c[3])
                 : "r"(a[0]), "r"(a[1]), "r"(a[2]), "r"(a[3]),
                   "r"(b[0]), "r"(b[1]));
}
__device__ __forceinline__ void ldsm4(uint32_t r[4], uint32_t addr) {
    asm volatile("ldmatrix.sync.aligned.m8n8.x4.shared.b16 {%0,%1,%2,%3}, [%4];"
                 : "=r"(r[0]), "=r"(r[1]), "=r"(r[2]), "=r"(r[3]) : "r"(addr));
}
__device__ __forceinline__ uint32_t s2u(const void* p) {
    return (uint32_t)__cvta_generic_to_shared(p);
}

// stage pre-transposed fp16 weight [128][srcK] slice -> smem [n][KSTR]
__device__ __forceinline__ void stage_wt(const __half* __restrict__ src, int srcK,
                                         int kOff, uint16_t* __restrict__ WsB, int tid) {
    int n = tid >> 1, kh = (tid & 1) * 64;
    const uint16_t* s = (const uint16_t*)src + (size_t)n * srcK + kOff + kh;
    uint16_t* d = WsB + n * KSTR + kh;
#pragma unroll
    for (int q = 0; q < 8; q++)
        *(uint4*)(d + 8 * q) = *(const uint4*)(s + 8 * q);
}
__device__ __forceinline__ void stage_wt64(const __half* __restrict__ src,
                                           uint16_t* __restrict__ WsB, int tid) {
    int n = tid >> 1, kh = (tid & 1) * 32;
    const uint16_t* s = (const uint16_t*)src + (size_t)n * 64 + kh;
    uint16_t* d = WsB + n * KSTR + kh;
#pragma unroll
    for (int q = 0; q < 4; q++)
        *(uint4*)(d + 8 * q) = *(const uint4*)(s + 8 * q);
}

// warp fp16 GEMM via ldmatrix
template<int AS, int BS>
__device__ __forceinline__ void mma_gemm16(const uint16_t* __restrict__ Hs,
                                           const uint16_t* __restrict__ Ws,
                                           int K, int m0, int n0, int lane,
                                           float acc[2][8][4]) {
    int lrow = lane & 7, lmi = lane >> 3;
    uint32_t abase = s2u(Hs) +
        (uint32_t)(((m0 + (lmi & 1) * 8 + lrow) * AS + (lmi >> 1) * 8) * 2);
    uint32_t bbase = s2u(Ws) +
        (uint32_t)(((n0 + (lmi >> 1) * 8 + lrow) * BS + (lmi & 1) * 8) * 2);
#pragma unroll
    for (int k0 = 0; k0 < K; k0 += 16) {
        uint32_t b[4][4];
#pragma unroll
        for (int jp = 0; jp < 4; jp++)
            ldsm4(b[jp], bbase + (uint32_t)((16 * jp * BS + k0) * 2));
        uint32_t a[2][4];
#pragma unroll
        for (int mt = 0; mt < 2; mt++)
            ldsm4(a[mt], abase + (uint32_t)((16 * mt * AS + k0) * 2));
#pragma unroll
        for (int mt = 0; mt < 2; mt++)
#pragma unroll
            for (int j = 0; j < 8; j++)
                mma_f16(acc[mt][j], a[mt], &b[j >> 1][(j & 1) * 2]);
    }
}

// ---- zero accumulators ----
__global__ void kZero() {
    float* msg = (float*)g_msg4;
    long total = (long)NN * 128 + NN * 3 + NN;
    for (long i = blockIdx.x * (long)blockDim.x + threadIdx.x; i < total;
         i += (long)gridDim.x * blockDim.x) {
        if (i < (long)NN * 128)             msg[i] = 0.f;
        else if (i < (long)NN * 128 + NN*3) g_coord[i - (long)NN * 128] = 0.f;
        else                                g_deg[i - (long)NN * 128 - NN * 3] = 0.f;
    }
}

// ---- weight transpose + fp16 convert ----
__global__ void kW(const float* __restrict__ We1, const float* __restrict__ We2,
                   const float* __restrict__ Wx1,
                   const float* __restrict__ Wh1, const float* __restrict__ Wh2) {
    int i = blockIdx.x * blockDim.x + threadIdx.x;
    if (i < 16384) {
        int n = i >> 7, p = i & 127;
        int k = iperm_c(p);
        g_We2h[i] = __float2half_rn(We2[k * 128 + n]);
        g_Wx1h[i] = __float2half_rn(Wx1[k * 128 + n]);
        g_Wh2h[i] = __float2half_rn(Wh2[k * 128 + n]);
    } else if (i < 49152) {
        int j = i - 16384;
        int n = j >> 8, k = j & 255;
        int kk = (k < 128) ? k : (128 + iperm_c(k - 128));
        g_Wh1h[j] = __float2half_rn(Wh1[kk * 128 + n]);
    } else if (i < 65536) {
        int j = i - 49152;
        int n = j >> 7, k = j & 127;
        g_W1ah[j] = __float2half_rn(We1[k * 128 + n]);
    } else if (i < 81920) {
        int j = i - 65536;
        int n = j >> 7, k = j & 127;
        g_W1bh[j] = __float2half_rn(We1[(128 + k) * 128 + n]);
    } else if (i < 90112) {
        int j = i - 81920;
        int n = j >> 6, k = j & 63;
        g_W1th[j] = __float2half_rn(We1[(265 + k) * 128 + n]);
    } else if (i < 92160) {
        int j = i - 90112;
        int n = j >> 4, k = j & 15;
        float v = 0.f;
        if (k == 0)      v = We1[256 * 128 + n];
        else if (k <= 8) v = We1[(256 + k) * 128 + n];
        g_WeEh[j] = __float2half_rn(v);
    }
}

// =====================================================================
// Kernel A: per-node precompute (fp16 mma), sigma-ordered P
// =====================================================================
__global__ __launch_bounds__(256, 2) void kA(const float* __restrict__ h,
                                             const float* __restrict__ temb,
                                             const float* __restrict__ be1) {
    extern __shared__ float sm[];
    uint16_t* HsB = (uint16_t*)sm;
    uint16_t* WsB = HsB + 128 * HSTR;
    uint16_t* Ts  = WsB + 128 * KSTR;
    int tid = threadIdx.x;
    int lane = tid & 31, w = tid >> 5;
    int g4 = lane >> 2, t4 = lane & 3;
    int m0 = (w & 3) * 32, n0 = (w >> 2) * 64;
    int tile0 = blockIdx.x * 128;

    {
        int n = tid >> 1, kh = (tid & 1) * 64;
        int gn = tile0 + n;
        uint16_t* d = HsB + (size_t)n * HSTR + kh;
#pragma unroll
        for (int q = 0; q < 8; q++) {
            float4 v0 = make_float4(0.f,0.f,0.f,0.f), v1 = v0;
            if (gn < NN) {
                v0 = *(const float4*)(h + (size_t)gn * 128 + kh + q * 8);
                v1 = *(const float4*)(h + (size_t)gn * 128 + kh + q * 8 + 4);
            }
            uint4 u;
            u.x = packh2(v0.x, v0.y); u.y = packh2(v0.z, v0.w);
            u.z = packh2(v1.x, v1.y); u.w = packh2(v1.z, v1.w);
            *(uint4*)(d + 8 * q) = u;
        }
    }
    {
        int n = tid >> 1, kh = (tid & 1) * 32;
        int gn = tile0 + n;
        uint16_t* d = Ts + (size_t)n * TSTR + kh;
#pragma unroll
        for (int q = 0; q < 4; q++) {
            float4 v0 = make_float4(0.f,0.f,0.f,0.f), v1 = v0;
            if (gn < NN) {
                v0 = *(const float4*)(temb + (size_t)gn * 64 + kh + q * 8);
                v1 = *(const float4*)(temb + (size_t)gn * 64 + kh + q * 8 + 4);
            }
            uint4 u;
            u.x = packh2(v0.x, v0.y); u.y = packh2(v0.z, v0.w);
            u.z = packh2(v1.x, v1.y); u.w = packh2(v1.z, v1.w);
            *(uint4*)(d + 8 * q) = u;
        }
    }
    stage_wt(g_W1ah, 128, 0, WsB, tid);
    __syncthreads();

    float acc[2][8][4];
#pragma unroll
    for (int mt = 0; mt < 2; mt++)
#pragma unroll
        for (int j = 0; j < 8; j++)
#pragma unroll
            for (int q = 0; q < 4; q++) acc[mt][j][q] = 0.f;
    mma_gemm16<HSTR,KSTR>(HsB, WsB, 128, m0, n0, lane, acc);
    __syncthreads();
    stage_wt64(g_W1th, WsB, tid);
    __syncthreads();
    mma_gemm16<TSTR,KSTR>(Ts, WsB, 64, m0, n0, lane, acc);

    {
        int off = n0 + 16 * t4;
#pragma unroll
        for (int mt = 0; mt < 2; mt++) {
            int rA = m0 + 16 * mt + g4;
            int gnA = tile0 + rA, gnB = gnA + 8;
            uint32_t wa[8], wb[8];
#pragma unroll
            for (int j = 0; j < 8; j++) {
                int c = n0 + 8 * j + 2 * t4;
                float2 bb = *(const float2*)(be1 + c);
                wa[j] = packh2(acc[mt][j][0] + bb.x, acc[mt][j][1] + bb.y);
                wb[j] = packh2(acc[mt][j][2] + bb.x, acc[mt][j][3] + bb.y);
            }
            if (gnA < NN) {
                uint16_t* p = (uint16_t*)g_Psrch + (size_t)gnA * 128 + off;
                *(uint4*)p       = make_uint4(wa[0], wa[1], wa[2], wa[3]);
                *(uint4*)(p + 8) = make_uint4(wa[4], wa[5], wa[6], wa[7]);
            }
            if (gnB < NN) {
                uint16_t* p = (uint16_t*)g_Psrch + (size_t)gnB * 128 + off;
                *(uint4*)p       = make_uint4(wb[0], wb[1], wb[2], wb[3]);
                *(uint4*)(p + 8) = make_uint4(wb[4], wb[5], wb[6], wb[7]);
            }
        }
    }
    __syncthreads();
    stage_wt(g_W1bh, 128, 0, WsB, tid);
    __syncthreads();
#pragma unroll
    for (int mt = 0; mt < 2; mt++)
#pragma unroll
        for (int j = 0; j < 8; j++)
#pragma unroll
            for (int q = 0; q < 4; q++) acc[mt][j][q] = 0.f;
    mma_gemm16<HSTR,KSTR>(HsB, WsB, 128, m0, n0, lane, acc);
    {
        int off = n0 + 16 * t4;
#pragma unroll
        for (int mt = 0; mt < 2; mt++) {
            int rA = m0 + 16 * mt + g4;
            int gnA = tile0 + rA, gnB = gnA + 8;
            uint32_t wa[8], wb[8];
#pragma unroll
            for (int j = 0; j < 8; j++) {
                wa[j] = packh2(acc[mt][j][0], acc[mt][j][1]);
                wb[j] = packh2(acc[mt][j][2], acc[mt][j][3]);
            }
            if (gnA < NN) {
                uint16_t* p = (uint16_t*)g_Pdsth + (size_t)gnA * 128 + off;
                *(uint4*)p       = make_uint4(wa[0], wa[1], wa[2], wa[3]);
                *(uint4*)(p + 8) = make_uint4(wa[4], wa[5], wa[6], wa[7]);
            }
            if (gnB < NN) {
                uint16_t* p = (uint16_t*)g_Pdsth + (size_t)gnB * 128 + off;
                *(uint4*)p       = make_uint4(wb[0], wb[1], wb[2], wb[3]);
                *(uint4*)(p + 8) = make_uint4(wb[4], wb[5], wb[6], wb[7]);
            }
        }
    }
}

// =====================================================================
// Kernel B: fused edge pipeline, 128 edges per block (sigma layout)
// =====================================================================
__global__ __launch_bounds__(256, 2) void kB(const float* __restrict__ x,
                                             const float* __restrict__ ea,
                                             const int* __restrict__ eidx,
                                             const float* __restrict__ be2,
                                             const float* __restrict__ Watt,
                                             const float* __restrict__ batt,
                                             const float* __restrict__ bx1,
                                             const float* __restrict__ Wx2,
                                             const float* __restrict__ bx2) {
    extern __shared__ float sm[];
    uint16_t* HsB = (uint16_t*)sm;
    uint16_t* WsB = HsB + 128 * HSTR;
    uint16_t* Es  = WsB + 128 * KSTR;
    uint16_t* Wes = Es + 128 * ESTR;
    float* red_s  = (float*)(Wes + 128 * ESTR);
    float* watt_s = red_s + 256;
    float* be2_s  = watt_s + 128;
    float* bx1_s  = be2_s + 128;
    float* wx2_s  = bx1_s + 128;
    float* att_s  = wx2_s + 128;
    float* diff_s = att_s + 128;
    int* src_s = (int*)(diff_s + 384);
    int* dst_s = src_s + 128;

    int tid = threadIdx.x;
    int lane = tid & 31, w = tid >> 5;
    int g4 = lane >> 2, t4 = lane & 3;
    int m0 = (w & 3) * 32, n0 = (w >> 2) * 64;
    int e0 = blockIdx.x * 128;
    // line-grouped edge mapping: 16 lanes per edge
    int eg   = (w << 4) + ((lane & 31) >> 4);   // base edge for this half-warp group
    int chnk = lane & 15;                       // 16B chunk within row

    if (tid < 128) {
        int e = e0 + tid;
        int s = eidx[e], d = eidx[EE + e];
        src_s[tid] = s; dst_s[tid] = d;
        float dx = x[s * 3 + 0] - x[d * 3 + 0];
        float dy = x[s * 3 + 1] - x[d * 3 + 1];
        float dz = x[s * 3 + 2] - x[d * 3 + 2];
        diff_s[tid * 3 + 0] = dx; diff_s[tid * 3 + 1] = dy; diff_s[tid * 3 + 2] = dz;
        float dsq = dx * dx + dy * dy + dz * dz;
        watt_s[tid] = Watt[tid];
        be2_s[tid]  = be2[tid];
        bx1_s[tid]  = bx1[tid];
        wx2_s[tid]  = Wx2[tid];
        float4 a0 = *(const float4*)(ea + (size_t)e * 8);
        float4 a1 = *(const float4*)(ea + (size_t)e * 8 + 4);
        uint4 u0, u1;
        u0.x = packh2(dsq,  a0.x); u0.y = packh2(a0.y, a0.z);
        u0.z = packh2(a0.w, a1.x); u0.w = packh2(a1.y, a1.z);
        u1.x = packh2(a1.w, 0.f);  u1.y = 0u; u1.z = 0u; u1.w = 0u;
        *(uint4*)(Es + tid * ESTR) = u0;
        *(uint4*)(Es + tid * ESTR + 8) = u1;
    }
    {
        int n = tid >> 1, half = tid & 1;
        *(uint4*)(Wes + n * ESTR + half * 8) =
            *(const uint4*)((const uint16_t*)g_WeEh + n * 16 + half * 8);
    }
    stage_wt(g_We2h, 128, 0, WsB, tid);
    __syncthreads();

    {   // gather Ps_sum, line-grouped: one warp instr = 2 edges x full 128B line
#pragma unroll
        for (int it = 0; it < 8; it++) {
            int e = eg + it * 2;
            int s = src_s[e], d = dst_s[e];
            uint4 a = *(const uint4*)((const uint16_t*)g_Psrch + (size_t)s * 128 + chnk * 8);
            uint4 b = *(const uint4*)((const uint16_t*)g_Pdsth + (size_t)d * 128 + chnk * 8);
            uint4 r;
            *(__half2*)&r.x = __hadd2(*(__half2*)&a.x, *(__half2*)&b.x);
            *(__half2*)&r.y = __hadd2(*(__half2*)&a.y, *(__half2*)&b.y);
            *(__half2*)&r.z = __hadd2(*(__half2*)&a.z, *(__half2*)&b.z);
            *(__half2*)&r.w = __hadd2(*(__half2*)&a.w, *(__half2*)&b.w);
            *(uint4*)(HsB + (size_t)e * HSTR + chnk * 8) = r;
        }
    }
    __syncthreads();

    float acc[2][8][4];
#pragma unroll
    for (int mt = 0; mt < 2; mt++)
#pragma unroll
        for (int j = 0; j < 8; j++)
#pragma unroll
            for (int q = 0; q < 4; q++) acc[mt][j][q] = 0.f;
    mma_gemm16<ESTR,ESTR>(Es, Wes, 16, m0, n0, lane, acc);

    // epilogue0: hidden = silu(acc + Ps_sum)
    {
        int off = n0 + 16 * t4;
#pragma unroll
        for (int mt = 0; mt < 2; mt++) {
            int rA = m0 + 16 * mt + g4, rB = rA + 8;
            uint16_t* pa = HsB + (size_t)rA * HSTR + off;
            uint16_t* pb = HsB + (size_t)rB * HSTR + off;
            uint4 a0 = *(uint4*)pa, a1 = *(uint4*)(pa + 8);
            uint4 b0 = *(uint4*)pb, b1 = *(uint4*)(pb + 8);
            uint32_t aw[8] = {a0.x,a0.y,a0.z,a0.w,a1.x,a1.y,a1.z,a1.w};
            uint32_t bw[8] = {b0.x,b0.y,b0.z,b0.w,b1.x,b1.y,b1.z,b1.w};
            uint32_t oa[8], ob[8];
#pragma unroll
            for (int j = 0; j < 8; j++) {
                float2 fa = __half22float2(*(__half2*)&aw[j]);
                float2 fb = __half22float2(*(__half2*)&bw[j]);
                oa[j] = packh2(silu_f(acc[mt][j][0] + fa.x), silu_f(acc[mt][j][1] + fa.y));
                ob[j] = packh2(silu_f(acc[mt][j][2] + fb.x), silu_f(acc[mt][j][3] + fb.y));
            }
            *(uint4*)pa       = make_uint4(oa[0], oa[1], oa[2], oa[3]);
            *(uint4*)(pa + 8) = make_uint4(oa[4], oa[5], oa[6], oa[7]);
            *(uint4*)pb       = make_uint4(ob[0], ob[1], ob[2], ob[3]);
            *(uint4*)(pb + 8) = make_uint4(ob[4], ob[5], ob[6], ob[7]);
        }
    }
    __syncthreads();

    // GEMM1: m = hidden @ We2
#pragma unroll
    for (int mt = 0; mt < 2; mt++)
#pragma unroll
        for (int j = 0; j < 8; j++)
#pragma unroll
            for (int q = 0; q < 4; q++) acc[mt][j][q] = 0.f;
    mma_gemm16<HSTR,KSTR>(HsB, WsB, 128, m0, n0, lane, acc);

    float pA[2], pB[2];
#pragma unroll
    for (int mt = 0; mt < 2; mt++) {
        pA[mt] = 0.f; pB[mt] = 0.f;
#pragma unroll
        for (int j = 0; j < 8; j++) {
            int c = n0 + 8 * j + 2 * t4;
            float b0 = be2_s[c], b1 = be2_s[c + 1];
            float w0 = watt_s[c], w1 = watt_s[c + 1];
            acc[mt][j][0] += b0; acc[mt][j][1] += b1;
            acc[mt][j][2] += b0; acc[mt][j][3] += b1;
            pA[mt] = fmaf(acc[mt][j][0], w0, fmaf(acc[mt][j][1], w1, pA[mt]));
            pB[mt] = fmaf(acc[mt][j][2], w0, fmaf(acc[mt][j][3], w1, pB[mt]));
        }
        pA[mt] += __shfl_xor_sync(0xffffffffu, pA[mt], 1);
        pA[mt] += __shfl_xor_sync(0xffffffffu, pA[mt], 2);
        pB[mt] += __shfl_xor_sync(0xffffffffu, pB[mt], 1);
        pB[mt] += __shfl_xor_sync(0xffffffffu, pB[mt], 2);
        if (t4 == 0) {
            red_s[(m0 + 16 * mt + g4) * 2 + (w >> 2)] = pA[mt];
            red_s[(m0 + 16 * mt + g4 + 8) * 2 + (w >> 2)] = pB[mt];
        }
    }
    __syncthreads();
    if (tid < 128) {
        float s = red_s[tid * 2] + red_s[tid * 2 + 1] + batt[0];
        att_s[tid] = 1.f / (1.f + __expf(-s));
    }
    __syncthreads();

    // gate + store m (sigma layout)
    {
        int off = n0 + 16 * t4;
#pragma unroll
        for (int mt = 0; mt < 2; mt++) {
            int rA = m0 + 16 * mt + g4, rB = rA + 8;
            float aA = att_s[rA], aB = att_s[rB];
            uint32_t oa[8], ob[8];
#pragma unroll
            for (int j = 0; j < 8; j++) {
                oa[j] = packh2(acc[mt][j][0] * aA, acc[mt][j][1] * aA);
                ob[j] = packh2(acc[mt][j][2] * aB, acc[mt][j][3] * aB);
            }
            uint16_t* pa = HsB + (size_t)rA * HSTR + off;
            uint16_t* pb = HsB + (size_t)rB * HSTR + off;
            *(uint4*)pa       = make_uint4(oa[0], oa[1], oa[2], oa[3]);
            *(uint4*)(pa + 8) = make_uint4(oa[4], oa[5], oa[6], oa[7]);
            *(uint4*)pb       = make_uint4(ob[0], ob[1], ob[2], ob[3]);
            *(uint4*)(pb + 8) = make_uint4(ob[4], ob[5], ob[6], ob[7]);
        }
    }
    stage_wt(g_Wx1h, 128, 0, WsB, tid);
    __syncthreads();

    {   // scatter msg_agg, line-grouped: 16 lanes per edge row
#pragma unroll
        for (int it = 0; it < 8; it++) {
            int e = eg + it * 2;
            int d = dst_s[e];
            uint4 raw = *(const uint4*)(HsB + (size_t)e * HSTR + chnk * 8);
            float2 f0 = __half22float2(*(__half2*)&raw.x);
            float2 f1 = __half22float2(*(__half2*)&raw.y);
            float2 f2 = __half22float2(*(__half2*)&raw.z);
            float2 f3 = __half22float2(*(__half2*)&raw.w);
            float* p = (float*)g_msg4 + (size_t)d * 128 + chnk * 8;
            red_add_v4(p,     f0.x, f0.y, f1.x, f1.y);
            red_add_v4(p + 4, f2.x, f2.y, f3.x, f3.y);
        }
    }

    // GEMM2: g = silu(m @ Wx1 + bx1); coordw partial = g @ Wx2
#pragma unroll
    for (int mt = 0; mt < 2; mt++)
#pragma unroll
        for (int j = 0; j < 8; j++)
#pragma unroll
            for (int q = 0; q < 4; q++) acc[mt][j][q] = 0.f;
    mma_gemm16<HSTR,KSTR>(HsB, WsB, 128, m0, n0, lane, acc);

#pragma unroll
    for (int mt = 0; mt < 2; mt++) {
        pA[mt] = 0.f; pB[mt] = 0.f;
#pragma unroll
        for (int j = 0; j < 8; j++) {
            int c = n0 + 8 * j + 2 * t4;
            float b0 = bx1_s[c], b1 = bx1_s[c + 1];
            float w0 = wx2_s[c], w1 = wx2_s[c + 1];
            float g0 = silu_f(acc[mt][j][0] + b0);
            float g1 = silu_f(acc[mt][j][1] + b1);
            float g2 = silu_f(acc[mt][j][2] + b0);
            float g3 = silu_f(acc[mt][j][3] + b1);
            pA[mt] = fmaf(g0, w0, fmaf(g1, w1, pA[mt]));
            pB[mt] = fmaf(g2, w0, fmaf(g3, w1, pB[mt]));
        }
        pA[mt] += __shfl_xor_sync(0xffffffffu, pA[mt], 1);
        pA[mt] += __shfl_xor_sync(0xffffffffu, pA[mt], 2);
        pB[mt] += __shfl_xor_sync(0xffffffffu, pB[mt], 1);
        pB[mt] += __shfl_xor_sync(0xffffffffu, pB[mt], 2);
        if (t4 == 0) {
            red_s[(m0 + 16 * mt + g4) * 2 + (w >> 2)] = pA[mt];
            red_s[(m0 + 16 * mt + g4 + 8) * 2 + (w >> 2)] = pB[mt];
        }
    }
    __syncthreads();
    if (tid < 128) {
        float s = red_s[tid * 2] + red_s[tid * 2 + 1] + bx2[0];
        float cw = tanhf(s);
        int d = dst_s[tid];
        red_add_f(g_coord + (size_t)d * 3 + 0, diff_s[tid * 3 + 0] * cw);
        red_add_f(g_coord + (size_t)d * 3 + 1, diff_s[tid * 3 + 1] * cw);
        red_add_f(g_coord + (size_t)d * 3 + 2, diff_s[tid * 3 + 2] * cw);
        red_add_f(g_deg + d, 1.0f);
    }
}

// =====================================================================
// Kernel C: node update (fp16 mma, sigma layout internally)
// =====================================================================
__global__ __launch_bounds__(256, 2) void kC(const float* __restrict__ h,
                                             const float* __restrict__ bh1,
                                             const float* __restrict__ bh2,
                                             float* __restrict__ out) {
    extern __shared__ float sm[];
    uint16_t* HsB = (uint16_t*)sm;
    uint16_t* WsB = HsB + 128 * HSTR;
    int tid = threadIdx.x;
    int lane = tid & 31, w = tid >> 5;
    int g4 = lane >> 2, t4 = lane & 3;
    int m0 = (w & 3) * 32, n0 = (w >> 2) * 64;
    int tile0 = blockIdx.x * 128;

    float acc[2][8][4];
#pragma unroll
    for (int mt = 0; mt < 2; mt++)
#pragma unroll
        for (int j = 0; j < 8; j++)
#pragma unroll
            for (int q = 0; q < 4; q++) acc[mt][j][q] = 0.f;

    for (int pass = 0; pass < 2; pass++) {
        const float* src = pass ? (const float*)g_msg4 : h;
        if (pass) __syncthreads();
        {
            int n = tid >> 1, kh = (tid & 1) * 64;
            int gn = tile0 + n;
            uint16_t* d = HsB + (size_t)n * HSTR + kh;
#pragma unroll
            for (int q = 0; q < 8; q++) {
                float4 v0 = make_float4(0.f, 0.f, 0.f, 0.f);
                float4 v1 = make_float4(0.f, 0.f, 0.f, 0.f);
                if (gn < NN) {
                    v0 = *(const float4*)(src + (size_t)gn * 128 + kh + q * 8);
                    v1 = *(const float4*)(src + (size_t)gn * 128 + kh + q * 8 + 4);
                }
                uint4 u;
                u.x = packh2(v0.x, v0.y); u.y = packh2(v0.z, v0.w);
                u.z = packh2(v1.x, v1.y); u.w = packh2(v1.z, v1.w);
                *(uint4*)(d + 8 * q) = u;
            }
        }
        stage_wt(g_Wh1h, 256, pass * 128, WsB, tid);
        __syncthreads();
        mma_gemm16<HSTR,KSTR>(HsB, WsB, 128, m0, n0, lane, acc);
    }

    __syncthreads();
    {
        int off = n0 + 16 * t4;
#pragma unroll
        for (int mt = 0; mt < 2; mt++) {
            int rA = m0 + 16 * mt + g4, rB = rA + 8;
            uint32_t oa[8], ob[8];
#pragma unroll
            for (int j = 0; j < 8; j++) {
                int c = n0 + 8 * j + 2 * t4;
                float2 bb = *(const float2*)(bh1 + c);
                oa[j] = packh2(silu_f(acc[mt][j][0] + bb.x), silu_f(acc[mt][j][1] + bb.y));
                ob[j] = packh2(silu_f(acc[mt][j][2] + bb.x), silu_f(acc[mt][j][3] + bb.y));
            }
            uint16_t* pa = HsB + (size_t)rA * HSTR + off;
            uint16_t* pb = HsB + (size_t)rB * HSTR + off;
            *(uint4*)pa       = make_uint4(oa[0], oa[1], oa[2], oa[3]);
            *(uint4*)(pa + 8) = make_uint4(oa[4], oa[5], oa[6], oa[7]);
            *(uint4*)pb       = make_uint4(ob[0], ob[1], ob[2], ob[3]);
            *(uint4*)(pb + 8) = make_uint4(ob[4], ob[5], ob[6], ob[7]);
        }
    }
    stage_wt(g_Wh2h, 128, 0, WsB, tid);
    __syncthreads();

#pragma unroll
    for (int mt = 0; mt < 2; mt++)
#pragma unroll
        for (int j = 0; j < 8; j++)
#pragma unroll
            for (int q = 0; q < 4; q++) acc[mt][j][q] = 0.f;
    mma_gemm16<HSTR,KSTR>(HsB, WsB, 128, m0, n0, lane, acc);

#pragma unroll
    for (int mt = 0; mt < 2; mt++) {
        int rA = m0 + 16 * mt + g4;
        int gnA = tile0 + rA, gnB = gnA + 8;
#pragma unroll
        for (int j = 0; j < 8; j++) {
            int c = n0 + 8 * j + 2 * t4;
            float2 bb = *(const float2*)(bh2 + c);
            if (gnA < NN) {
                float2 hv = *(const float2*)(h + (size_t)gnA * 128 + c);
                *(float2*)(out + (size_t)gnA * 128 + c) =
                    make_float2(hv.x + acc[mt][j][0] + bb.x,
                                hv.y + acc[mt][j][1] + bb.y);
            }
            if (gnB < NN) {
                float2 hv = *(const float2*)(h + (size_t)gnB * 128 + c);
                *(float2*)(out + (size_t)gnB * 128 + c) =
                    make_float2(hv.x + acc[mt][j][2] + bb.x,
                                hv.y + acc[mt][j][3] + bb.y);
            }
        }
    }
}

// ---- x_out ----
__global__ void kX(const float* __restrict__ x, float* __restrict__ out) {
    int n = blockIdx.x * blockDim.x + threadIdx.x;
    if (n < NN) {
        float inv = 1.f / (g_deg[n] + 1.f);
        float* o = out + (size_t)NN * 128 + (size_t)n * 3;
        o[0] = x[n * 3 + 0] + g_coord[n * 3 + 0] * inv;
        o[1] = x[n * 3 + 1] + g_coord[n * 3 + 1] * inv;
        o[2] = x[n * 3 + 2] + g_coord[n * 3 + 2] * inv;
    }
}

extern "C" void kernel_launch(void* const* d_in, const int* in_sizes, int n_in,
                              void* d_out, int out_size) {
    const float* h    = (const float*)d_in[0];
    const float* x    = (const float*)d_in[1];
    const float* ea   = (const float*)d_in[2];
    const float* temb = (const float*)d_in[3];
    const float* We1w = (const float*)d_in[4];
    const float* We1b = (const float*)d_in[5];
    const float* We2w = (const float*)d_in[6];
    const float* We2b = (const float*)d_in[7];
    const float* Wattw = (const float*)d_in[8];
    const float* Wattb = (const float*)d_in[9];
    const float* Wx1w = (const float*)d_in[10];
    const float* Wx1b = (const float*)d_in[11];
    const float* Wx2w = (const float*)d_in[12];
    const float* Wx2b = (const float*)d_in[13];
    const float* Wh1w = (const float*)d_in[14];
    const float* Wh1b = (const float*)d_in[15];
    const float* Wh2w = (const float*)d_in[16];
    const float* Wh2b = (const float*)d_in[17];
    const int*   eidx = (const int*)d_in[18];
    float* out = (float*)d_out;

    const int smA = 128 * (HSTR + KSTR + TSTR) * 2;
    const int smB = 128 * (HSTR + KSTR) * 2 + 128 * ESTR * 2 * 2 +
                    (256 + 128 * 5 + 384) * 4 + 256 * 4 + 512;
    const int smC = 128 * (HSTR + KSTR) * 2;
    cudaFuncSetAttribute(kA, cudaFuncAttributeMaxDynamicSharedMemorySize, smA);
    cudaFuncSetAttribute(kB, cudaFuncAttributeMaxDynamicSharedMemorySize, smB);
    cudaFuncSetAttribute(kC, cudaFuncAttributeMaxDynamicSharedMemorySize, smC);

    kZero<<<2048, 256>>>();
    kW<<<360, 256>>>(We1w, We2w, Wx1w, Wh1w, Wh2w);
    kA<<<(NN + 127) / 128, 256, smA>>>(h, temb, We1b);
    kB<<<EE / 128, 256, smB>>>(x, ea, eidx, We2b,
                               Wattw, Wattb, Wx1b, Wx2w, Wx2b);
    kC<<<(NN + 127) / 128, 256, smC>>>(h, Wh1b, Wh2b, out);
    kX<<<(NN + 255) / 256, 256>>>(x, out);
}

// round 10
// speedup vs baseline: 1.4790x; 1.3270x over previous
#include <cuda_runtime.h>
#include <cuda_fp16.h>
#include <math.h>
#include <stdint.h>

#define NN 50000
#define EE 800000
#define HSTR 136   // fp16 A-tile stride (halves)
#define KSTR 136   // fp16 B-tile stride (halves)
#define ESTR 40    // edge-feature tile stride (halves)
#define TSTR 72    // t_emb tile stride (halves)

// sigma layout: logical hidden col c -> physical p
__device__ __host__ __forceinline__ int iperm_c(int p) {
    int r = p & 63;
    return (p & 64) + 8 * ((r >> 1) & 7) + 2 * (r >> 4) + (r & 1);
}

// ---- static device scratch ----
__device__ __half g_Psrch[NN * 128];   // sigma-ordered columns
__device__ __half g_Pdsth[NN * 128];
__device__ float4 g_msg4 [NN * 32];    // sigma-ordered columns
__device__ float  g_coord[NN * 3];
__device__ float  g_deg  [NN];
// pre-transposed fp16 weights [n][k]
__device__ __half g_We2h[128 * 128];   // k sigma-permuted
__device__ __half g_Wx1h[128 * 128];   // k sigma-permuted
__device__ __half g_Wh1h[128 * 256];   // k in [128,256) sigma-permuted
__device__ __half g_Wh2h[128 * 128];   // k sigma-permuted
__device__ __half g_W1ah[128 * 128];
__device__ __half g_W1bh[128 * 128];
__device__ __half g_W1th[128 * 64];
__device__ __half g_WeEh[128 * 16];

// ---- fast transcendentals (tanh.approx.f32, sm_75+) ----
__device__ __forceinline__ float tanh_ap(float x) {
    float r;
    asm("tanh.approx.f32 %0, %1;" : "=f"(r) : "f"(x));
    return r;
}
__device__ __forceinline__ float silu_f(float v) {
    float hv = 0.5f * v;
    return fmaf(hv, tanh_ap(hv), hv);
}
__device__ __forceinline__ float sigmoid_f(float s) {
    return fmaf(0.5f, tanh_ap(0.5f * s), 0.5f);
}

__device__ __forceinline__ void red_add_v4(float* p, float a, float b, float c, float d) {
    asm volatile("red.global.add.v4.f32 [%0], {%1,%2,%3,%4};"
                 :: "l"(p), "f"(a), "f"(b), "f"(c), "f"(d) : "memory");
}
__device__ __forceinline__ void red_add_f(float* p, float a) {
    asm volatile("red.global.add.f32 [%0], %1;" :: "l"(p), "f"(a) : "memory");
}
__device__ __forceinline__ uint32_t packh2(float a, float b) {
    __half2 h = __floats2half2_rn(a, b);
    return *(uint32_t*)&h;
}
__device__ __forceinline__ void mma_f16(float c[4], const uint32_t a[4], const uint32_t b[2]) {
    asm volatile("mma.sync.aligned.m16n8k16.row.col.f32.f16.f16.f32 "
                 "{%0,%1,%2,%3}, {%4,%5,%6,%7}, {%8,%9}, {%0,%1,%2,%3};"
                 : "+f"(c[0]), "+f"(c[1]), "+f"(c[2]), "+f"(c[3])
                 : "r"(a[0]), "r"(a[1]), "r"(a[2]), "r"(a[3]),
                   "r"(b[0]), "r"(b[1]));
}
__device__ __forceinline__ void ldsm4(uint32_t r[4], uint32_t addr) {
    asm volatile("ldmatrix.sync.aligned.m8n8.x4.shared.b16 {%0,%1,%2,%3}, [%4];"
                 : "=r"(r[0]), "=r"(r[1]), "=r"(r[2]), "=r"(r[3]) : "r"(addr));
}
__device__ __forceinline__ uint32_t s2u(const void* p) {
    return (uint32_t)__cvta_generic_to_shared(p);
}

// stage pre-transposed fp16 weight [128][srcK] slice -> smem [n][KSTR]
__device__ __forceinline__ void stage_wt(const __half* __restrict__ src, int srcK,
                                         int kOff, uint16_t* __restrict__ WsB, int tid) {
    int n = tid >> 1, kh = (tid & 1) * 64;
    const uint16_t* s = (const uint16_t*)src + (size_t)n * srcK + kOff + kh;
    uint16_t* d = WsB + n * KSTR + kh;
#pragma unroll
    for (int q = 0; q < 8; q++)
        *(uint4*)(d + 8 * q) = *(const uint4*)(s + 8 * q);
}
__device__ __forceinline__ void stage_wt64(const __half* __restrict__ src,
                                           uint16_t* __restrict__ WsB, int tid) {
    int n = tid >> 1, kh = (tid & 1) * 32;
    const uint16_t* s = (const uint16_t*)src + (size_t)n * 64 + kh;
    uint16_t* d = WsB + n * KSTR + kh;
#pragma unroll
    for (int q = 0; q < 4; q++)
        *(uint4*)(d + 8 * q) = *(const uint4*)(s + 8 * q);
}

// warp fp16 GEMM via ldmatrix
template<int AS, int BS>
__device__ __forceinline__ void mma_gemm16(const uint16_t* __restrict__ Hs,
                                           const uint16_t* __restrict__ Ws,
                                           int K, int m0, int n0, int lane,
                                           float acc[2][8][4]) {
    int lrow = lane & 7, lmi = lane >> 3;
    uint32_t abase = s2u(Hs) +
        (uint32_t)(((m0 + (lmi & 1) * 8 + lrow) * AS + (lmi >> 1) * 8) * 2);
    uint32_t bbase = s2u(Ws) +
        (uint32_t)(((n0 + (lmi >> 1) * 8 + lrow) * BS + (lmi & 1) * 8) * 2);
#pragma unroll
    for (int k0 = 0; k0 < K; k0 += 16) {
        uint32_t b[4][4];
#pragma unroll
        for (int jp = 0; jp < 4; jp++)
            ldsm4(b[jp], bbase + (uint32_t)((16 * jp * BS + k0) * 2));
        uint32_t a[2][4];
#pragma unroll
        for (int mt = 0; mt < 2; mt++)
            ldsm4(a[mt], abase + (uint32_t)((16 * mt * AS + k0) * 2));
#pragma unroll
        for (int mt = 0; mt < 2; mt++)
#pragma unroll
            for (int j = 0; j < 8; j++)
                mma_f16(acc[mt][j], a[mt], &b[j >> 1][(j & 1) * 2]);
    }
}

// ---- zero accumulators ----
__global__ void kZero() {
    float* msg = (float*)g_msg4;
    long total = (long)NN * 128 + NN * 3 + NN;
    for (long i = blockIdx.x * (long)blockDim.x + threadIdx.x; i < total;
         i += (long)gridDim.x * blockDim.x) {
        if (i < (long)NN * 128)             msg[i] = 0.f;
        else if (i < (long)NN * 128 + NN*3) g_coord[i - (long)NN * 128] = 0.f;
        else                                g_deg[i - (long)NN * 128 - NN * 3] = 0.f;
    }
}

// ---- weight transpose + fp16 convert ----
__global__ void kW(const float* __restrict__ We1, const float* __restrict__ We2,
                   const float* __restrict__ Wx1,
                   const float* __restrict__ Wh1, const float* __restrict__ Wh2) {
    int i = blockIdx.x * blockDim.x + threadIdx.x;
    if (i < 16384) {
        int n = i >> 7, p = i & 127;
        int k = iperm_c(p);
        g_We2h[i] = __float2half_rn(We2[k * 128 + n]);
        g_Wx1h[i] = __float2half_rn(Wx1[k * 128 + n]);
        g_Wh2h[i] = __float2half_rn(Wh2[k * 128 + n]);
    } else if (i < 49152) {
        int j = i - 16384;
        int n = j >> 8, k = j & 255;
        int kk = (k < 128) ? k : (128 + iperm_c(k - 128));
        g_Wh1h[j] = __float2half_rn(Wh1[kk * 128 + n]);
    } else if (i < 65536) {
        int j = i - 49152;
        int n = j >> 7, k = j & 127;
        g_W1ah[j] = __float2half_rn(We1[k * 128 + n]);
    } else if (i < 81920) {
        int j = i - 65536;
        int n = j >> 7, k = j & 127;
        g_W1bh[j] = __float2half_rn(We1[(128 + k) * 128 + n]);
    } else if (i < 90112) {
        int j = i - 81920;
        int n = j >> 6, k = j & 63;
        g_W1th[j] = __float2half_rn(We1[(265 + k) * 128 + n]);
    } else if (i < 92160) {
        int j = i - 90112;
        int n = j >> 4, k = j & 15;
        float v = 0.f;
        if (k == 0)      v = We1[256 * 128 + n];
        else if (k <= 8) v = We1[(256 + k) * 128 + n];
        g_WeEh[j] = __float2half_rn(v);
    }
}

// =====================================================================
// Kernel A: per-node precompute (fp16 mma), sigma-ordered P
// =====================================================================
__global__ __launch_bounds__(256, 2) void kA(const float* __restrict__ h,
                                             const float* __restrict__ temb,
                                             const float* __restrict__ be1) {
    extern __shared__ float sm[];
    uint16_t* HsB = (uint16_t*)sm;
    uint16_t* WsB = HsB + 128 * HSTR;
    uint16_t* Ts  = WsB + 128 * KSTR;
    int tid = threadIdx.x;
    int lane = tid & 31, w = tid >> 5;
    int g4 = lane >> 2, t4 = lane & 3;
    int m0 = (w & 3) * 32, n0 = (w >> 2) * 64;
    int tile0 = blockIdx.x * 128;

    {
        int n = tid >> 1, kh = (tid & 1) * 64;
        int gn = tile0 + n;
        uint16_t* d = HsB + (size_t)n * HSTR + kh;
#pragma unroll
        for (int q = 0; q < 8; q++) {
            float4 v0 = make_float4(0.f,0.f,0.f,0.f), v1 = v0;
            if (gn < NN) {
                v0 = *(const float4*)(h + (size_t)gn * 128 + kh + q * 8);
                v1 = *(const float4*)(h + (size_t)gn * 128 + kh + q * 8 + 4);
            }
            uint4 u;
            u.x = packh2(v0.x, v0.y); u.y = packh2(v0.z, v0.w);
            u.z = packh2(v1.x, v1.y); u.w = packh2(v1.z, v1.w);
            *(uint4*)(d + 8 * q) = u;
        }
    }
    {
        int n = tid >> 1, kh = (tid & 1) * 32;
        int gn = tile0 + n;
        uint16_t* d = Ts + (size_t)n * TSTR + kh;
#pragma unroll
        for (int q = 0; q < 4; q++) {
            float4 v0 = make_float4(0.f,0.f,0.f,0.f), v1 = v0;
            if (gn < NN) {
                v0 = *(const float4*)(temb + (size_t)gn * 64 + kh + q * 8);
                v1 = *(const float4*)(temb + (size_t)gn * 64 + kh + q * 8 + 4);
            }
            uint4 u;
            u.x = packh2(v0.x, v0.y); u.y = packh2(v0.z, v0.w);
            u.z = packh2(v1.x, v1.y); u.w = packh2(v1.z, v1.w);
            *(uint4*)(d + 8 * q) = u;
        }
    }
    stage_wt(g_W1ah, 128, 0, WsB, tid);
    __syncthreads();

    float acc[2][8][4];
#pragma unroll
    for (int mt = 0; mt < 2; mt++)
#pragma unroll
        for (int j = 0; j < 8; j++)
#pragma unroll
            for (int q = 0; q < 4; q++) acc[mt][j][q] = 0.f;
    mma_gemm16<HSTR,KSTR>(HsB, WsB, 128, m0, n0, lane, acc);
    __syncthreads();
    stage_wt64(g_W1th, WsB, tid);
    __syncthreads();
    mma_gemm16<TSTR,KSTR>(Ts, WsB, 64, m0, n0, lane, acc);

    {
        int off = n0 + 16 * t4;
#pragma unroll
        for (int mt = 0; mt < 2; mt++) {
            int rA = m0 + 16 * mt + g4;
            int gnA = tile0 + rA, gnB = gnA + 8;
            uint32_t wa[8], wb[8];
#pragma unroll
            for (int j = 0; j < 8; j++) {
                int c = n0 + 8 * j + 2 * t4;
                float2 bb = *(const float2*)(be1 + c);
                wa[j] = packh2(acc[mt][j][0] + bb.x, acc[mt][j][1] + bb.y);
                wb[j] = packh2(acc[mt][j][2] + bb.x, acc[mt][j][3] + bb.y);
            }
            if (gnA < NN) {
                uint16_t* p = (uint16_t*)g_Psrch + (size_t)gnA * 128 + off;
                *(uint4*)p       = make_uint4(wa[0], wa[1], wa[2], wa[3]);
                *(uint4*)(p + 8) = make_uint4(wa[4], wa[5], wa[6], wa[7]);
            }
            if (gnB < NN) {
                uint16_t* p = (uint16_t*)g_Psrch + (size_t)gnB * 128 + off;
                *(uint4*)p       = make_uint4(wb[0], wb[1], wb[2], wb[3]);
                *(uint4*)(p + 8) = make_uint4(wb[4], wb[5], wb[6], wb[7]);
            }
        }
    }
    __syncthreads();
    stage_wt(g_W1bh, 128, 0, WsB, tid);
    __syncthreads();
#pragma unroll
    for (int mt = 0; mt < 2; mt++)
#pragma unroll
        for (int j = 0; j < 8; j++)
#pragma unroll
            for (int q = 0; q < 4; q++) acc[mt][j][q] = 0.f;
    mma_gemm16<HSTR,KSTR>(HsB, WsB, 128, m0, n0, lane, acc);
    {
        int off = n0 + 16 * t4;
#pragma unroll
        for (int mt = 0; mt < 2; mt++) {
            int rA = m0 + 16 * mt + g4;
            int gnA = tile0 + rA, gnB = gnA + 8;
            uint32_t wa[8], wb[8];
#pragma unroll
            for (int j = 0; j < 8; j++) {
                wa[j] = packh2(acc[mt][j][0], acc[mt][j][1]);
                wb[j] = packh2(acc[mt][j][2], acc[mt][j][3]);
            }
            if (gnA < NN) {
                uint16_t* p = (uint16_t*)g_Pdsth + (size_t)gnA * 128 + off;
                *(uint4*)p       = make_uint4(wa[0], wa[1], wa[2], wa[3]);
                *(uint4*)(p + 8) = make_uint4(wa[4], wa[5], wa[6], wa[7]);
            }
            if (gnB < NN) {
                uint16_t* p = (uint16_t*)g_Pdsth + (size_t)gnB * 128 + off;
                *(uint4*)p       = make_uint4(wb[0], wb[1], wb[2], wb[3]);
                *(uint4*)(p + 8) = make_uint4(wb[4], wb[5], wb[6], wb[7]);
            }
        }
    }
}

// =====================================================================
// Kernel B: fused edge pipeline, 128 edges per block (sigma layout)
// =====================================================================
__global__ __launch_bounds__(256, 2) void kB(const float* __restrict__ x,
                                             const float* __restrict__ ea,
                                             const int* __restrict__ eidx,
                                             const float* __restrict__ be2,
                                             const float* __restrict__ Watt,
                                             const float* __restrict__ batt,
                                             const float* __restrict__ bx1,
                                             const float* __restrict__ Wx2,
                                             const float* __restrict__ bx2) {
    extern __shared__ float sm[];
    uint16_t* HsB = (uint16_t*)sm;
    uint16_t* WsB = HsB + 128 * HSTR;
    uint16_t* Es  = WsB + 128 * KSTR;
    uint16_t* Wes = Es + 128 * ESTR;
    float* red_s  = (float*)(Wes + 128 * ESTR);
    float* watt_s = red_s + 256;
    float* be2_s  = watt_s + 128;
    float* bx1_s  = be2_s + 128;
    float* wx2_s  = bx1_s + 128;
    float* att_s  = wx2_s + 128;
    float* diff_s = att_s + 128;
    int* src_s = (int*)(diff_s + 384);
    int* dst_s = src_s + 128;

    int tid = threadIdx.x;
    int lane = tid & 31, w = tid >> 5;
    int g4 = lane >> 2, t4 = lane & 3;
    int m0 = (w & 3) * 32, n0 = (w >> 2) * 64;
    int e0 = blockIdx.x * 128;
    int eg   = (w << 4) + ((lane & 31) >> 4);
    int chnk = lane & 15;

    if (tid < 128) {
        int e = e0 + tid;
        int s = eidx[e], d = eidx[EE + e];
        src_s[tid] = s; dst_s[tid] = d;
        float dx = x[s * 3 + 0] - x[d * 3 + 0];
        float dy = x[s * 3 + 1] - x[d * 3 + 1];
        float dz = x[s * 3 + 2] - x[d * 3 + 2];
        diff_s[tid * 3 + 0] = dx; diff_s[tid * 3 + 1] = dy; diff_s[tid * 3 + 2] = dz;
        float dsq = dx * dx + dy * dy + dz * dz;
        watt_s[tid] = Watt[tid];
        be2_s[tid]  = be2[tid];
        bx1_s[tid]  = bx1[tid];
        wx2_s[tid]  = Wx2[tid];
        float4 a0 = *(const float4*)(ea + (size_t)e * 8);
        float4 a1 = *(const float4*)(ea + (size_t)e * 8 + 4);
        uint4 u0, u1;
        u0.x = packh2(dsq,  a0.x); u0.y = packh2(a0.y, a0.z);
        u0.z = packh2(a0.w, a1.x); u0.w = packh2(a1.y, a1.z);
        u1.x = packh2(a1.w, 0.f);  u1.y = 0u; u1.z = 0u; u1.w = 0u;
        *(uint4*)(Es + tid * ESTR) = u0;
        *(uint4*)(Es + tid * ESTR + 8) = u1;
    }
    {
        int n = tid >> 1, half = tid & 1;
        *(uint4*)(Wes + n * ESTR + half * 8) =
            *(const uint4*)((const uint16_t*)g_WeEh + n * 16 + half * 8);
    }
    stage_wt(g_We2h, 128, 0, WsB, tid);
    __syncthreads();

    {   // gather Ps_sum, line-grouped
#pragma unroll
        for (int it = 0; it < 8; it++) {
            int e = eg + it * 2;
            int s = src_s[e], d = dst_s[e];
            uint4 a = *(const uint4*)((const uint16_t*)g_Psrch + (size_t)s * 128 + chnk * 8);
            uint4 b = *(const uint4*)((const uint16_t*)g_Pdsth + (size_t)d * 128 + chnk * 8);
            uint4 r;
            *(__half2*)&r.x = __hadd2(*(__half2*)&a.x, *(__half2*)&b.x);
            *(__half2*)&r.y = __hadd2(*(__half2*)&a.y, *(__half2*)&b.y);
            *(__half2*)&r.z = __hadd2(*(__half2*)&a.z, *(__half2*)&b.z);
            *(__half2*)&r.w = __hadd2(*(__half2*)&a.w, *(__half2*)&b.w);
            *(uint4*)(HsB + (size_t)e * HSTR + chnk * 8) = r;
        }
    }
    __syncthreads();

    float acc[2][8][4];
#pragma unroll
    for (int mt = 0; mt < 2; mt++)
#pragma unroll
        for (int j = 0; j < 8; j++)
#pragma unroll
            for (int q = 0; q < 4; q++) acc[mt][j][q] = 0.f;
    mma_gemm16<ESTR,ESTR>(Es, Wes, 16, m0, n0, lane, acc);

    // epilogue0: hidden = silu(acc + Ps_sum)
    {
        int off = n0 + 16 * t4;
#pragma unroll
        for (int mt = 0; mt < 2; mt++) {
            int rA = m0 + 16 * mt + g4, rB = rA + 8;
            uint16_t* pa = HsB + (size_t)rA * HSTR + off;
            uint16_t* pb = HsB + (size_t)rB * HSTR + off;
            uint4 a0 = *(uint4*)pa, a1 = *(uint4*)(pa + 8);
            uint4 b0 = *(uint4*)pb, b1 = *(uint4*)(pb + 8);
            uint32_t aw[8] = {a0.x,a0.y,a0.z,a0.w,a1.x,a1.y,a1.z,a1.w};
            uint32_t bw[8] = {b0.x,b0.y,b0.z,b0.w,b1.x,b1.y,b1.z,b1.w};
            uint32_t oa[8], ob[8];
#pragma unroll
            for (int j = 0; j < 8; j++) {
                float2 fa = __half22float2(*(__half2*)&aw[j]);
                float2 fb = __half22float2(*(__half2*)&bw[j]);
                oa[j] = packh2(silu_f(acc[mt][j][0] + fa.x), silu_f(acc[mt][j][1] + fa.y));
                ob[j] = packh2(silu_f(acc[mt][j][2] + fb.x), silu_f(acc[mt][j][3] + fb.y));
            }
            *(uint4*)pa       = make_uint4(oa[0], oa[1], oa[2], oa[3]);
            *(uint4*)(pa + 8) = make_uint4(oa[4], oa[5], oa[6], oa[7]);
            *(uint4*)pb       = make_uint4(ob[0], ob[1], ob[2], ob[3]);
            *(uint4*)(pb + 8) = make_uint4(ob[4], ob[5], ob[6], ob[7]);
        }
    }
    __syncthreads();

    // GEMM1: m = hidden @ We2
#pragma unroll
    for (int mt = 0; mt < 2; mt++)
#pragma unroll
        for (int j = 0; j < 8; j++)
#pragma unroll
            for (int q = 0; q < 4; q++) acc[mt][j][q] = 0.f;
    mma_gemm16<HSTR,KSTR>(HsB, WsB, 128, m0, n0, lane, acc);

    float pA[2], pB[2];
#pragma unroll
    for (int mt = 0; mt < 2; mt++) {
        pA[mt] = 0.f; pB[mt] = 0.f;
#pragma unroll
        for (int j = 0; j < 8; j++) {
            int c = n0 + 8 * j + 2 * t4;
            float b0 = be2_s[c], b1 = be2_s[c + 1];
            float w0 = watt_s[c], w1 = watt_s[c + 1];
            acc[mt][j][0] += b0; acc[mt][j][1] += b1;
            acc[mt][j][2] += b0; acc[mt][j][3] += b1;
            pA[mt] = fmaf(acc[mt][j][0], w0, fmaf(acc[mt][j][1], w1, pA[mt]));
            pB[mt] = fmaf(acc[mt][j][2], w0, fmaf(acc[mt][j][3], w1, pB[mt]));
        }
        pA[mt] += __shfl_xor_sync(0xffffffffu, pA[mt], 1);
        pA[mt] += __shfl_xor_sync(0xffffffffu, pA[mt], 2);
        pB[mt] += __shfl_xor_sync(0xffffffffu, pB[mt], 1);
        pB[mt] += __shfl_xor_sync(0xffffffffu, pB[mt], 2);
        if (t4 == 0) {
            red_s[(m0 + 16 * mt + g4) * 2 + (w >> 2)] = pA[mt];
            red_s[(m0 + 16 * mt + g4 + 8) * 2 + (w >> 2)] = pB[mt];
        }
    }
    __syncthreads();
    if (tid < 128) {
        float s = red_s[tid * 2] + red_s[tid * 2 + 1] + batt[0];
        att_s[tid] = sigmoid_f(s);
    }
    __syncthreads();

    // gate + store m (sigma layout)
    {
        int off = n0 + 16 * t4;
#pragma unroll
        for (int mt = 0; mt < 2; mt++) {
            int rA = m0 + 16 * mt + g4, rB = rA + 8;
            float aA = att_s[rA], aB = att_s[rB];
            uint32_t oa[8], ob[8];
#pragma unroll
            for (int j = 0; j < 8; j++) {
                oa[j] = packh2(acc[mt][j][0] * aA, acc[mt][j][1] * aA);
                ob[j] = packh2(acc[mt][j][2] * aB, acc[mt][j][3] * aB);
            }
            uint16_t* pa = HsB + (size_t)rA * HSTR + off;
            uint16_t* pb = HsB + (size_t)rB * HSTR + off;
            *(uint4*)pa       = make_uint4(oa[0], oa[1], oa[2], oa[3]);
            *(uint4*)(pa + 8) = make_uint4(oa[4], oa[5], oa[6], oa[7]);
            *(uint4*)pb       = make_uint4(ob[0], ob[1], ob[2], ob[3]);
            *(uint4*)(pb + 8) = make_uint4(ob[4], ob[5], ob[6], ob[7]);
        }
    }
    stage_wt(g_Wx1h, 128, 0, WsB, tid);
    __syncthreads();

    {   // scatter msg_agg, line-grouped
#pragma unroll
        for (int it = 0; it < 8; it++) {
            int e = eg + it * 2;
            int d = dst_s[e];
            uint4 raw = *(const uint4*)(HsB + (size_t)e * HSTR + chnk * 8);
            float2 f0 = __half22float2(*(__half2*)&raw.x);
            float2 f1 = __half22float2(*(__half2*)&raw.y);
            float2 f2 = __half22float2(*(__half2*)&raw.z);
            float2 f3 = __half22float2(*(__half2*)&raw.w);
            float* p = (float*)g_msg4 + (size_t)d * 128 + chnk * 8;
            red_add_v4(p,     f0.x, f0.y, f1.x, f1.y);
            red_add_v4(p + 4, f2.x, f2.y, f3.x, f3.y);
        }
    }

    // GEMM2: g = silu(m @ Wx1 + bx1); coordw partial = g @ Wx2
#pragma unroll
    for (int mt = 0; mt < 2; mt++)
#pragma unroll
        for (int j = 0; j < 8; j++)
#pragma unroll
            for (int q = 0; q < 4; q++) acc[mt][j][q] = 0.f;
    mma_gemm16<HSTR,KSTR>(HsB, WsB, 128, m0, n0, lane, acc);

#pragma unroll
    for (int mt = 0; mt < 2; mt++) {
        pA[mt] = 0.f; pB[mt] = 0.f;
#pragma unroll
        for (int j = 0; j < 8; j++) {
            int c = n0 + 8 * j + 2 * t4;
            float b0 = bx1_s[c], b1 = bx1_s[c + 1];
            float w0 = wx2_s[c], w1 = wx2_s[c + 1];
            float g0 = silu_f(acc[mt][j][0] + b0);
            float g1 = silu_f(acc[mt][j][1] + b1);
            float g2 = silu_f(acc[mt][j][2] + b0);
            float g3 = silu_f(acc[mt][j][3] + b1);
            pA[mt] = fmaf(g0, w0, fmaf(g1, w1, pA[mt]));
            pB[mt] = fmaf(g2, w0, fmaf(g3, w1, pB[mt]));
        }
        pA[mt] += __shfl_xor_sync(0xffffffffu, pA[mt], 1);
        pA[mt] += __shfl_xor_sync(0xffffffffu, pA[mt], 2);
        pB[mt] += __shfl_xor_sync(0xffffffffu, pB[mt], 1);
        pB[mt] += __shfl_xor_sync(0xffffffffu, pB[mt], 2);
        if (t4 == 0) {
            red_s[(m0 + 16 * mt + g4) * 2 + (w >> 2)] = pA[mt];
            red_s[(m0 + 16 * mt + g4 + 8) * 2 + (w >> 2)] = pB[mt];
        }
    }
    __syncthreads();
    if (tid < 128) {
        float s = red_s[tid * 2] + red_s[tid * 2 + 1] + bx2[0];
        float cw = tanh_ap(s);
        int d = dst_s[tid];
        red_add_f(g_coord + (size_t)d * 3 + 0, diff_s[tid * 3 + 0] * cw);
        red_add_f(g_coord + (size_t)d * 3 + 1, diff_s[tid * 3 + 1] * cw);
        red_add_f(g_coord + (size_t)d * 3 + 2, diff_s[tid * 3 + 2] * cw);
        red_add_f(g_deg + d, 1.0f);
    }
}

// =====================================================================
// Kernel C: node update (fp16 mma, sigma layout internally)
// =====================================================================
__global__ __launch_bounds__(256, 2) void kC(const float* __restrict__ h,
                                             const float* __restrict__ bh1,
                                             const float* __restrict__ bh2,
                                             float* __restrict__ out) {
    extern __shared__ float sm[];
    uint16_t* HsB = (uint16_t*)sm;
    uint16_t* WsB = HsB + 128 * HSTR;
    int tid = threadIdx.x;
    int lane = tid & 31, w = tid >> 5;
    int g4 = lane >> 2, t4 = lane & 3;
    int m0 = (w & 3) * 32, n0 = (w >> 2) * 64;
    int tile0 = blockIdx.x * 128;

    float acc[2][8][4];
#pragma unroll
    for (int mt = 0; mt < 2; mt++)
#pragma unroll
        for (int j = 0; j < 8; j++)
#pragma unroll
            for (int q = 0; q < 4; q++) acc[mt][j][q] = 0.f;

    for (int pass = 0; pass < 2; pass++) {
        const float* src = pass ? (const float*)g_msg4 : h;
        if (pass) __syncthreads();
        {
            int n = tid >> 1, kh = (tid & 1) * 64;
            int gn = tile0 + n;
            uint16_t* d = HsB + (size_t)n * HSTR + kh;
#pragma unroll
            for (int q = 0; q < 8; q++) {
                float4 v0 = make_float4(0.f, 0.f, 0.f, 0.f);
                float4 v1 = make_float4(0.f, 0.f, 0.f, 0.f);
                if (gn < NN) {
                    v0 = *(const float4*)(src + (size_t)gn * 128 + kh + q * 8);
                    v1 = *(const float4*)(src + (size_t)gn * 128 + kh + q * 8 + 4);
                }
                uint4 u;
                u.x = packh2(v0.x, v0.y); u.y = packh2(v0.z, v0.w);
                u.z = packh2(v1.x, v1.y); u.w = packh2(v1.z, v1.w);
                *(uint4*)(d + 8 * q) = u;
            }
        }
        stage_wt(g_Wh1h, 256, pass * 128, WsB, tid);
        __syncthreads();
        mma_gemm16<HSTR,KSTR>(HsB, WsB, 128, m0, n0, lane, acc);
    }

    __syncthreads();
    {
        int off = n0 + 16 * t4;
#pragma unroll
        for (int mt = 0; mt < 2; mt++) {
            int rA = m0 + 16 * mt + g4, rB = rA + 8;
            uint32_t oa[8], ob[8];
#pragma unroll
            for (int j = 0; j < 8; j++) {
                int c = n0 + 8 * j + 2 * t4;
                float2 bb = *(const float2*)(bh1 + c);
                oa[j] = packh2(silu_f(acc[mt][j][0] + bb.x), silu_f(acc[mt][j][1] + bb.y));
                ob[j] = packh2(silu_f(acc[mt][j][2] + bb.x), silu_f(acc[mt][j][3] + bb.y));
            }
            uint16_t* pa = HsB + (size_t)rA * HSTR + off;
            uint16_t* pb = HsB + (size_t)rB * HSTR + off;
            *(uint4*)pa       = make_uint4(oa[0], oa[1], oa[2], oa[3]);
            *(uint4*)(pa + 8) = make_uint4(oa[4], oa[5], oa[6], oa[7]);
            *(uint4*)pb       = make_uint4(ob[0], ob[1], ob[2], ob[3]);
            *(uint4*)(pb + 8) = make_uint4(ob[4], ob[5], ob[6], ob[7]);
        }
    }
    stage_wt(g_Wh2h, 128, 0, WsB, tid);
    __syncthreads();

#pragma unroll
    for (int mt = 0; mt < 2; mt++)
#pragma unroll
        for (int j = 0; j < 8; j++)
#pragma unroll
            for (int q = 0; q < 4; q++) acc[mt][j][q] = 0.f;
    mma_gemm16<HSTR,KSTR>(HsB, WsB, 128, m0, n0, lane, acc);

#pragma unroll
    for (int mt = 0; mt < 2; mt++) {
        int rA = m0 + 16 * mt + g4;
        int gnA = tile0 + rA, gnB = gnA + 8;
#pragma unroll
        for (int j = 0; j < 8; j++) {
            int c = n0 + 8 * j + 2 * t4;
            float2 bb = *(const float2*)(bh2 + c);
            if (gnA < NN) {
                float2 hv = *(const float2*)(h + (size_t)gnA * 128 + c);
                *(float2*)(out + (size_t)gnA * 128 + c) =
                    make_float2(hv.x + acc[mt][j][0] + bb.x,
                                hv.y + acc[mt][j][1] + bb.y);
            }
            if (gnB < NN) {
                float2 hv = *(const float2*)(h + (size_t)gnB * 128 + c);
                *(float2*)(out + (size_t)gnB * 128 + c) =
                    make_float2(hv.x + acc[mt][j][2] + bb.x,
                                hv.y + acc[mt][j][3] + bb.y);
            }
        }
    }
}

// ---- x_out ----
__global__ void kX(const float* __restrict__ x, float* __restrict__ out) {
    int n = blockIdx.x * blockDim.x + threadIdx.x;
    if (n < NN) {
        float inv = 1.f / (g_deg[n] + 1.f);
        float* o = out + (size_t)NN * 128 + (size_t)n * 3;
        o[0] = x[n * 3 + 0] + g_coord[n * 3 + 0] * inv;
        o[1] = x[n * 3 + 1] + g_coord[n * 3 + 1] * inv;
        o[2] = x[n * 3 + 2] + g_coord[n * 3 + 2] * inv;
    }
}

extern "C" void kernel_launch(void* const* d_in, const int* in_sizes, int n_in,
                              void* d_out, int out_size) {
    const float* h    = (const float*)d_in[0];
    const float* x    = (const float*)d_in[1];
    const float* ea   = (const float*)d_in[2];
    const float* temb = (const float*)d_in[3];
    const float* We1w = (const float*)d_in[4];
    const float* We1b = (const float*)d_in[5];
    const float* We2w = (const float*)d_in[6];
    const float* We2b = (const float*)d_in[7];
    const float* Wattw = (const float*)d_in[8];
    const float* Wattb = (const float*)d_in[9];
    const float* Wx1w = (const float*)d_in[10];
    const float* Wx1b = (const float*)d_in[11];
    const float* Wx2w = (const float*)d_in[12];
    const float* Wx2b = (const float*)d_in[13];
    const float* Wh1w = (const float*)d_in[14];
    const float* Wh1b = (const float*)d_in[15];
    const float* Wh2w = (const float*)d_in[16];
    const float* Wh2b = (const float*)d_in[17];
    const int*   eidx = (const int*)d_in[18];
    float* out = (float*)d_out;

    const int smA = 128 * (HSTR + KSTR + TSTR) * 2;
    const int smB = 128 * (HSTR + KSTR) * 2 + 128 * ESTR * 2 * 2 +
                    (256 + 128 * 5 + 384) * 4 + 256 * 4 + 512;
    const int smC = 128 * (HSTR + KSTR) * 2;
    cudaFuncSetAttribute(kA, cudaFuncAttributeMaxDynamicSharedMemorySize, smA);
    cudaFuncSetAttribute(kB, cudaFuncAttributeMaxDynamicSharedMemorySize, smB);
    cudaFuncSetAttribute(kC, cudaFuncAttributeMaxDynamicSharedMemorySize, smC);

    kZero<<<2048, 256>>>();
    kW<<<360, 256>>>(We1w, We2w, Wx1w, Wh1w, Wh2w);
    kA<<<(NN + 127) / 128, 256, smA>>>(h, temb, We1b);
    kB<<<EE / 128, 256, smB>>>(x, ea, eidx, We2b,
                               Wattw, Wattb, Wx1b, Wx2w, Wx2b);
    kC<<<(NN + 127) / 128, 256, smC>>>(h, Wh1b, Wh2b, out);
    kX<<<(NN + 255) / 256, 256>>>(x, out);
}

// round 12
// speedup vs baseline: 1.4960x; 1.0115x over previous
#include <cuda_runtime.h>
#include <cuda_fp16.h>
#include <math.h>
#include <stdint.h>

#define NN 50000
#define EE 800000
#define HSTR 136   // fp16 A-tile stride (halves)
#define KSTR 136   // fp16 B-tile stride (halves) -- kA/kC
#define WSTR 264   // fused We2|Wx1 B-tile stride (halves), K=256
#define ESTR 16    // edge-feature tile stride (halves), 32B rows
#define TSTR 72    // t_emb tile stride (halves)

// sigma layout: logical hidden col c -> physical p
__device__ __host__ __forceinline__ int iperm_c(int p) {
    int r = p & 63;
    return (p & 64) + 8 * ((r >> 1) & 7) + 2 * (r >> 4) + (r & 1);
}

// ---- static device scratch ----
__device__ __half g_Psrch[NN * 128];   // sigma-ordered columns
__device__ __half g_Pdsth[NN * 128];
__device__ float4 g_msg4 [NN * 32];    // sigma-ordered columns
__device__ float  g_coord[NN * 3];
__device__ float  g_deg  [NN];
// pre-transposed fp16 weights [n][k]
__device__ __half g_We2h[128 * 128];   // k sigma-permuted
__device__ __half g_Wx1h[128 * 128];   // k sigma-permuted
__device__ __half g_Wh1h[128 * 256];   // k in [128,256) sigma-permuted
__device__ __half g_Wh2h[128 * 128];   // k sigma-permuted
__device__ __half g_W1ah[128 * 128];
__device__ __half g_W1bh[128 * 128];
__device__ __half g_W1th[128 * 64];
// per-lane precomputed B-fragments of the edge mini-GEMM: [n0half][lane][16]
__device__ uint32_t g_WeEfrag[2 * 32 * 16];

// ---- fast transcendentals ----
__device__ __forceinline__ float tanh_ap(float x) {
    float r;
    asm("tanh.approx.f32 %0, %1;" : "=f"(r) : "f"(x));
    return r;
}
__device__ __forceinline__ float silu_f(float v) {
    float hv = 0.5f * v;
    return fmaf(hv, tanh_ap(hv), hv);
}
__device__ __forceinline__ float sigmoid_f(float s) {
    return fmaf(0.5f, tanh_ap(0.5f * s), 0.5f);
}

__device__ __forceinline__ void red_add_v4(float* p, float a, float b, float c, float d) {
    asm volatile("red.global.add.v4.f32 [%0], {%1,%2,%3,%4};"
                 :: "l"(p), "f"(a), "f"(b), "f"(c), "f"(d) : "memory");
}
__device__ __forceinline__ void red_add_f(float* p, float a) {
    asm volatile("red.global.add.f32 [%0], %1;" :: "l"(p), "f"(a) : "memory");
}
__device__ __forceinline__ uint32_t packh2(float a, float b) {
    __half2 h = __floats2half2_rn(a, b);
    return *(uint32_t*)&h;
}
__device__ __forceinline__ void mma_f16(float c[4], const uint32_t a[4], const uint32_t b[2]) {
    asm volatile("mma.sync.aligned.m16n8k16.row.col.f32.f16.f16.f32 "
                 "{%0,%1,%2,%3}, {%4,%5,%6,%7}, {%8,%9}, {%0,%1,%2,%3};"
                 : "+f"(c[0]), "+f"(c[1]), "+f"(c[2]), "+f"(c[3])
                 : "r"(a[0]), "r"(a[1]), "r"(a[2]), "r"(a[3]),
                   "r"(b[0]), "r"(b[1]));
}
__device__ __forceinline__ void ldsm4(uint32_t r[4], uint32_t addr) {
    asm volatile("ldmatrix.sync.aligned.m8n8.x4.shared.b16 {%0,%1,%2,%3}, [%4];"
                 : "=r"(r[0]), "=r"(r[1]), "=r"(r[2]), "=r"(r[3]) : "r"(addr));
}
__device__ __forceinline__ uint32_t s2u(const void* p) {
    return (uint32_t)__cvta_generic_to_shared(p);
}
#define BARH(h) asm volatile("bar.sync %0, 128;" :: "r"(1 + (h)) : "memory")

// stage pre-transposed fp16 weight [128][srcK] slice -> smem [n][KSTR]
__device__ __forceinline__ void stage_wt(const __half* __restrict__ src, int srcK,
                                         int kOff, uint16_t* __restrict__ WsB, int tid) {
    int n = tid >> 1, kh = (tid & 1) * 64;
    const uint16_t* s = (const uint16_t*)src + (size_t)n * srcK + kOff + kh;
    uint16_t* d = WsB + n * KSTR + kh;
#pragma unroll
    for (int q = 0; q < 8; q++)
        *(uint4*)(d + 8 * q) = *(const uint4*)(s + 8 * q);
}
__device__ __forceinline__ void stage_wt64(const __half* __restrict__ src,
                                           uint16_t* __restrict__ WsB, int tid) {
    int n = tid >> 1, kh = (tid & 1) * 32;
    const uint16_t* s = (const uint16_t*)src + (size_t)n * 64 + kh;
    uint16_t* d = WsB + n * KSTR + kh;
#pragma unroll
    for (int q = 0; q < 4; q++)
        *(uint4*)(d + 8 * q) = *(const uint4*)(s + 8 * q);
}

// warp fp16 GEMM via ldmatrix; B cols at kOff..kOff+K
template<int AS, int BS>
__device__ __forceinline__ void mma_gemm16(const uint16_t* __restrict__ Hs,
                                           const uint16_t* __restrict__ Ws,
                                           int K, int kOff, int m0, int n0, int lane,
                                           float acc[2][8][4]) {
    int lrow = lane & 7, lmi = lane >> 3;
    uint32_t abase = s2u(Hs) +
        (uint32_t)(((m0 + (lmi & 1) * 8 + lrow) * AS + (lmi >> 1) * 8) * 2);
    uint32_t bbase = s2u(Ws) +
        (uint32_t)(((n0 + (lmi >> 1) * 8 + lrow) * BS + (lmi & 1) * 8 + kOff) * 2);
#pragma unroll
    for (int k0 = 0; k0 < K; k0 += 16) {
        uint32_t b[4][4];
#pragma unroll
        for (int jp = 0; jp < 4; jp++)
            ldsm4(b[jp], bbase + (uint32_t)((16 * jp * BS + k0) * 2));
        uint32_t a[2][4];
#pragma unroll
        for (int mt = 0; mt < 2; mt++)
            ldsm4(a[mt], abase + (uint32_t)((16 * mt * AS + k0) * 2));
#pragma unroll
        for (int mt = 0; mt < 2; mt++)
#pragma unroll
            for (int j = 0; j < 8; j++)
                mma_f16(acc[mt][j], a[mt], &b[j >> 1][(j & 1) * 2]);
    }
}

// ---- zero accumulators ----
__global__ void kZero() {
    float* msg = (float*)g_msg4;
    long total = (long)NN * 128 + NN * 3 + NN;
    for (long i = blockIdx.x * (long)blockDim.x + threadIdx.x; i < total;
         i += (long)gridDim.x * blockDim.x) {
        if (i < (long)NN * 128)             msg[i] = 0.f;
        else if (i < (long)NN * 128 + NN*3) g_coord[i - (long)NN * 128] = 0.f;
        else                                g_deg[i - (long)NN * 128 - NN * 3] = 0.f;
    }
}

// ---- weight transpose + fp16 convert ----
__global__ void kW(const float* __restrict__ We1, const float* __restrict__ We2,
                   const float* __restrict__ Wx1,
                   const float* __restrict__ Wh1, const float* __restrict__ Wh2) {
    int i = blockIdx.x * blockDim.x + threadIdx.x;
    if (i < 16384) {
        int n = i >> 7, p = i & 127;
        int k = iperm_c(p);
        g_We2h[i] = __float2half_rn(We2[k * 128 + n]);
        g_Wx1h[i] = __float2half_rn(Wx1[k * 128 + n]);
        g_Wh2h[i] = __float2half_rn(Wh2[k * 128 + n]);
    } else if (i < 49152) {
        int j = i - 16384;
        int n = j >> 8, k = j & 255;
        int kk = (k < 128) ? k : (128 + iperm_c(k - 128));
        g_Wh1h[j] = __float2half_rn(Wh1[kk * 128 + n]);
    } else if (i < 65536) {
        int j = i - 49152;
        int n = j >> 7, k = j & 127;
        g_W1ah[j] = __float2half_rn(We1[k * 128 + n]);
    } else if (i < 81920) {
        int j = i - 65536;
        int n = j >> 7, k = j & 127;
        g_W1bh[j] = __float2half_rn(We1[(128 + k) * 128 + n]);
    } else if (i < 90112) {
        int j = i - 81920;
        int n = j >> 6, k = j & 63;
        g_W1th[j] = __float2half_rn(We1[(265 + k) * 128 + n]);
    } else if (i < 91136) {
        // mini-GEMM B-fragments: [nv][lane][jp*4+mi]
        int j = i - 90112;
        int nv = j >> 9, rem = j & 511;
        int lane = rem >> 4, q = rem & 15;
        int jp = q >> 2, mi = q & 3;
        int n = nv * 64 + 16 * jp + 8 * (mi >> 1) + (lane >> 2);
        int k = 8 * (mi & 1) + 2 * (lane & 3);
        float v0 = 0.f, v1 = 0.f;
        if (k == 0)      v0 = We1[256 * 128 + n];
        else if (k <= 8) v0 = We1[(256 + k) * 128 + n];
        if (k + 1 <= 8 && k + 1 >= 1) v1 = We1[(256 + k + 1) * 128 + n];
        g_WeEfrag[j] = packh2(v0, v1);
    }
}

// =====================================================================
// Kernel A: per-node precompute (fp16 mma), sigma-ordered P
// =====================================================================
__global__ __launch_bounds__(256, 2) void kA(const float* __restrict__ h,
                                             const float* __restrict__ temb,
                                             const float* __restrict__ be1) {
    extern __shared__ float sm[];
    uint16_t* HsB = (uint16_t*)sm;
    uint16_t* WsB = HsB + 128 * HSTR;
    uint16_t* Ts  = WsB + 128 * KSTR;
    int tid = threadIdx.x;
    int lane = tid & 31, w = tid >> 5;
    int g4 = lane >> 2, t4 = lane & 3;
    int m0 = (w & 3) * 32, n0 = (w >> 2) * 64;
    int tile0 = blockIdx.x * 128;

    {
        int n = tid >> 1, kh = (tid & 1) * 64;
        int gn = tile0 + n;
        uint16_t* d = HsB + (size_t)n * HSTR + kh;
#pragma unroll
        for (int q = 0; q < 8; q++) {
            float4 v0 = make_float4(0.f,0.f,0.f,0.f), v1 = v0;
            if (gn < NN) {
                v0 = *(const float4*)(h + (size_t)gn * 128 + kh + q * 8);
                v1 = *(const float4*)(h + (size_t)gn * 128 + kh + q * 8 + 4);
            }
            uint4 u;
            u.x = packh2(v0.x, v0.y); u.y = packh2(v0.z, v0.w);
            u.z = packh2(v1.x, v1.y); u.w = packh2(v1.z, v1.w);
            *(uint4*)(d + 8 * q) = u;
        }
    }
    {
        int n = tid >> 1, kh = (tid & 1) * 32;
        int gn = tile0 + n;
        uint16_t* d = Ts + (size_t)n * TSTR + kh;
#pragma unroll
        for (int q = 0; q < 4; q++) {
            float4 v0 = make_float4(0.f,0.f,0.f,0.f), v1 = v0;
            if (gn < NN) {
                v0 = *(const float4*)(temb + (size_t)gn * 64 + kh + q * 8);
                v1 = *(const float4*)(temb + (size_t)gn * 64 + kh + q * 8 + 4);
            }
            uint4 u;
            u.x = packh2(v0.x, v0.y); u.y = packh2(v0.z, v0.w);
            u.z = packh2(v1.x, v1.y); u.w = packh2(v1.z, v1.w);
            *(uint4*)(d + 8 * q) = u;
        }
    }
    stage_wt(g_W1ah, 128, 0, WsB, tid);
    __syncthreads();

    float acc[2][8][4];
#pragma unroll
    for (int mt = 0; mt < 2; mt++)
#pragma unroll
        for (int j = 0; j < 8; j++)
#pragma unroll
            for (int q = 0; q < 4; q++) acc[mt][j][q] = 0.f;
    mma_gemm16<HSTR,KSTR>(HsB, WsB, 128, 0, m0, n0, lane, acc);
    __syncthreads();
    stage_wt64(g_W1th, WsB, tid);
    __syncthreads();
    mma_gemm16<TSTR,KSTR>(Ts, WsB, 64, 0, m0, n0, lane, acc);

    {
        int off = n0 + 16 * t4;
#pragma unroll
        for (int mt = 0; mt < 2; mt++) {
            int rA = m0 + 16 * mt + g4;
            int gnA = tile0 + rA, gnB = gnA + 8;
            uint32_t wa[8], wb[8];
#pragma unroll
            for (int j = 0; j < 8; j++) {
                int c = n0 + 8 * j + 2 * t4;
                float2 bb = *(const float2*)(be1 + c);
                wa[j] = packh2(acc[mt][j][0] + bb.x, acc[mt][j][1] + bb.y);
                wb[j] = packh2(acc[mt][j][2] + bb.x, acc[mt][j][3] + bb.y);
            }
            if (gnA < NN) {
                uint16_t* p = (uint16_t*)g_Psrch + (size_t)gnA * 128 + off;
                *(uint4*)p       = make_uint4(wa[0], wa[1], wa[2], wa[3]);
                *(uint4*)(p + 8) = make_uint4(wa[4], wa[5], wa[6], wa[7]);
            }
            if (gnB < NN) {
                uint16_t* p = (uint16_t*)g_Psrch + (size_t)gnB * 128 + off;
                *(uint4*)p       = make_uint4(wb[0], wb[1], wb[2], wb[3]);
                *(uint4*)(p + 8) = make_uint4(wb[4], wb[5], wb[6], wb[7]);
            }
        }
    }
    __syncthreads();
    stage_wt(g_W1bh, 128, 0, WsB, tid);
    __syncthreads();
#pragma unroll
    for (int mt = 0; mt < 2; mt++)
#pragma unroll
        for (int j = 0; j < 8; j++)
#pragma unroll
            for (int q = 0; q < 4; q++) acc[mt][j][q] = 0.f;
    mma_gemm16<HSTR,KSTR>(HsB, WsB, 128, 0, m0, n0, lane, acc);
    {
        int off = n0 + 16 * t4;
#pragma unroll
        for (int mt = 0; mt < 2; mt++) {
            int rA = m0 + 16 * mt + g4;
            int gnA = tile0 + rA, gnB = gnA + 8;
            uint32_t wa[8], wb[8];
#pragma unroll
            for (int j = 0; j < 8; j++) {
                wa[j] = packh2(acc[mt][j][0], acc[mt][j][1]);
                wb[j] = packh2(acc[mt][j][2], acc[mt][j][3]);
            }
            if (gnA < NN) {
                uint16_t* p = (uint16_t*)g_Pdsth + (size_t)gnA * 128 + off;
                *(uint4*)p       = make_uint4(wa[0], wa[1], wa[2], wa[3]);
                *(uint4*)(p + 8) = make_uint4(wa[4], wa[5], wa[6], wa[7]);
            }
            if (gnB < NN) {
                uint16_t* p = (uint16_t*)g_Pdsth + (size_t)gnB * 128 + off;
                *(uint4*)p       = make_uint4(wb[0], wb[1], wb[2], wb[3]);
                *(uint4*)(p + 8) = make_uint4(wb[4], wb[5], wb[6], wb[7]);
            }
        }
    }
}

// =====================================================================
// Kernel B: fused edge pipeline, 128 edges per block,
//           split into two independent 64-edge halves (named barriers)
// =====================================================================
__global__ __launch_bounds__(256, 2) void kB(const float* __restrict__ x,
                                             const float* __restrict__ ea,
                                             const int* __restrict__ eidx,
                                             const float* __restrict__ be2,
                                             const float* __restrict__ Watt,
                                             const float* __restrict__ batt,
                                             const float* __restrict__ bx1,
                                             const float* __restrict__ Wx2,
                                             const float* __restrict__ bx2) {
    extern __shared__ float sm[];
    uint16_t* HsB = (uint16_t*)sm;                 // 128*HSTR
    uint16_t* WsB = HsB + 128 * HSTR;              // 128*WSTR (We2 | Wx1)
    uint16_t* Es  = WsB + 128 * WSTR;              // 128*ESTR
    float* watt_s = (float*)(Es + 128 * ESTR);     // 128
    float* be2_s  = watt_s + 128;                  // 128
    float* bx1_s  = be2_s + 128;                   // 128
    float* wx2_s  = bx1_s + 128;                   // 128
    float* att_s  = wx2_s + 128;                   // 128 (64 per half)
    float* red_s  = att_s + 128;                   // 256 (128 per half)
    float* diff_s = red_s + 256;                   // 384
    int* src_s = (int*)(diff_s + 384);             // 128
    int* dst_s = src_s + 128;                      // 128

    int tid = threadIdx.x;
    int lane = tid & 31, w = tid >> 5;
    int g4 = lane >> 2, t4 = lane & 3;
    int hf = w >> 2, ww = w & 3;
    int m0 = 64 * hf + (ww & 1) * 32;              // global row base
    int n0 = ((ww >> 1) & 1) * 64;
    int e0 = blockIdx.x * 128;
    int eg   = 64 * hf + ((ww & 3) << 4) + (lane >> 4);
    int chnk = lane & 15;

    if (tid < 128) {
        int e = e0 + tid;
        int s = eidx[e], d = eidx[EE + e];
        src_s[tid] = s; dst_s[tid] = d;
        float dx = x[s * 3 + 0] - x[d * 3 + 0];
        float dy = x[s * 3 + 1] - x[d * 3 + 1];
        float dz = x[s * 3 + 2] - x[d * 3 + 2];
        diff_s[tid * 3 + 0] = dx; diff_s[tid * 3 + 1] = dy; diff_s[tid * 3 + 2] = dz;
        float dsq = dx * dx + dy * dy + dz * dz;
        watt_s[tid] = Watt[tid];
        be2_s[tid]  = be2[tid];
        bx1_s[tid]  = bx1[tid];
        wx2_s[tid]  = Wx2[tid];
        float4 a0 = *(const float4*)(ea + (size_t)e * 8);
        float4 a1 = *(const float4*)(ea + (size_t)e * 8 + 4);
        uint4 u0, u1;
        u0.x = packh2(dsq,  a0.x); u0.y = packh2(a0.y, a0.z);
        u0.z = packh2(a0.w, a1.x); u0.w = packh2(a1.y, a1.z);
        u1.x = packh2(a1.w, 0.f);  u1.y = 0u; u1.z = 0u; u1.w = 0u;
        *(uint4*)(Es + tid * ESTR) = u0;
        *(uint4*)(Es + tid * ESTR + 8) = u1;
    }
    {   // stage BOTH weights into fused buffer: We2 -> k[0,128), Wx1 -> k[128,256)
        int n = tid >> 1, kh = (tid & 1) * 64;
        const uint16_t* s2 = (const uint16_t*)g_We2h + (size_t)n * 128 + kh;
        const uint16_t* s1 = (const uint16_t*)g_Wx1h + (size_t)n * 128 + kh;
        uint16_t* d2 = WsB + n * WSTR + kh;
        uint16_t* d1 = WsB + n * WSTR + 128 + kh;
#pragma unroll
        for (int q = 0; q < 8; q++) {
            *(uint4*)(d2 + 8 * q) = *(const uint4*)(s2 + 8 * q);
            *(uint4*)(d1 + 8 * q) = *(const uint4*)(s1 + 8 * q);
        }
    }
    // mini-GEMM B-fragments from global
    uint32_t bfr[16];
    {
        const uint4* fbp = (const uint4*)g_WeEfrag + ((n0 >> 6) * 32 + lane) * 4;
        uint4 f0 = fbp[0], f1 = fbp[1], f2 = fbp[2], f3 = fbp[3];
        bfr[0]=f0.x; bfr[1]=f0.y; bfr[2]=f0.z; bfr[3]=f0.w;
        bfr[4]=f1.x; bfr[5]=f1.y; bfr[6]=f1.z; bfr[7]=f1.w;
        bfr[8]=f2.x; bfr[9]=f2.y; bfr[10]=f2.z; bfr[11]=f2.w;
        bfr[12]=f3.x; bfr[13]=f3.y; bfr[14]=f3.z; bfr[15]=f3.w;
    }
    __syncthreads();

    {   // gather Ps_sum for own half, line-grouped
#pragma unroll
        for (int it = 0; it < 8; it++) {
            int e = eg + it * 2;
            int s = src_s[e], d = dst_s[e];
            uint4 a = *(const uint4*)((const uint16_t*)g_Psrch + (size_t)s * 128 + chnk * 8);
            uint4 b = *(const uint4*)((const uint16_t*)g_Pdsth + (size_t)d * 128 + chnk * 8);
            uint4 r;
            *(__half2*)&r.x = __hadd2(*(__half2*)&a.x, *(__half2*)&b.x);
            *(__half2*)&r.y = __hadd2(*(__half2*)&a.y, *(__half2*)&b.y);
            *(__half2*)&r.z = __hadd2(*(__half2*)&a.z, *(__half2*)&b.z);
            *(__half2*)&r.w = __hadd2(*(__half2*)&a.w, *(__half2*)&b.w);
            *(uint4*)(HsB + (size_t)e * HSTR + chnk * 8) = r;
        }
    }
    BARH(hf);

    float acc[2][8][4];
#pragma unroll
    for (int mt = 0; mt < 2; mt++)
#pragma unroll
        for (int j = 0; j < 8; j++)
#pragma unroll
            for (int q = 0; q < 4; q++) acc[mt][j][q] = 0.f;
    {   // mini-GEMM: edge-feature contribution (K=16), A from Es, B from regs
        int lrow = lane & 7, lmi = lane >> 3;
        uint32_t abase = s2u(Es) +
            (uint32_t)(((m0 + (lmi & 1) * 8 + lrow) * ESTR + (lmi >> 1) * 8) * 2);
        uint32_t aE[2][4];
#pragma unroll
        for (int mt = 0; mt < 2; mt++)
            ldsm4(aE[mt], abase + (uint32_t)(16 * mt * ESTR * 2));
#pragma unroll
        for (int mt = 0; mt < 2; mt++)
#pragma unroll
            for (int j = 0; j < 8; j++)
                mma_f16(acc[mt][j], aE[mt], &bfr[(j >> 1) * 4 + (j & 1) * 2]);
    }

    // epilogue0: hidden = silu(acc + Ps_sum)
    {
        int off = n0 + 16 * t4;
#pragma unroll
        for (int mt = 0; mt < 2; mt++) {
            int rA = m0 + 16 * mt + g4, rB = rA + 8;
            uint16_t* pa = HsB + (size_t)rA * HSTR + off;
            uint16_t* pb = HsB + (size_t)rB * HSTR + off;
            uint4 a0 = *(uint4*)pa, a1 = *(uint4*)(pa + 8);
            uint4 b0 = *(uint4*)pb, b1 = *(uint4*)(pb + 8);
            uint32_t aw[8] = {a0.x,a0.y,a0.z,a0.w,a1.x,a1.y,a1.z,a1.w};
            uint32_t bw[8] = {b0.x,b0.y,b0.z,b0.w,b1.x,b1.y,b1.z,b1.w};
            uint32_t oa[8], ob[8];
#pragma unroll
            for (int j = 0; j < 8; j++) {
                float2 fa = __half22float2(*(__half2*)&aw[j]);
                float2 fb = __half22float2(*(__half2*)&bw[j]);
                oa[j] = packh2(silu_f(acc[mt][j][0] + fa.x), silu_f(acc[mt][j][1] + fa.y));
                ob[j] = packh2(silu_f(acc[mt][j][2] + fb.x), silu_f(acc[mt][j][3] + fb.y));
            }
            *(uint4*)pa       = make_uint4(oa[0], oa[1], oa[2], oa[3]);
            *(uint4*)(pa + 8) = make_uint4(oa[4], oa[5], oa[6], oa[7]);
            *(uint4*)pb       = make_uint4(ob[0], ob[1], ob[2], ob[3]);
            *(uint4*)(pb + 8) = make_uint4(ob[4], ob[5], ob[6], ob[7]);
        }
    }
    BARH(hf);

    // GEMM1: m = hidden @ We2 (fused buffer, kOff=0)
#pragma unroll
    for (int mt = 0; mt < 2; mt++)
#pragma unroll
        for (int j = 0; j < 8; j++)
#pragma unroll
            for (int q = 0; q < 4; q++) acc[mt][j][q] = 0.f;
    mma_gemm16<HSTR,WSTR>(HsB, WsB, 128, 0, m0, n0, lane, acc);

    float pA[2], pB[2];
#pragma unroll
    for (int mt = 0; mt < 2; mt++) {
        pA[mt] = 0.f; pB[mt] = 0.f;
#pragma unroll
        for (int j = 0; j < 8; j++) {
            int c = n0 + 8 * j + 2 * t4;
            float b0 = be2_s[c], b1 = be2_s[c + 1];
            float w0 = watt_s[c], w1 = watt_s[c + 1];
            acc[mt][j][0] += b0; acc[mt][j][1] += b1;
            acc[mt][j][2] += b0; acc[mt][j][3] += b1;
            pA[mt] = fmaf(acc[mt][j][0], w0, fmaf(acc[mt][j][1], w1, pA[mt]));
            pB[mt] = fmaf(acc[mt][j][2], w0, fmaf(acc[mt][j][3], w1, pB[mt]));
        }
        pA[mt] += __shfl_xor_sync(0xffffffffu, pA[mt], 1);
        pA[mt] += __shfl_xor_sync(0xffffffffu, pA[mt], 2);
        pB[mt] += __shfl_xor_sync(0xffffffffu, pB[mt], 1);
        pB[mt] += __shfl_xor_sync(0xffffffffu, pB[mt], 2);
        if (t4 == 0) {
            int rl = (ww & 1) * 32 + 16 * mt + g4;  // 0..63 within half
            red_s[hf * 128 + rl * 2 + ((ww >> 1) & 1)] = pA[mt];
            red_s[hf * 128 + (rl + 8) * 2 + ((ww >> 1) & 1)] = pB[mt];
        }
    }
    BARH(hf);
    {
        int t = tid & 127;
        if (t < 64) {
            float s = red_s[hf * 128 + t * 2] + red_s[hf * 128 + t * 2 + 1] + batt[0];
            att_s[hf * 64 + t] = sigmoid_f(s);
        }
    }
    BARH(hf);

    // gate + store m (sigma layout)
    {
        int off = n0 + 16 * t4;
#pragma unroll
        for (int mt = 0; mt < 2; mt++) {
            int rA = m0 + 16 * mt + g4, rB = rA + 8;
            int rl = rA - 64 * hf;
            float aA = att_s[hf * 64 + rl], aB = att_s[hf * 64 + rl + 8];
            uint32_t oa[8], ob[8];
#pragma unroll
            for (int j = 0; j < 8; j++) {
                oa[j] = packh2(acc[mt][j][0] * aA, acc[mt][j][1] * aA);
                ob[j] = packh2(acc[mt][j][2] * aB, acc[mt][j][3] * aB);
            }
            uint16_t* pa = HsB + (size_t)rA * HSTR + off;
            uint16_t* pb = HsB + (size_t)rB * HSTR + off;
            *(uint4*)pa       = make_uint4(oa[0], oa[1], oa[2], oa[3]);
            *(uint4*)(pa + 8) = make_uint4(oa[4], oa[5], oa[6], oa[7]);
            *(uint4*)pb       = make_uint4(ob[0], ob[1], ob[2], ob[3]);
            *(uint4*)(pb + 8) = make_uint4(ob[4], ob[5], ob[6], ob[7]);
        }
    }
    BARH(hf);

    {   // scatter msg_agg for own half, line-grouped
#pragma unroll
        for (int it = 0; it < 8; it++) {
            int e = eg + it * 2;
            int d = dst_s[e];
            uint4 raw = *(const uint4*)(HsB + (size_t)e * HSTR + chnk * 8);
            float2 f0 = __half22float2(*(__half2*)&raw.x);
            float2 f1 = __half22float2(*(__half2*)&raw.y);
            float2 f2 = __half22float2(*(__half2*)&raw.z);
            float2 f3 = __half22float2(*(__half2*)&raw.w);
            float* p = (float*)g_msg4 + (size_t)d * 128 + chnk * 8;
            red_add_v4(p,     f0.x, f0.y, f1.x, f1.y);
            red_add_v4(p + 4, f2.x, f2.y, f3.x, f3.y);
        }
    }

    // GEMM2: g = silu(m @ Wx1 + bx1); coordw partial = g @ Wx2 (kOff=128)
#pragma unroll
    for (int mt = 0; mt < 2; mt++)
#pragma unroll
        for (int j = 0; j < 8; j++)
#pragma unroll
            for (int q = 0; q < 4; q++) acc[mt][j][q] = 0.f;
    mma_gemm16<HSTR,WSTR>(HsB, WsB, 128, 128, m0, n0, lane, acc);

#pragma unroll
    for (int mt = 0; mt < 2; mt++) {
        pA[mt] = 0.f; pB[mt] = 0.f;
#pragma unroll
        for (int j = 0; j < 8; j++) {
            int c = n0 + 8 * j + 2 * t4;
            float b0 = bx1_s[c], b1 = bx1_s[c + 1];
            float w0 = wx2_s[c], w1 = wx2_s[c + 1];
            float g0 = silu_f(acc[mt][j][0] + b0);
            float g1 = silu_f(acc[mt][j][1] + b1);
            float g2 = silu_f(acc[mt][j][2] + b0);
            float g3 = silu_f(acc[mt][j][3] + b1);
            pA[mt] = fmaf(g0, w0, fmaf(g1, w1, pA[mt]));
            pB[mt] = fmaf(g2, w0, fmaf(g3, w1, pB[mt]));
        }
        pA[mt] += __shfl_xor_sync(0xffffffffu, pA[mt], 1);
        pA[mt] += __shfl_xor_sync(0xffffffffu, pA[mt], 2);
        pB[mt] += __shfl_xor_sync(0xffffffffu, pB[mt], 1);
        pB[mt] += __shfl_xor_sync(0xffffffffu, pB[mt], 2);
        if (t4 == 0) {
            int rl = (ww & 1) * 32 + 16 * mt + g4;
            red_s[hf * 128 + rl * 2 + ((ww >> 1) & 1)] = pA[mt];
            red_s[hf * 128 + (rl + 8) * 2 + ((ww >> 1) & 1)] = pB[mt];
        }
    }
    BARH(hf);
    {
        int t = tid & 127;
        if (t < 64) {
            float s = red_s[hf * 128 + t * 2] + red_s[hf * 128 + t * 2 + 1] + bx2[0];
            float cw = tanh_ap(s);
            int e = 64 * hf + t;
            int d = dst_s[e];
            red_add_f(g_coord + (size_t)d * 3 + 0, diff_s[e * 3 + 0] * cw);
            red_add_f(g_coord + (size_t)d * 3 + 1, diff_s[e * 3 + 1] * cw);
            red_add_f(g_coord + (size_t)d * 3 + 2, diff_s[e * 3 + 2] * cw);
            red_add_f(g_deg + d, 1.0f);
        }
    }
}

// =====================================================================
// Kernel C: node update (fp16 mma, sigma layout internally)
// =====================================================================
__global__ __launch_bounds__(256, 2) void kC(const float* __restrict__ h,
                                             const float* __restrict__ bh1,
                                             const float* __restrict__ bh2,
                                             float* __restrict__ out) {
    extern __shared__ float sm[];
    uint16_t* HsB = (uint16_t*)sm;
    uint16_t* WsB = HsB + 128 * HSTR;
    int tid = threadIdx.x;
    int lane = tid & 31, w = tid >> 5;
    int g4 = lane >> 2, t4 = lane & 3;
    int m0 = (w & 3) * 32, n0 = (w >> 2) * 64;
    int tile0 = blockIdx.x * 128;

    float acc[2][8][4];
#pragma unroll
    for (int mt = 0; mt < 2; mt++)
#pragma unroll
        for (int j = 0; j < 8; j++)
#pragma unroll
            for (int q = 0; q < 4; q++) acc[mt][j][q] = 0.f;

    for (int pass = 0; pass < 2; pass++) {
        const float* src = pass ? (const float*)g_msg4 : h;
        if (pass) __syncthreads();
        {
            int n = tid >> 1, kh = (tid & 1) * 64;
            int gn = tile0 + n;
            uint16_t* d = HsB + (size_t)n * HSTR + kh;
#pragma unroll
            for (int q = 0; q < 8; q++) {
                float4 v0 = make_float4(0.f, 0.f, 0.f, 0.f);
                float4 v1 = make_float4(0.f, 0.f, 0.f, 0.f);
                if (gn < NN) {
                    v0 = *(const float4*)(src + (size_t)gn * 128 + kh + q * 8);
                    v1 = *(const float4*)(src + (size_t)gn * 128 + kh + q * 8 + 4);
                }
                uint4 u;
                u.x = packh2(v0.x, v0.y); u.y = packh2(v0.z, v0.w);
                u.z = packh2(v1.x, v1.y); u.w = packh2(v1.z, v1.w);
                *(uint4*)(d + 8 * q) = u;
            }
        }
        stage_wt(g_Wh1h, 256, pass * 128, WsB, tid);
        __syncthreads();
        mma_gemm16<HSTR,KSTR>(HsB, WsB, 128, 0, m0, n0, lane, acc);
    }

    __syncthreads();
    {
        int off = n0 + 16 * t4;
#pragma unroll
        for (int mt = 0; mt < 2; mt++) {
            int rA = m0 + 16 * mt + g4, rB = rA + 8;
            uint32_t oa[8], ob[8];
#pragma unroll
            for (int j = 0; j < 8; j++) {
                int c = n0 + 8 * j + 2 * t4;
                float2 bb = *(const float2*)(bh1 + c);
                oa[j] = packh2(silu_f(acc[mt][j][0] + bb.x), silu_f(acc[mt][j][1] + bb.y));
                ob[j] = packh2(silu_f(acc[mt][j][2] + bb.x), silu_f(acc[mt][j][3] + bb.y));
            }
            uint16_t* pa = HsB + (size_t)rA * HSTR + off;
            uint16_t* pb = HsB + (size_t)rB * HSTR + off;
            *(uint4*)pa       = make_uint4(oa[0], oa[1], oa[2], oa[3]);
            *(uint4*)(pa + 8) = make_uint4(oa[4], oa[5], oa[6], oa[7]);
            *(uint4*)pb       = make_uint4(ob[0], ob[1], ob[2], ob[3]);
            *(uint4*)(pb + 8) = make_uint4(ob[4], ob[5], ob[6], ob[7]);
        }
    }
    stage_wt(g_Wh2h, 128, 0, WsB, tid);
    __syncthreads();

#pragma unroll
    for (int mt = 0; mt < 2; mt++)
#pragma unroll
        for (int j = 0; j < 8; j++)
#pragma unroll
            for (int q = 0; q < 4; q++) acc[mt][j][q] = 0.f;
    mma_gemm16<HSTR,KSTR>(HsB, WsB, 128, 0, m0, n0, lane, acc);

#pragma unroll
    for (int mt = 0; mt < 2; mt++) {
        int rA = m0 + 16 * mt + g4;
        int gnA = tile0 + rA, gnB = gnA + 8;
#pragma unroll
        for (int j = 0; j < 8; j++) {
            int c = n0 + 8 * j + 2 * t4;
            float2 bb = *(const float2*)(bh2 + c);
            if (gnA < NN) {
                float2 hv = *(const float2*)(h + (size_t)gnA * 128 + c);
                *(float2*)(out + (size_t)gnA * 128 + c) =
                    make_float2(hv.x + acc[mt][j][0] + bb.x,
                                hv.y + acc[mt][j][1] + bb.y);
            }
            if (gnB < NN) {
                float2 hv = *(const float2*)(h + (size_t)gnB * 128 + c);
                *(float2*)(out + (size_t)gnB * 128 + c) =
                    make_float2(hv.x + acc[mt][j][2] + bb.x,
                                hv.y + acc[mt][j][3] + bb.y);
            }
        }
    }
}

// ---- x_out ----
__global__ void kX(const float* __restrict__ x, float* __restrict__ out) {
    int n = blockIdx.x * blockDim.x + threadIdx.x;
    if (n < NN) {
        float inv = 1.f / (g_deg[n] + 1.f);
        float* o = out + (size_t)NN * 128 + (size_t)n * 3;
        o[0] = x[n * 3 + 0] + g_coord[n * 3 + 0] * inv;
        o[1] = x[n * 3 + 1] + g_coord[n * 3 + 1] * inv;
        o[2] = x[n * 3 + 2] + g_coord[n * 3 + 2] * inv;
    }
}

extern "C" void kernel_launch(void* const* d_in, const int* in_sizes, int n_in,
                              void* d_out, int out_size) {
    const float* h    = (const float*)d_in[0];
    const float* x    = (const float*)d_in[1];
    const float* ea   = (const float*)d_in[2];
    const float* temb = (const float*)d_in[3];
    const float* We1w = (const float*)d_in[4];
    const float* We1b = (const float*)d_in[5];
    const float* We2w = (const float*)d_in[6];
    const float* We2b = (const float*)d_in[7];
    const float* Wattw = (const float*)d_in[8];
    const float* Wattb = (const float*)d_in[9];
    const float* Wx1w = (const float*)d_in[10];
    const float* Wx1b = (const float*)d_in[11];
    const float* Wx2w = (const float*)d_in[12];
    const float* Wx2b = (const float*)d_in[13];
    const float* Wh1w = (const float*)d_in[14];
    const float* Wh1b = (const float*)d_in[15];
    const float* Wh2w = (const float*)d_in[16];
    const float* Wh2b = (const float*)d_in[17];
    const int*   eidx = (const int*)d_in[18];
    float* out = (float*)d_out;

    const int smA = 128 * (HSTR + KSTR + TSTR) * 2;
    const int smB = 128 * (HSTR + WSTR + ESTR) * 2 +
                    (128 * 4 + 128 + 256 + 384) * 4 + 256 * 4 + 128;
    const int smC = 128 * (HSTR + KSTR) * 2;
    cudaFuncSetAttribute(kA, cudaFuncAttributeMaxDynamicSharedMemorySize, smA);
    cudaFuncSetAttribute(kB, cudaFuncAttributeMaxDynamicSharedMemorySize, smB);
    cudaFuncSetAttribute(kC, cudaFuncAttributeMaxDynamicSharedMemorySize, smC);

    kZero<<<2048, 256>>>();
    kW<<<365, 256>>>(We1w, We2w, Wx1w, Wh1w, Wh2w);
    kA<<<(NN + 127) / 128, 256, smA>>>(h, temb, We1b);
    kB<<<EE / 128, 256, smB>>>(x, ea, eidx, We2b,
                               Wattw, Wattb, Wx1b, Wx2w, Wx2b);
    kC<<<(NN + 127) / 128, 256, smC>>>(h, Wh1b, Wh2b, out);
    kX<<<(NN + 255) / 256, 256>>>(x, out);
}

// round 13
// speedup vs baseline: 1.6960x; 1.1337x over previous
#include <cuda_runtime.h>
#include <cuda_fp16.h>
#include <math.h>
#include <stdint.h>

#define NN 50000
#define EE 800000
#define HSTR 136   // fp16 A-tile stride (halves)
#define KSTR 136   // fp16 B-tile stride (halves) -- kA/kC
#define WSTR 264   // fused We2|Wx1 B-tile stride (halves), K=256
#define ESTR 16    // edge-feature tile stride (halves), 32B rows
#define TSTR 72    // t_emb tile stride (halves)

// sigma layout: logical hidden col c -> physical p
__device__ __host__ __forceinline__ int iperm_c(int p) {
    int r = p & 63;
    return (p & 64) + 8 * ((r >> 1) & 7) + 2 * (r >> 4) + (r & 1);
}

// ---- static device scratch ----
__device__ __half g_Psrch[NN * 128];   // sigma-ordered columns
__device__ __half g_Pdsth[NN * 128];
__device__ float4 g_msg4 [NN * 32];    // sigma-ordered columns
__device__ float  g_coord[NN * 3];
__device__ float  g_deg  [NN];
// pre-transposed fp16 weights [n][k]
__device__ __half g_We2h[128 * 128];   // k sigma-permuted
__device__ __half g_Wx1h[128 * 128];   // k sigma-permuted
__device__ __half g_Wh1h[128 * 256];   // k in [128,256) sigma-permuted
__device__ __half g_Wh2h[128 * 128];   // k sigma-permuted
__device__ __half g_W1ah[128 * 128];
__device__ __half g_W1bh[128 * 128];
__device__ __half g_W1th[128 * 64];
// per-lane precomputed B-fragments of the edge mini-GEMM: [n0half][lane][16]
__device__ uint32_t g_WeEfrag[2 * 32 * 16];

// ---- fast transcendentals ----
__device__ __forceinline__ float tanh_ap(float x) {
    float r;
    asm("tanh.approx.f32 %0, %1;" : "=f"(r) : "f"(x));
    return r;
}
__device__ __forceinline__ float silu_f(float v) {
    float hv = 0.5f * v;
    return fmaf(hv, tanh_ap(hv), hv);
}
__device__ __forceinline__ float sigmoid_f(float s) {
    return fmaf(0.5f, tanh_ap(0.5f * s), 0.5f);
}

__device__ __forceinline__ void red_add_v4(float* p, float a, float b, float c, float d) {
    asm volatile("red.global.add.v4.f32 [%0], {%1,%2,%3,%4};"
                 :: "l"(p), "f"(a), "f"(b), "f"(c), "f"(d) : "memory");
}
__device__ __forceinline__ void red_add_f(float* p, float a) {
    asm volatile("red.global.add.f32 [%0], %1;" :: "l"(p), "f"(a) : "memory");
}
__device__ __forceinline__ uint32_t packh2(float a, float b) {
    __half2 h = __floats2half2_rn(a, b);
    return *(uint32_t*)&h;
}
__device__ __forceinline__ void mma_f16(float c[4], const uint32_t a[4], const uint32_t b[2]) {
    asm volatile("mma.sync.aligned.m16n8k16.row.col.f32.f16.f16.f32 "
                 "{%0,%1,%2,%3}, {%4,%5,%6,%7}, {%8,%9}, {%0,%1,%2,%3};"
                 : "+f"(c[0]), "+f"(c[1]), "+f"(c[2]), "+f"(c[3])
                 : "r"(a[0]), "r"(a[1]), "r"(a[2]), "r"(a[3]),
                   "r"(b[0]), "r"(b[1]));
}
__device__ __forceinline__ void ldsm4(uint32_t r[4], uint32_t addr) {
    asm volatile("ldmatrix.sync.aligned.m8n8.x4.shared.b16 {%0,%1,%2,%3}, [%4];"
                 : "=r"(r[0]), "=r"(r[1]), "=r"(r[2]), "=r"(r[3]) : "r"(addr));
}
__device__ __forceinline__ uint32_t s2u(const void* p) {
    return (uint32_t)__cvta_generic_to_shared(p);
}
#define BARH(h) asm volatile("bar.sync %0, 128;" :: "r"(1 + (h)) : "memory")

// stage pre-transposed fp16 weight [128][srcK] slice -> smem [n][KSTR]
__device__ __forceinline__ void stage_wt(const __half* __restrict__ src, int srcK,
                                         int kOff, uint16_t* __restrict__ WsB, int tid) {
    int n = tid >> 1, kh = (tid & 1) * 64;
    const uint16_t* s = (const uint16_t*)src + (size_t)n * srcK + kOff + kh;
    uint16_t* d = WsB + n * KSTR + kh;
#pragma unroll
    for (int q = 0; q < 8; q++)
        *(uint4*)(d + 8 * q) = *(const uint4*)(s + 8 * q);
}
__device__ __forceinline__ void stage_wt64(const __half* __restrict__ src,
                                           uint16_t* __restrict__ WsB, int tid) {
    int n = tid >> 1, kh = (tid & 1) * 32;
    const uint16_t* s = (const uint16_t*)src + (size_t)n * 64 + kh;
    uint16_t* d = WsB + n * KSTR + kh;
#pragma unroll
    for (int q = 0; q < 4; q++)
        *(uint4*)(d + 8 * q) = *(const uint4*)(s + 8 * q);
}

// warp fp16 GEMM via ldmatrix; B cols at kOff..kOff+K
template<int AS, int BS>
__device__ __forceinline__ void mma_gemm16(const uint16_t* __restrict__ Hs,
                                           const uint16_t* __restrict__ Ws,
                                           int K, int kOff, int m0, int n0, int lane,
                                           float acc[2][8][4]) {
    int lrow = lane & 7, lmi = lane >> 3;
    uint32_t abase = s2u(Hs) +
        (uint32_t)(((m0 + (lmi & 1) * 8 + lrow) * AS + (lmi >> 1) * 8) * 2);
    uint32_t bbase = s2u(Ws) +
        (uint32_t)(((n0 + (lmi >> 1) * 8 + lrow) * BS + (lmi & 1) * 8 + kOff) * 2);
#pragma unroll
    for (int k0 = 0; k0 < K; k0 += 16) {
        uint32_t b[4][4];
#pragma unroll
        for (int jp = 0; jp < 4; jp++)
            ldsm4(b[jp], bbase + (uint32_t)((16 * jp * BS + k0) * 2));
        uint32_t a[2][4];
#pragma unroll
        for (int mt = 0; mt < 2; mt++)
            ldsm4(a[mt], abase + (uint32_t)((16 * mt * AS + k0) * 2));
#pragma unroll
        for (int mt = 0; mt < 2; mt++)
#pragma unroll
            for (int j = 0; j < 8; j++)
                mma_f16(acc[mt][j], a[mt], &b[j >> 1][(j & 1) * 2]);
    }
}

// ---- zero accumulators ----
__global__ void kZero() {
    float* msg = (float*)g_msg4;
    long total = (long)NN * 128 + NN * 3 + NN;
    for (long i = blockIdx.x * (long)blockDim.x + threadIdx.x; i < total;
         i += (long)gridDim.x * blockDim.x) {
        if (i < (long)NN * 128)             msg[i] = 0.f;
        else if (i < (long)NN * 128 + NN*3) g_coord[i - (long)NN * 128] = 0.f;
        else                                g_deg[i - (long)NN * 128 - NN * 3] = 0.f;
    }
}

// ---- weight transpose + fp16 convert ----
__global__ void kW(const float* __restrict__ We1, const float* __restrict__ We2,
                   const float* __restrict__ Wx1,
                   const float* __restrict__ Wh1, const float* __restrict__ Wh2) {
    int i = blockIdx.x * blockDim.x + threadIdx.x;
    if (i < 16384) {
        int n = i >> 7, p = i & 127;
        int k = iperm_c(p);
        g_We2h[i] = __float2half_rn(We2[k * 128 + n]);
        g_Wx1h[i] = __float2half_rn(Wx1[k * 128 + n]);
        g_Wh2h[i] = __float2half_rn(Wh2[k * 128 + n]);
    } else if (i < 49152) {
        int j = i - 16384;
        int n = j >> 8, k = j & 255;
        int kk = (k < 128) ? k : (128 + iperm_c(k - 128));
        g_Wh1h[j] = __float2half_rn(Wh1[kk * 128 + n]);
    } else if (i < 65536) {
        int j = i - 49152;
        int n = j >> 7, k = j & 127;
        g_W1ah[j] = __float2half_rn(We1[k * 128 + n]);
    } else if (i < 81920) {
        int j = i - 65536;
        int n = j >> 7, k = j & 127;
        g_W1bh[j] = __float2half_rn(We1[(128 + k) * 128 + n]);
    } else if (i < 90112) {
        int j = i - 81920;
        int n = j >> 6, k = j & 63;
        g_W1th[j] = __float2half_rn(We1[(265 + k) * 128 + n]);
    } else if (i < 91136) {
        // mini-GEMM B-fragments: [nv][lane][jp*4+mi]
        int j = i - 90112;
        int nv = j >> 9, rem = j & 511;
        int lane = rem >> 4, q = rem & 15;
        int jp = q >> 2, mi = q & 3;
        int n = nv * 64 + 16 * jp + 8 * (mi >> 1) + (lane >> 2);
        int k = 8 * (mi & 1) + 2 * (lane & 3);
        float v0 = 0.f, v1 = 0.f;
        if (k == 0)      v0 = We1[256 * 128 + n];
        else if (k <= 8) v0 = We1[(256 + k) * 128 + n];
        if (k + 1 <= 8 && k + 1 >= 1) v1 = We1[(256 + k + 1) * 128 + n];
        g_WeEfrag[j] = packh2(v0, v1);
    }
}

// =====================================================================
// Kernel A: per-node precompute (fp16 mma), sigma-ordered P
// =====================================================================
__global__ __launch_bounds__(256, 2) void kA(const float* __restrict__ h,
                                             const float* __restrict__ temb,
                                             const float* __restrict__ be1) {
    extern __shared__ float sm[];
    uint16_t* HsB = (uint16_t*)sm;
    uint16_t* WsB = HsB + 128 * HSTR;
    uint16_t* Ts  = WsB + 128 * KSTR;
    int tid = threadIdx.x;
    int lane = tid & 31, w = tid >> 5;
    int g4 = lane >> 2, t4 = lane & 3;
    int m0 = (w & 3) * 32, n0 = (w >> 2) * 64;
    int tile0 = blockIdx.x * 128;

    {
        int n = tid >> 1, kh = (tid & 1) * 64;
        int gn = tile0 + n;
        uint16_t* d = HsB + (size_t)n * HSTR + kh;
#pragma unroll
        for (int q = 0; q < 8; q++) {
            float4 v0 = make_float4(0.f,0.f,0.f,0.f), v1 = v0;
            if (gn < NN) {
                v0 = *(const float4*)(h + (size_t)gn * 128 + kh + q * 8);
                v1 = *(const float4*)(h + (size_t)gn * 128 + kh + q * 8 + 4);
            }
            uint4 u;
            u.x = packh2(v0.x, v0.y); u.y = packh2(v0.z, v0.w);
            u.z = packh2(v1.x, v1.y); u.w = packh2(v1.z, v1.w);
            *(uint4*)(d + 8 * q) = u;
        }
    }
    {
        int n = tid >> 1, kh = (tid & 1) * 32;
        int gn = tile0 + n;
        uint16_t* d = Ts + (size_t)n * TSTR + kh;
#pragma unroll
        for (int q = 0; q < 4; q++) {
            float4 v0 = make_float4(0.f,0.f,0.f,0.f), v1 = v0;
            if (gn < NN) {
                v0 = *(const float4*)(temb + (size_t)gn * 64 + kh + q * 8);
                v1 = *(const float4*)(temb + (size_t)gn * 64 + kh + q * 8 + 4);
            }
            uint4 u;
            u.x = packh2(v0.x, v0.y); u.y = packh2(v0.z, v0.w);
            u.z = packh2(v1.x, v1.y); u.w = packh2(v1.z, v1.w);
            *(uint4*)(d + 8 * q) = u;
        }
    }
    stage_wt(g_W1ah, 128, 0, WsB, tid);
    __syncthreads();

    float acc[2][8][4];
#pragma unroll
    for (int mt = 0; mt < 2; mt++)
#pragma unroll
        for (int j = 0; j < 8; j++)
#pragma unroll
            for (int q = 0; q < 4; q++) acc[mt][j][q] = 0.f;
    mma_gemm16<HSTR,KSTR>(HsB, WsB, 128, 0, m0, n0, lane, acc);
    __syncthreads();
    stage_wt64(g_W1th, WsB, tid);
    __syncthreads();
    mma_gemm16<TSTR,KSTR>(Ts, WsB, 64, 0, m0, n0, lane, acc);

    {
        int off = n0 + 16 * t4;
#pragma unroll
        for (int mt = 0; mt < 2; mt++) {
            int rA = m0 + 16 * mt + g4;
            int gnA = tile0 + rA, gnB = gnA + 8;
            uint32_t wa[8], wb[8];
#pragma unroll
            for (int j = 0; j < 8; j++) {
                int c = n0 + 8 * j + 2 * t4;
                float2 bb = *(const float2*)(be1 + c);
                wa[j] = packh2(acc[mt][j][0] + bb.x, acc[mt][j][1] + bb.y);
                wb[j] = packh2(acc[mt][j][2] + bb.x, acc[mt][j][3] + bb.y);
            }
            if (gnA < NN) {
                uint16_t* p = (uint16_t*)g_Psrch + (size_t)gnA * 128 + off;
                *(uint4*)p       = make_uint4(wa[0], wa[1], wa[2], wa[3]);
                *(uint4*)(p + 8) = make_uint4(wa[4], wa[5], wa[6], wa[7]);
            }
            if (gnB < NN) {
                uint16_t* p = (uint16_t*)g_Psrch + (size_t)gnB * 128 + off;
                *(uint4*)p       = make_uint4(wb[0], wb[1], wb[2], wb[3]);
                *(uint4*)(p + 8) = make_uint4(wb[4], wb[5], wb[6], wb[7]);
            }
        }
    }
    __syncthreads();
    stage_wt(g_W1bh, 128, 0, WsB, tid);
    __syncthreads();
#pragma unroll
    for (int mt = 0; mt < 2; mt++)
#pragma unroll
        for (int j = 0; j < 8; j++)
#pragma unroll
            for (int q = 0; q < 4; q++) acc[mt][j][q] = 0.f;
    mma_gemm16<HSTR,KSTR>(HsB, WsB, 128, 0, m0, n0, lane, acc);
    {
        int off = n0 + 16 * t4;
#pragma unroll
        for (int mt = 0; mt < 2; mt++) {
            int rA = m0 + 16 * mt + g4;
            int gnA = tile0 + rA, gnB = gnA + 8;
            uint32_t wa[8], wb[8];
#pragma unroll
            for (int j = 0; j < 8; j++) {
                wa[j] = packh2(acc[mt][j][0], acc[mt][j][1]);
                wb[j] = packh2(acc[mt][j][2], acc[mt][j][3]);
            }
            if (gnA < NN) {
                uint16_t* p = (uint16_t*)g_Pdsth + (size_t)gnA * 128 + off;
                *(uint4*)p       = make_uint4(wa[0], wa[1], wa[2], wa[3]);
                *(uint4*)(p + 8) = make_uint4(wa[4], wa[5], wa[6], wa[7]);
            }
            if (gnB < NN) {
                uint16_t* p = (uint16_t*)g_Pdsth + (size_t)gnB * 128 + off;
                *(uint4*)p       = make_uint4(wb[0], wb[1], wb[2], wb[3]);
                *(uint4*)(p + 8) = make_uint4(wb[4], wb[5], wb[6], wb[7]);
            }
        }
    }
}

// =====================================================================
// Kernel B: fused edge pipeline, 256 edges per block in two 128-edge
//           passes (weights staged once); two 64-edge halves per pass
// =====================================================================
__global__ __launch_bounds__(256, 2) void kB(const float* __restrict__ x,
                                             const float* __restrict__ ea,
                                             const int* __restrict__ eidx,
                                             const float* __restrict__ be2,
                                             const float* __restrict__ Watt,
                                             const float* __restrict__ batt,
                                             const float* __restrict__ bx1,
                                             const float* __restrict__ Wx2,
                                             const float* __restrict__ bx2) {
    extern __shared__ float sm[];
    uint16_t* HsB = (uint16_t*)sm;                 // 128*HSTR
    uint16_t* WsB = HsB + 128 * HSTR;              // 128*WSTR (We2 | Wx1)
    uint16_t* Es  = WsB + 128 * WSTR;              // 128*ESTR
    float* watt_s = (float*)(Es + 128 * ESTR);     // 128
    float* be2_s  = watt_s + 128;                  // 128
    float* bx1_s  = be2_s + 128;                   // 128
    float* wx2_s  = bx1_s + 128;                   // 128
    float* att_s  = wx2_s + 128;                   // 128 (64 per half)
    float* red_s  = att_s + 128;                   // 256 (128 per half)
    float* diff_s = red_s + 256;                   // 384
    int* src_s = (int*)(diff_s + 384);             // 128
    int* dst_s = src_s + 128;                      // 128

    int tid = threadIdx.x;
    int lane = tid & 31, w = tid >> 5;
    int g4 = lane >> 2, t4 = lane & 3;
    int hf = w >> 2, ww = w & 3;
    int m0 = 64 * hf + (ww & 1) * 32;
    int n0 = ((ww >> 1) & 1) * 64;
    int eg   = 64 * hf + ((ww & 3) << 4) + (lane >> 4);
    int chnk = lane & 15;
    int t7 = tid & 127;

    if (tid < 128) {   // pass-invariant scalars
        watt_s[tid] = Watt[tid];
        be2_s[tid]  = be2[tid];
        bx1_s[tid]  = bx1[tid];
        wx2_s[tid]  = Wx2[tid];
    }
    {   // stage BOTH weights into fused buffer: We2 -> k[0,128), Wx1 -> k[128,256)
        int n = tid >> 1, kh = (tid & 1) * 64;
        const uint16_t* s2 = (const uint16_t*)g_We2h + (size_t)n * 128 + kh;
        const uint16_t* s1 = (const uint16_t*)g_Wx1h + (size_t)n * 128 + kh;
        uint16_t* d2 = WsB + n * WSTR + kh;
        uint16_t* d1 = WsB + n * WSTR + 128 + kh;
#pragma unroll
        for (int q = 0; q < 8; q++) {
            *(uint4*)(d2 + 8 * q) = *(const uint4*)(s2 + 8 * q);
            *(uint4*)(d1 + 8 * q) = *(const uint4*)(s1 + 8 * q);
        }
    }
    // mini-GEMM B-fragments from global
    uint32_t bfr[16];
    {
        const uint4* fbp = (const uint4*)g_WeEfrag + ((n0 >> 6) * 32 + lane) * 4;
        uint4 f0 = fbp[0], f1 = fbp[1], f2 = fbp[2], f3 = fbp[3];
        bfr[0]=f0.x; bfr[1]=f0.y; bfr[2]=f0.z; bfr[3]=f0.w;
        bfr[4]=f1.x; bfr[5]=f1.y; bfr[6]=f1.z; bfr[7]=f1.w;
        bfr[8]=f2.x; bfr[9]=f2.y; bfr[10]=f2.z; bfr[11]=f2.w;
        bfr[12]=f3.x; bfr[13]=f3.y; bfr[14]=f3.z; bfr[15]=f3.w;
    }

    for (int pass = 0; pass < 2; pass++) {
        int e0p = blockIdx.x * 256 + pass * 128;

        // per-pass edge init (own half only: threads t7<64)
        if (t7 < 64) {
            int el = 64 * hf + t7;
            int e = e0p + el;
            int s = eidx[e], d = eidx[EE + e];
            src_s[el] = s; dst_s[el] = d;
            float dx = x[s * 3 + 0] - x[d * 3 + 0];
            float dy = x[s * 3 + 1] - x[d * 3 + 1];
            float dz = x[s * 3 + 2] - x[d * 3 + 2];
            diff_s[el * 3 + 0] = dx; diff_s[el * 3 + 1] = dy; diff_s[el * 3 + 2] = dz;
            float dsq = dx * dx + dy * dy + dz * dz;
            float4 a0 = *(const float4*)(ea + (size_t)e * 8);
            float4 a1 = *(const float4*)(ea + (size_t)e * 8 + 4);
            uint4 u0, u1;
            u0.x = packh2(dsq,  a0.x); u0.y = packh2(a0.y, a0.z);
            u0.z = packh2(a0.w, a1.x); u0.w = packh2(a1.y, a1.z);
            u1.x = packh2(a1.w, 0.f);  u1.y = 0u; u1.z = 0u; u1.w = 0u;
            *(uint4*)(Es + el * ESTR) = u0;
            *(uint4*)(Es + el * ESTR + 8) = u1;
        }
        if (pass == 0) __syncthreads();
        else BARH(hf);

        {   // gather Ps_sum for own half, line-grouped (16 lanes/edge)
#pragma unroll
            for (int it = 0; it < 8; it++) {
                int e = eg + it * 2;
                int s = src_s[e], d = dst_s[e];
                uint4 a = *(const uint4*)((const uint16_t*)g_Psrch + (size_t)s * 128 + chnk * 8);
                uint4 b = *(const uint4*)((const uint16_t*)g_Pdsth + (size_t)d * 128 + chnk * 8);
                uint4 r;
                *(__half2*)&r.x = __hadd2(*(__half2*)&a.x, *(__half2*)&b.x);
                *(__half2*)&r.y = __hadd2(*(__half2*)&a.y, *(__half2*)&b.y);
                *(__half2*)&r.z = __hadd2(*(__half2*)&a.z, *(__half2*)&b.z);
                *(__half2*)&r.w = __hadd2(*(__half2*)&a.w, *(__half2*)&b.w);
                *(uint4*)(HsB + (size_t)e * HSTR + chnk * 8) = r;
            }
        }
        BARH(hf);

        float acc[2][8][4];
#pragma unroll
        for (int mt = 0; mt < 2; mt++)
#pragma unroll
            for (int j = 0; j < 8; j++)
#pragma unroll
                for (int q = 0; q < 4; q++) acc[mt][j][q] = 0.f;
        {   // mini-GEMM: edge-feature contribution (K=16)
            int lrow = lane & 7, lmi = lane >> 3;
            uint32_t abase = s2u(Es) +
                (uint32_t)(((m0 + (lmi & 1) * 8 + lrow) * ESTR + (lmi >> 1) * 8) * 2);
            uint32_t aE[2][4];
#pragma unroll
            for (int mt = 0; mt < 2; mt++)
                ldsm4(aE[mt], abase + (uint32_t)(16 * mt * ESTR * 2));
#pragma unroll
            for (int mt = 0; mt < 2; mt++)
#pragma unroll
                for (int j = 0; j < 8; j++)
                    mma_f16(acc[mt][j], aE[mt], &bfr[(j >> 1) * 4 + (j & 1) * 2]);
        }

        // epilogue0: hidden = silu(acc + Ps_sum)
        {
            int off = n0 + 16 * t4;
#pragma unroll
            for (int mt = 0; mt < 2; mt++) {
                int rA = m0 + 16 * mt + g4, rB = rA + 8;
                uint16_t* pa = HsB + (size_t)rA * HSTR + off;
                uint16_t* pb = HsB + (size_t)rB * HSTR + off;
                uint4 a0 = *(uint4*)pa, a1 = *(uint4*)(pa + 8);
                uint4 b0 = *(uint4*)pb, b1 = *(uint4*)(pb + 8);
                uint32_t aw[8] = {a0.x,a0.y,a0.z,a0.w,a1.x,a1.y,a1.z,a1.w};
                uint32_t bw[8] = {b0.x,b0.y,b0.z,b0.w,b1.x,b1.y,b1.z,b1.w};
                uint32_t oa[8], ob[8];
#pragma unroll
                for (int j = 0; j < 8; j++) {
                    float2 fa = __half22float2(*(__half2*)&aw[j]);
                    float2 fb = __half22float2(*(__half2*)&bw[j]);
                    oa[j] = packh2(silu_f(acc[mt][j][0] + fa.x), silu_f(acc[mt][j][1] + fa.y));
                    ob[j] = packh2(silu_f(acc[mt][j][2] + fb.x), silu_f(acc[mt][j][3] + fb.y));
                }
                *(uint4*)pa       = make_uint4(oa[0], oa[1], oa[2], oa[3]);
                *(uint4*)(pa + 8) = make_uint4(oa[4], oa[5], oa[6], oa[7]);
                *(uint4*)pb       = make_uint4(ob[0], ob[1], ob[2], ob[3]);
                *(uint4*)(pb + 8) = make_uint4(ob[4], ob[5], ob[6], ob[7]);
            }
        }
        BARH(hf);

        // GEMM1: m = hidden @ We2 (fused buffer, kOff=0)
#pragma unroll
        for (int mt = 0; mt < 2; mt++)
#pragma unroll
            for (int j = 0; j < 8; j++)
#pragma unroll
                for (int q = 0; q < 4; q++) acc[mt][j][q] = 0.f;
        mma_gemm16<HSTR,WSTR>(HsB, WsB, 128, 0, m0, n0, lane, acc);

        float pA[2], pB[2];
#pragma unroll
        for (int mt = 0; mt < 2; mt++) {
            pA[mt] = 0.f; pB[mt] = 0.f;
#pragma unroll
            for (int j = 0; j < 8; j++) {
                int c = n0 + 8 * j + 2 * t4;
                float b0 = be2_s[c], b1 = be2_s[c + 1];
                float w0 = watt_s[c], w1 = watt_s[c + 1];
                acc[mt][j][0] += b0; acc[mt][j][1] += b1;
                acc[mt][j][2] += b0; acc[mt][j][3] += b1;
                pA[mt] = fmaf(acc[mt][j][0], w0, fmaf(acc[mt][j][1], w1, pA[mt]));
                pB[mt] = fmaf(acc[mt][j][2], w0, fmaf(acc[mt][j][3], w1, pB[mt]));
            }
            pA[mt] += __shfl_xor_sync(0xffffffffu, pA[mt], 1);
            pA[mt] += __shfl_xor_sync(0xffffffffu, pA[mt], 2);
            pB[mt] += __shfl_xor_sync(0xffffffffu, pB[mt], 1);
            pB[mt] += __shfl_xor_sync(0xffffffffu, pB[mt], 2);
            if (t4 == 0) {
                int rl = (ww & 1) * 32 + 16 * mt + g4;
                red_s[hf * 128 + rl * 2 + ((ww >> 1) & 1)] = pA[mt];
                red_s[hf * 128 + (rl + 8) * 2 + ((ww >> 1) & 1)] = pB[mt];
            }
        }
        BARH(hf);
        if (t7 < 64) {
            float s = red_s[hf * 128 + t7 * 2] + red_s[hf * 128 + t7 * 2 + 1] + batt[0];
            att_s[hf * 64 + t7] = sigmoid_f(s);
        }
        BARH(hf);

        // gate + store m (sigma layout)
        {
            int off = n0 + 16 * t4;
#pragma unroll
            for (int mt = 0; mt < 2; mt++) {
                int rA = m0 + 16 * mt + g4, rB = rA + 8;
                int rl = rA - 64 * hf;
                float aA = att_s[hf * 64 + rl], aB = att_s[hf * 64 + rl + 8];
                uint32_t oa[8], ob[8];
#pragma unroll
                for (int j = 0; j < 8; j++) {
                    oa[j] = packh2(acc[mt][j][0] * aA, acc[mt][j][1] * aA);
                    ob[j] = packh2(acc[mt][j][2] * aB, acc[mt][j][3] * aB);
                }
                uint16_t* pa = HsB + (size_t)rA * HSTR + off;
                uint16_t* pb = HsB + (size_t)rB * HSTR + off;
                *(uint4*)pa       = make_uint4(oa[0], oa[1], oa[2], oa[3]);
                *(uint4*)(pa + 8) = make_uint4(oa[4], oa[5], oa[6], oa[7]);
                *(uint4*)pb       = make_uint4(ob[0], ob[1], ob[2], ob[3]);
                *(uint4*)(pb + 8) = make_uint4(ob[4], ob[5], ob[6], ob[7]);
            }
        }
        BARH(hf);

        {   // scatter msg_agg, contiguous: 32 lanes per edge, 16 edges per warp
            int ew0 = 64 * hf + ww * 16;
#pragma unroll
            for (int it = 0; it < 16; it++) {
                int e = ew0 + it;
                int d = dst_s[e];
                uint2 raw = *(const uint2*)(HsB + (size_t)e * HSTR + lane * 4);
                float2 f0 = __half22float2(*(__half2*)&raw.x);
                float2 f1 = __half22float2(*(__half2*)&raw.y);
                float* p = (float*)g_msg4 + (size_t)d * 128 + lane * 4;
                red_add_v4(p, f0.x, f0.y, f1.x, f1.y);
            }
        }

        // GEMM2: g = silu(m @ Wx1 + bx1); coordw partial = g @ Wx2 (kOff=128)
#pragma unroll
        for (int mt = 0; mt < 2; mt++)
#pragma unroll
            for (int j = 0; j < 8; j++)
#pragma unroll
                for (int q = 0; q < 4; q++) acc[mt][j][q] = 0.f;
        mma_gemm16<HSTR,WSTR>(HsB, WsB, 128, 128, m0, n0, lane, acc);

#pragma unroll
        for (int mt = 0; mt < 2; mt++) {
            pA[mt] = 0.f; pB[mt] = 0.f;
#pragma unroll
            for (int j = 0; j < 8; j++) {
                int c = n0 + 8 * j + 2 * t4;
                float b0 = bx1_s[c], b1 = bx1_s[c + 1];
                float w0 = wx2_s[c], w1 = wx2_s[c + 1];
                float g0 = silu_f(acc[mt][j][0] + b0);
                float g1 = silu_f(acc[mt][j][1] + b1);
                float g2 = silu_f(acc[mt][j][2] + b0);
                float g3 = silu_f(acc[mt][j][3] + b1);
                pA[mt] = fmaf(g0, w0, fmaf(g1, w1, pA[mt]));
                pB[mt] = fmaf(g2, w0, fmaf(g3, w1, pB[mt]));
            }
            pA[mt] += __shfl_xor_sync(0xffffffffu, pA[mt], 1);
            pA[mt] += __shfl_xor_sync(0xffffffffu, pA[mt], 2);
            pB[mt] += __shfl_xor_sync(0xffffffffu, pB[mt], 1);
            pB[mt] += __shfl_xor_sync(0xffffffffu, pB[mt], 2);
            if (t4 == 0) {
                int rl = (ww & 1) * 32 + 16 * mt + g4;
                red_s[hf * 128 + rl * 2 + ((ww >> 1) & 1)] = pA[mt];
                red_s[hf * 128 + (rl + 8) * 2 + ((ww >> 1) & 1)] = pB[mt];
            }
        }
        BARH(hf);
        if (t7 < 64) {
            float s = red_s[hf * 128 + t7 * 2] + red_s[hf * 128 + t7 * 2 + 1] + bx2[0];
            float cw = tanh_ap(s);
            int e = 64 * hf + t7;
            int d = dst_s[e];
            red_add_f(g_coord + (size_t)d * 3 + 0, diff_s[e * 3 + 0] * cw);
            red_add_f(g_coord + (size_t)d * 3 + 1, diff_s[e * 3 + 1] * cw);
            red_add_f(g_coord + (size_t)d * 3 + 2, diff_s[e * 3 + 2] * cw);
            red_add_f(g_deg + d, 1.0f);
        }
    }
}

// =====================================================================
// Kernel C: node update (fp16 mma, sigma layout internally)
// =====================================================================
__global__ __launch_bounds__(256, 2) void kC(const float* __restrict__ h,
                                             const float* __restrict__ bh1,
                                             const float* __restrict__ bh2,
                                             float* __restrict__ out) {
    extern __shared__ float sm[];
    uint16_t* HsB = (uint16_t*)sm;
    uint16_t* WsB = HsB + 128 * HSTR;
    int tid = threadIdx.x;
    int lane = tid & 31, w = tid >> 5;
    int g4 = lane >> 2, t4 = lane & 3;
    int m0 = (w & 3) * 32, n0 = (w >> 2) * 64;
    int tile0 = blockIdx.x * 128;

    float acc[2][8][4];
#pragma unroll
    for (int mt = 0; mt < 2; mt++)
#pragma unroll
        for (int j = 0; j < 8; j++)
#pragma unroll
            for (int q = 0; q < 4; q++) acc[mt][j][q] = 0.f;

    for (int pass = 0; pass < 2; pass++) {
        const float* src = pass ? (const float*)g_msg4 : h;
        if (pass) __syncthreads();
        {
            int n = tid >> 1, kh = (tid & 1) * 64;
            int gn = tile0 + n;
            uint16_t* d = HsB + (size_t)n * HSTR + kh;
#pragma unroll
            for (int q = 0; q < 8; q++) {
                float4 v0 = make_float4(0.f, 0.f, 0.f, 0.f);
                float4 v1 = make_float4(0.f, 0.f, 0.f, 0.f);
                if (gn < NN) {
                    v0 = *(const float4*)(src + (size_t)gn * 128 + kh + q * 8);
                    v1 = *(const float4*)(src + (size_t)gn * 128 + kh + q * 8 + 4);
                }
                uint4 u;
                u.x = packh2(v0.x, v0.y); u.y = packh2(v0.z, v0.w);
                u.z = packh2(v1.x, v1.y); u.w = packh2(v1.z, v1.w);
                *(uint4*)(d + 8 * q) = u;
            }
        }
        stage_wt(g_Wh1h, 256, pass * 128, WsB, tid);
        __syncthreads();
        mma_gemm16<HSTR,KSTR>(HsB, WsB, 128, 0, m0, n0, lane, acc);
    }

    __syncthreads();
    {
        int off = n0 + 16 * t4;
#pragma unroll
        for (int mt = 0; mt < 2; mt++) {
            int rA = m0 + 16 * mt + g4, rB = rA + 8;
            uint32_t oa[8], ob[8];
#pragma unroll
            for (int j = 0; j < 8; j++) {
                int c = n0 + 8 * j + 2 * t4;
                float2 bb = *(const float2*)(bh1 + c);
                oa[j] = packh2(silu_f(acc[mt][j][0] + bb.x), silu_f(acc[mt][j][1] + bb.y));
                ob[j] = packh2(silu_f(acc[mt][j][2] + bb.x), silu_f(acc[mt][j][3] + bb.y));
            }
            uint16_t* pa = HsB + (size_t)rA * HSTR + off;
            uint16_t* pb = HsB + (size_t)rB * HSTR + off;
            *(uint4*)pa       = make_uint4(oa[0], oa[1], oa[2], oa[3]);
            *(uint4*)(pa + 8) = make_uint4(oa[4], oa[5], oa[6], oa[7]);
            *(uint4*)pb       = make_uint4(ob[0], ob[1], ob[2], ob[3]);
            *(uint4*)(pb + 8) = make_uint4(ob[4], ob[5], ob[6], ob[7]);
        }
    }
    stage_wt(g_Wh2h, 128, 0, WsB, tid);
    __syncthreads();

#pragma unroll
    for (int mt = 0; mt < 2; mt++)
#pragma unroll
        for (int j = 0; j < 8; j++)
#pragma unroll
            for (int q = 0; q < 4; q++) acc[mt][j][q] = 0.f;
    mma_gemm16<HSTR,KSTR>(HsB, WsB, 128, 0, m0, n0, lane, acc);

#pragma unroll
    for (int mt = 0; mt < 2; mt++) {
        int rA = m0 + 16 * mt + g4;
        int gnA = tile0 + rA, gnB = gnA + 8;
#pragma unroll
        for (int j = 0; j < 8; j++) {
            int c = n0 + 8 * j + 2 * t4;
            float2 bb = *(const float2*)(bh2 + c);
            if (gnA < NN) {
                float2 hv = *(const float2*)(h + (size_t)gnA * 128 + c);
                *(float2*)(out + (size_t)gnA * 128 + c) =
                    make_float2(hv.x + acc[mt][j][0] + bb.x,
                                hv.y + acc[mt][j][1] + bb.y);
            }
            if (gnB < NN) {
                float2 hv = *(const float2*)(h + (size_t)gnB * 128 + c);
                *(float2*)(out + (size_t)gnB * 128 + c) =
                    make_float2(hv.x + acc[mt][j][2] + bb.x,
                                hv.y + acc[mt][j][3] + bb.y);
            }
        }
    }
}

// ---- x_out ----
__global__ void kX(const float* __restrict__ x, float* __restrict__ out) {
    int n = blockIdx.x * blockDim.x + threadIdx.x;
    if (n < NN) {
        float inv = 1.f / (g_deg[n] + 1.f);
        float* o = out + (size_t)NN * 128 + (size_t)n * 3;
        o[0] = x[n * 3 + 0] + g_coord[n * 3 + 0] * inv;
        o[1] = x[n * 3 + 1] + g_coord[n * 3 + 1] * inv;
        o[2] = x[n * 3 + 2] + g_coord[n * 3 + 2] * inv;
    }
}

extern "C" void kernel_launch(void* const* d_in, const int* in_sizes, int n_in,
                              void* d_out, int out_size) {
    const float* h    = (const float*)d_in[0];
    const float* x    = (const float*)d_in[1];
    const float* ea   = (const float*)d_in[2];
    const float* temb = (const float*)d_in[3];
    const float* We1w = (const float*)d_in[4];
    const float* We1b = (const float*)d_in[5];
    const float* We2w = (const float*)d_in[6];
    const float* We2b = (const float*)d_in[7];
    const float* Wattw = (const float*)d_in[8];
    const float* Wattb = (const float*)d_in[9];
    const float* Wx1w = (const float*)d_in[10];
    const float* Wx1b = (const float*)d_in[11];
    const float* Wx2w = (const float*)d_in[12];
    const float* Wx2b = (const float*)d_in[13];
    const float* Wh1w = (const float*)d_in[14];
    const float* Wh1b = (const float*)d_in[15];
    const float* Wh2w = (const float*)d_in[16];
    const float* Wh2b = (const float*)d_in[17];
    const int*   eidx = (const int*)d_in[18];
    float* out = (float*)d_out;

    const int smA = 128 * (HSTR + KSTR + TSTR) * 2;
    const int smB = 128 * (HSTR + WSTR + ESTR) * 2 +
                    (128 * 4 + 128 + 256 + 384) * 4 + 256 * 4 + 128;
    const int smC = 128 * (HSTR + KSTR) * 2;
    cudaFuncSetAttribute(kA, cudaFuncAttributeMaxDynamicSharedMemorySize, smA);
    cudaFuncSetAttribute(kB, cudaFuncAttributeMaxDynamicSharedMemorySize, smB);
    cudaFuncSetAttribute(kC, cudaFuncAttributeMaxDynamicSharedMemorySize, smC);

    kZero<<<2048, 256>>>();
    kW<<<365, 256>>>(We1w, We2w, Wx1w, Wh1w, Wh2w);
    kA<<<(NN + 127) / 128, 256, smA>>>(h, temb, We1b);
    kB<<<EE / 256, 256, smB>>>(x, ea, eidx, We2b,
                               Wattw, Wattb, Wx1b, Wx2w, Wx2b);
    kC<<<(NN + 127) / 128, 256, smC>>>(h, Wh1b, Wh2b, out);
    kX<<<(NN + 255) / 256, 256>>>(x, out);
}

// round 14
// speedup vs baseline: 2.1022x; 1.2395x over previous
#include <cuda_runtime.h>
#include <cuda_fp16.h>
#include <math.h>
#include <stdint.h>

#define NN 50000
#define EE 800000
#define HSTR 136   // fp16 A-tile stride (halves)
#define KSTR 136   // fp16 B-tile stride (halves)
#define ESTR 16    // edge-feature tile stride (halves), 32B rows
#define TSTR 72    // t_emb tile stride (halves)

// sigma layout: logical hidden col c -> physical p (inverse map)
__device__ __host__ __forceinline__ int iperm_c(int p) {
    int r = p & 63;
    return (p & 64) + 8 * ((r >> 1) & 7) + 2 * (r >> 4) + (r & 1);
}

// ---- static device scratch ----
__device__ __half g_Psrch[NN * 128];   // sigma-ordered columns
__device__ __half g_Pdsth[NN * 128];
__device__ float4 g_msg4 [NN * 32];    // sigma-ordered: S = sum att*hidden
__device__ float  g_satt [NN];         // sum att per node
__device__ float  g_coord[NN * 3];
__device__ float  g_deg  [NN];
// pre-transposed fp16 weights [n][k]
__device__ __half g_Wh1h[128 * 256];   // k<128: h part; k in [128,256): folded Wcb (sigma)
__device__ __half g_Wh2h[128 * 128];   // k sigma-permuted
__device__ __half g_W1ah[128 * 128];
__device__ __half g_W1bh[128 * 128];
__device__ __half g_W1th[128 * 64];
__device__ __half g_Wexh[128 * 128];   // folded We2@Wx1, [o][p] sigma k
__device__ uint32_t g_WeEfrag[2 * 32 * 16];
// folded vectors
__device__ float g_bex[128];   // be2@Wx1 (logical o)
__device__ float g_vcb[128];   // be2@Wh1b (logical o)
__device__ float g_vatt[128];  // (We2@Watt) sigma-ordered
__device__ float g_catt;       // be2@Watt + batt

// ---- fast transcendentals ----
__device__ __forceinline__ float tanh_ap(float x) {
    float r;
    asm("tanh.approx.f32 %0, %1;" : "=f"(r) : "f"(x));
    return r;
}
__device__ __forceinline__ float silu_f(float v) {
    float hv = 0.5f * v;
    return fmaf(hv, tanh_ap(hv), hv);
}
__device__ __forceinline__ float sigmoid_f(float s) {
    return fmaf(0.5f, tanh_ap(0.5f * s), 0.5f);
}

__device__ __forceinline__ void red_add_v4(float* p, float a, float b, float c, float d) {
    asm volatile("red.global.add.v4.f32 [%0], {%1,%2,%3,%4};"
                 :: "l"(p), "f"(a), "f"(b), "f"(c), "f"(d) : "memory");
}
__device__ __forceinline__ void red_add_f(float* p, float a) {
    asm volatile("red.global.add.f32 [%0], %1;" :: "l"(p), "f"(a) : "memory");
}
__device__ __forceinline__ uint32_t packh2(float a, float b) {
    __half2 h = __floats2half2_rn(a, b);
    return *(uint32_t*)&h;
}
__device__ __forceinline__ void mma_f16(float c[4], const uint32_t a[4], const uint32_t b[2]) {
    asm volatile("mma.sync.aligned.m16n8k16.row.col.f32.f16.f16.f32 "
                 "{%0,%1,%2,%3}, {%4,%5,%6,%7}, {%8,%9}, {%0,%1,%2,%3};"
                 : "+f"(c[0]), "+f"(c[1]), "+f"(c[2]), "+f"(c[3])
                 : "r"(a[0]), "r"(a[1]), "r"(a[2]), "r"(a[3]),
                   "r"(b[0]), "r"(b[1]));
}
__device__ __forceinline__ void ldsm4(uint32_t r[4], uint32_t addr) {
    asm volatile("ldmatrix.sync.aligned.m8n8.x4.shared.b16 {%0,%1,%2,%3}, [%4];"
                 : "=r"(r[0]), "=r"(r[1]), "=r"(r[2]), "=r"(r[3]) : "r"(addr));
}
__device__ __forceinline__ uint32_t s2u(const void* p) {
    return (uint32_t)__cvta_generic_to_shared(p);
}
#define BARH(h) asm volatile("bar.sync %0, 128;" :: "r"(1 + (h)) : "memory")

// stage pre-transposed fp16 weight [128][srcK] slice -> smem [n][KSTR]
__device__ __forceinline__ void stage_wt(const __half* __restrict__ src, int srcK,
                                         int kOff, uint16_t* __restrict__ WsB, int tid) {
    int n = tid >> 1, kh = (tid & 1) * 64;
    const uint16_t* s = (const uint16_t*)src + (size_t)n * srcK + kOff + kh;
    uint16_t* d = WsB + n * KSTR + kh;
#pragma unroll
    for (int q = 0; q < 8; q++)
        *(uint4*)(d + 8 * q) = *(const uint4*)(s + 8 * q);
}
__device__ __forceinline__ void stage_wt64(const __half* __restrict__ src,
                                           uint16_t* __restrict__ WsB, int tid) {
    int n = tid >> 1, kh = (tid & 1) * 32;
    const uint16_t* s = (const uint16_t*)src + (size_t)n * 64 + kh;
    uint16_t* d = WsB + n * KSTR + kh;
#pragma unroll
    for (int q = 0; q < 4; q++)
        *(uint4*)(d + 8 * q) = *(const uint4*)(s + 8 * q);
}

// warp fp16 GEMM via ldmatrix
template<int AS, int BS>
__device__ __forceinline__ void mma_gemm16(const uint16_t* __restrict__ Hs,
                                           const uint16_t* __restrict__ Ws,
                                           int K, int kOff, int m0, int n0, int lane,
                                           float acc[2][8][4]) {
    int lrow = lane & 7, lmi = lane >> 3;
    uint32_t abase = s2u(Hs) +
        (uint32_t)(((m0 + (lmi & 1) * 8 + lrow) * AS + (lmi >> 1) * 8) * 2);
    uint32_t bbase = s2u(Ws) +
        (uint32_t)(((n0 + (lmi >> 1) * 8 + lrow) * BS + (lmi & 1) * 8 + kOff) * 2);
#pragma unroll
    for (int k0 = 0; k0 < K; k0 += 16) {
        uint32_t b[4][4];
#pragma unroll
        for (int jp = 0; jp < 4; jp++)
            ldsm4(b[jp], bbase + (uint32_t)((16 * jp * BS + k0) * 2));
        uint32_t a[2][4];
#pragma unroll
        for (int mt = 0; mt < 2; mt++)
            ldsm4(a[mt], abase + (uint32_t)((16 * mt * AS + k0) * 2));
#pragma unroll
        for (int mt = 0; mt < 2; mt++)
#pragma unroll
            for (int j = 0; j < 8; j++)
                mma_f16(acc[mt][j], a[mt], &b[j >> 1][(j & 1) * 2]);
    }
}

// ---- zero accumulators ----
__global__ void kZero() {
    float* msg = (float*)g_msg4;
    long base1 = (long)NN * 128;
    long base2 = base1 + NN * 3;
    long base3 = base2 + NN;
    long total = base3 + NN;
    for (long i = blockIdx.x * (long)blockDim.x + threadIdx.x; i < total;
         i += (long)gridDim.x * blockDim.x) {
        if (i < base1)       msg[i] = 0.f;
        else if (i < base2)  g_coord[i - base1] = 0.f;
        else if (i < base3)  g_deg[i - base2] = 0.f;
        else                 g_satt[i - base3] = 0.f;
    }
}

// ---- weight transpose + fp16 convert ----
__global__ void kW(const float* __restrict__ We1,
                   const float* __restrict__ Wh1, const float* __restrict__ Wh2) {
    int i = blockIdx.x * blockDim.x + threadIdx.x;
    if (i < 16384) {           // Wh2h (sigma k)
        int n = i >> 7, p = i & 127;
        int k = iperm_c(p);
        g_Wh2h[i] = __float2half_rn(Wh2[k * 128 + n]);
    } else if (i < 32768) {    // Wh1h, h part k<128
        int j = i - 16384;
        int n = j >> 7, k = j & 127;
        g_Wh1h[n * 256 + k] = __float2half_rn(Wh1[k * 128 + n]);
    } else if (i < 49152) {    // W1ah
        int j = i - 32768;
        int n = j >> 7, k = j & 127;
        g_W1ah[j] = __float2half_rn(We1[k * 128 + n]);
    } else if (i < 65536) {    // W1bh
        int j = i - 49152;
        int n = j >> 7, k = j & 127;
        g_W1bh[j] = __float2half_rn(We1[(128 + k) * 128 + n]);
    } else if (i < 73728) {    // W1th
        int j = i - 65536;
        int n = j >> 6, k = j & 63;
        g_W1th[j] = __float2half_rn(We1[(265 + k) * 128 + n]);
    } else if (i < 74752) {    // mini-GEMM B-fragments
        int j = i - 73728;
        int nv = j >> 9, rem = j & 511;
        int lane = rem >> 4, q = rem & 15;
        int jp = q >> 2, mi = q & 3;
        int n = nv * 64 + 16 * jp + 8 * (mi >> 1) + (lane >> 2);
        int k = 8 * (mi & 1) + 2 * (lane & 3);
        float v0 = 0.f, v1 = 0.f;
        if (k == 0)      v0 = We1[256 * 128 + n];
        else if (k <= 8) v0 = We1[(256 + k) * 128 + n];
        if (k + 1 <= 8 && k + 1 >= 1) v1 = We1[(256 + k + 1) * 128 + n];
        g_WeEfrag[j] = packh2(v0, v1);
    }
}

// ---- folded weights (fp32 folds, once per launch) ----
__global__ void kWx(const float* __restrict__ We2, const float* __restrict__ Wx1,
                    const float* __restrict__ Wh1, const float* __restrict__ Watt,
                    const float* __restrict__ be2, const float* __restrict__ batt) {
    int i = blockIdx.x * blockDim.x + threadIdx.x;
    if (i < 16384) {           // Wex = We2@Wx1, [o][p] sigma
        int o = i >> 7, p = i & 127, ii = iperm_c(p);
        float s = 0.f;
        for (int j = 0; j < 128; j++)
            s += We2[ii * 128 + j] * Wx1[j * 128 + o];
        g_Wexh[o * 128 + p] = __float2half_rn(s);
    } else if (i < 32768) {    // Wcb = We2@Wh1b -> g_Wh1h second half
        int j2 = i - 16384;
        int o = j2 >> 7, p = j2 & 127, ii = iperm_c(p);
        float s = 0.f;
        for (int j = 0; j < 128; j++)
            s += We2[ii * 128 + j] * Wh1[(128 + j) * 128 + o];
        g_Wh1h[o * 256 + 128 + p] = __float2half_rn(s);
    } else if (i < 32896) {    // bex = be2@Wx1
        int o = i - 32768;
        float s = 0.f;
        for (int j = 0; j < 128; j++) s += be2[j] * Wx1[j * 128 + o];
        g_bex[o] = s;
    } else if (i < 33024) {    // vcb = be2@Wh1b
        int o = i - 32896;
        float s = 0.f;
        for (int j = 0; j < 128; j++) s += be2[j] * Wh1[(128 + j) * 128 + o];
        g_vcb[o] = s;
    } else if (i < 33152) {    // vatt = We2@Watt (sigma-ordered)
        int p = i - 33024;
        int ii = iperm_c(p);
        float s = 0.f;
        for (int j = 0; j < 128; j++) s += We2[ii * 128 + j] * Watt[j];
        g_vatt[p] = s;
    } else if (i == 33152) {   // catt
        float s = batt[0];
        for (int j = 0; j < 128; j++) s += be2[j] * Watt[j];
        g_catt = s;
    }
}

// =====================================================================
// Kernel A: per-node precompute (fp16 mma), sigma-ordered P
// =====================================================================
__global__ __launch_bounds__(256, 2) void kA(const float* __restrict__ h,
                                             const float* __restrict__ temb,
                                             const float* __restrict__ be1) {
    extern __shared__ float sm[];
    uint16_t* HsB = (uint16_t*)sm;
    uint16_t* WsB = HsB + 128 * HSTR;
    uint16_t* Ts  = WsB + 128 * KSTR;
    int tid = threadIdx.x;
    int lane = tid & 31, w = tid >> 5;
    int g4 = lane >> 2, t4 = lane & 3;
    int m0 = (w & 3) * 32, n0 = (w >> 2) * 64;
    int tile0 = blockIdx.x * 128;

    {
        int n = tid >> 1, kh = (tid & 1) * 64;
        int gn = tile0 + n;
        uint16_t* d = HsB + (size_t)n * HSTR + kh;
#pragma unroll
        for (int q = 0; q < 8; q++) {
            float4 v0 = make_float4(0.f,0.f,0.f,0.f), v1 = v0;
            if (gn < NN) {
                v0 = *(const float4*)(h + (size_t)gn * 128 + kh + q * 8);
                v1 = *(const float4*)(h + (size_t)gn * 128 + kh + q * 8 + 4);
            }
            uint4 u;
            u.x = packh2(v0.x, v0.y); u.y = packh2(v0.z, v0.w);
            u.z = packh2(v1.x, v1.y); u.w = packh2(v1.z, v1.w);
            *(uint4*)(d + 8 * q) = u;
        }
    }
    {
        int n = tid >> 1, kh = (tid & 1) * 32;
        int gn = tile0 + n;
        uint16_t* d = Ts + (size_t)n * TSTR + kh;
#pragma unroll
        for (int q = 0; q < 4; q++) {
            float4 v0 = make_float4(0.f,0.f,0.f,0.f), v1 = v0;
            if (gn < NN) {
                v0 = *(const float4*)(temb + (size_t)gn * 64 + kh + q * 8);
                v1 = *(const float4*)(temb + (size_t)gn * 64 + kh + q * 8 + 4);
            }
            uint4 u;
            u.x = packh2(v0.x, v0.y); u.y = packh2(v0.z, v0.w);
            u.z = packh2(v1.x, v1.y); u.w = packh2(v1.z, v1.w);
            *(uint4*)(d + 8 * q) = u;
        }
    }
    stage_wt(g_W1ah, 128, 0, WsB, tid);
    __syncthreads();

    float acc[2][8][4];
#pragma unroll
    for (int mt = 0; mt < 2; mt++)
#pragma unroll
        for (int j = 0; j < 8; j++)
#pragma unroll
            for (int q = 0; q < 4; q++) acc[mt][j][q] = 0.f;
    mma_gemm16<HSTR,KSTR>(HsB, WsB, 128, 0, m0, n0, lane, acc);
    __syncthreads();
    stage_wt64(g_W1th, WsB, tid);
    __syncthreads();
    mma_gemm16<TSTR,KSTR>(Ts, WsB, 64, 0, m0, n0, lane, acc);

    {
        int off = n0 + 16 * t4;
#pragma unroll
        for (int mt = 0; mt < 2; mt++) {
            int rA = m0 + 16 * mt + g4;
            int gnA = tile0 + rA, gnB = gnA + 8;
            uint32_t wa[8], wb[8];
#pragma unroll
            for (int j = 0; j < 8; j++) {
                int c = n0 + 8 * j + 2 * t4;
                float2 bb = *(const float2*)(be1 + c);
                wa[j] = packh2(acc[mt][j][0] + bb.x, acc[mt][j][1] + bb.y);
                wb[j] = packh2(acc[mt][j][2] + bb.x, acc[mt][j][3] + bb.y);
            }
            if (gnA < NN) {
                uint16_t* p = (uint16_t*)g_Psrch + (size_t)gnA * 128 + off;
                *(uint4*)p       = make_uint4(wa[0], wa[1], wa[2], wa[3]);
                *(uint4*)(p + 8) = make_uint4(wa[4], wa[5], wa[6], wa[7]);
            }
            if (gnB < NN) {
                uint16_t* p = (uint16_t*)g_Psrch + (size_t)gnB * 128 + off;
                *(uint4*)p       = make_uint4(wb[0], wb[1], wb[2], wb[3]);
                *(uint4*)(p + 8) = make_uint4(wb[4], wb[5], wb[6], wb[7]);
            }
        }
    }
    __syncthreads();
    stage_wt(g_W1bh, 128, 0, WsB, tid);
    __syncthreads();
#pragma unroll
    for (int mt = 0; mt < 2; mt++)
#pragma unroll
        for (int j = 0; j < 8; j++)
#pragma unroll
            for (int q = 0; q < 4; q++) acc[mt][j][q] = 0.f;
    mma_gemm16<HSTR,KSTR>(HsB, WsB, 128, 0, m0, n0, lane, acc);
    {
        int off = n0 + 16 * t4;
#pragma unroll
        for (int mt = 0; mt < 2; mt++) {
            int rA = m0 + 16 * mt + g4;
            int gnA = tile0 + rA, gnB = gnA + 8;
            uint32_t wa[8], wb[8];
#pragma unroll
            for (int j = 0; j < 8; j++) {
                wa[j] = packh2(acc[mt][j][0], acc[mt][j][1]);
                wb[j] = packh2(acc[mt][j][2], acc[mt][j][3]);
            }
            if (gnA < NN) {
                uint16_t* p = (uint16_t*)g_Pdsth + (size_t)gnA * 128 + off;
                *(uint4*)p       = make_uint4(wa[0], wa[1], wa[2], wa[3]);
                *(uint4*)(p + 8) = make_uint4(wa[4], wa[5], wa[6], wa[7]);
            }
            if (gnB < NN) {
                uint16_t* p = (uint16_t*)g_Pdsth + (size_t)gnB * 128 + off;
                *(uint4*)p       = make_uint4(wb[0], wb[1], wb[2], wb[3]);
                *(uint4*)(p + 8) = make_uint4(wb[4], wb[5], wb[6], wb[7]);
            }
        }
    }
}

// =====================================================================
// Kernel B: fused edge pipeline, 256 edges/block (2 passes), ONE GEMM
// =====================================================================
__global__ __launch_bounds__(256, 2) void kB(const float* __restrict__ x,
                                             const float* __restrict__ ea,
                                             const int* __restrict__ eidx,
                                             const float* __restrict__ bx1,
                                             const float* __restrict__ Wx2,
                                             const float* __restrict__ bx2) {
    extern __shared__ float sm[];
    uint16_t* HsB = (uint16_t*)sm;                 // 128*HSTR
    uint16_t* WsB = HsB + 128 * HSTR;              // 128*KSTR (Wexh)
    uint16_t* Es  = WsB + 128 * KSTR;              // 128*ESTR
    float* vatt_s = (float*)(Es + 128 * ESTR);     // 128 (sigma)
    float* bex_s  = vatt_s + 128;                  // 128 (logical)
    float* bx1_s  = bex_s + 128;
    float* wx2_s  = bx1_s + 128;
    float* att_s  = wx2_s + 128;                   // 64 per half
    float* red_s  = att_s + 128;                   // 128 per half
    float* diff_s = red_s + 256;                   // 384
    int* src_s = (int*)(diff_s + 384);
    int* dst_s = src_s + 128;

    int tid = threadIdx.x;
    int lane = tid & 31, w = tid >> 5;
    int g4 = lane >> 2, t4 = lane & 3;
    int hf = w >> 2, ww = w & 3;
    int m0 = 64 * hf + (ww & 1) * 32;
    int n0 = ((ww >> 1) & 1) * 64;
    int eg   = 64 * hf + ((ww & 3) << 4) + (lane >> 4);
    int chnk = lane & 15;
    int t7 = tid & 127;

    if (tid < 128) {
        vatt_s[tid] = g_vatt[tid];
        bex_s[tid]  = g_bex[tid];
        bx1_s[tid]  = bx1[tid];
        wx2_s[tid]  = Wx2[tid];
    }
    stage_wt(g_Wexh, 128, 0, WsB, tid);
    uint32_t bfr[16];
    {
        const uint4* fbp = (const uint4*)g_WeEfrag + ((n0 >> 6) * 32 + lane) * 4;
        uint4 f0 = fbp[0], f1 = fbp[1], f2 = fbp[2], f3 = fbp[3];
        bfr[0]=f0.x; bfr[1]=f0.y; bfr[2]=f0.z; bfr[3]=f0.w;
        bfr[4]=f1.x; bfr[5]=f1.y; bfr[6]=f1.z; bfr[7]=f1.w;
        bfr[8]=f2.x; bfr[9]=f2.y; bfr[10]=f2.z; bfr[11]=f2.w;
        bfr[12]=f3.x; bfr[13]=f3.y; bfr[14]=f3.z; bfr[15]=f3.w;
    }

    for (int pass = 0; pass < 2; pass++) {
        int e0p = blockIdx.x * 256 + pass * 128;

        if (t7 < 64) {   // per-pass edge init (own half)
            int el = 64 * hf + t7;
            int e = e0p + el;
            int s = eidx[e], d = eidx[EE + e];
            src_s[el] = s; dst_s[el] = d;
            float dx = x[s * 3 + 0] - x[d * 3 + 0];
            float dy = x[s * 3 + 1] - x[d * 3 + 1];
            float dz = x[s * 3 + 2] - x[d * 3 + 2];
            diff_s[el * 3 + 0] = dx; diff_s[el * 3 + 1] = dy; diff_s[el * 3 + 2] = dz;
            float dsq = dx * dx + dy * dy + dz * dz;
            float4 a0 = *(const float4*)(ea + (size_t)e * 8);
            float4 a1 = *(const float4*)(ea + (size_t)e * 8 + 4);
            uint4 u0, u1;
            u0.x = packh2(dsq,  a0.x); u0.y = packh2(a0.y, a0.z);
            u0.z = packh2(a0.w, a1.x); u0.w = packh2(a1.y, a1.z);
            u1.x = packh2(a1.w, 0.f);  u1.y = 0u; u1.z = 0u; u1.w = 0u;
            *(uint4*)(Es + el * ESTR) = u0;
            *(uint4*)(Es + el * ESTR + 8) = u1;
        }
        if (pass == 0) __syncthreads();
        else BARH(hf);

        {   // gather Ps_sum, line-grouped
#pragma unroll
            for (int it = 0; it < 8; it++) {
                int e = eg + it * 2;
                int s = src_s[e], d = dst_s[e];
                uint4 a = *(const uint4*)((const uint16_t*)g_Psrch + (size_t)s * 128 + chnk * 8);
                uint4 b = *(const uint4*)((const uint16_t*)g_Pdsth + (size_t)d * 128 + chnk * 8);
                uint4 r;
                *(__half2*)&r.x = __hadd2(*(__half2*)&a.x, *(__half2*)&b.x);
                *(__half2*)&r.y = __hadd2(*(__half2*)&a.y, *(__half2*)&b.y);
                *(__half2*)&r.z = __hadd2(*(__half2*)&a.z, *(__half2*)&b.z);
                *(__half2*)&r.w = __hadd2(*(__half2*)&a.w, *(__half2*)&b.w);
                *(uint4*)(HsB + (size_t)e * HSTR + chnk * 8) = r;
            }
        }
        BARH(hf);

        float acc[2][8][4];
#pragma unroll
        for (int mt = 0; mt < 2; mt++)
#pragma unroll
            for (int j = 0; j < 8; j++)
#pragma unroll
                for (int q = 0; q < 4; q++) acc[mt][j][q] = 0.f;
        {   // mini-GEMM: edge-feature contribution (K=16)
            int lrow = lane & 7, lmi = lane >> 3;
            uint32_t abase = s2u(Es) +
                (uint32_t)(((m0 + (lmi & 1) * 8 + lrow) * ESTR + (lmi >> 1) * 8) * 2);
            uint32_t aE[2][4];
#pragma unroll
            for (int mt = 0; mt < 2; mt++)
                ldsm4(aE[mt], abase + (uint32_t)(16 * mt * ESTR * 2));
#pragma unroll
            for (int mt = 0; mt < 2; mt++)
#pragma unroll
                for (int j = 0; j < 8; j++)
                    mma_f16(acc[mt][j], aE[mt], &bfr[(j >> 1) * 4 + (j & 1) * 2]);
        }

        // epilogue0: hidden = silu(acc + Ps_sum) + att partial dot with vatt
        float pA[2], pB[2];
        {
            int off = n0 + 16 * t4;
#pragma unroll
            for (int mt = 0; mt < 2; mt++) {
                int rA = m0 + 16 * mt + g4, rB = rA + 8;
                uint16_t* pa = HsB + (size_t)rA * HSTR + off;
                uint16_t* pb = HsB + (size_t)rB * HSTR + off;
                uint4 a0 = *(uint4*)pa, a1 = *(uint4*)(pa + 8);
                uint4 b0 = *(uint4*)pb, b1 = *(uint4*)(pb + 8);
                uint32_t aw[8] = {a0.x,a0.y,a0.z,a0.w,a1.x,a1.y,a1.z,a1.w};
                uint32_t bw[8] = {b0.x,b0.y,b0.z,b0.w,b1.x,b1.y,b1.z,b1.w};
                uint32_t oa[8], ob[8];
                pA[mt] = 0.f; pB[mt] = 0.f;
#pragma unroll
                for (int j = 0; j < 8; j++) {
                    float2 fa = __half22float2(*(__half2*)&aw[j]);
                    float2 fb = __half22float2(*(__half2*)&bw[j]);
                    float s0 = silu_f(acc[mt][j][0] + fa.x);
                    float s1 = silu_f(acc[mt][j][1] + fa.y);
                    float s2 = silu_f(acc[mt][j][2] + fb.x);
                    float s3 = silu_f(acc[mt][j][3] + fb.y);
                    oa[j] = packh2(s0, s1);
                    ob[j] = packh2(s2, s3);
                    float v0 = vatt_s[off + 2 * j], v1 = vatt_s[off + 2 * j + 1];
                    pA[mt] = fmaf(s0, v0, fmaf(s1, v1, pA[mt]));
                    pB[mt] = fmaf(s2, v0, fmaf(s3, v1, pB[mt]));
                }
                *(uint4*)pa       = make_uint4(oa[0], oa[1], oa[2], oa[3]);
                *(uint4*)(pa + 8) = make_uint4(oa[4], oa[5], oa[6], oa[7]);
                *(uint4*)pb       = make_uint4(ob[0], ob[1], ob[2], ob[3]);
                *(uint4*)(pb + 8) = make_uint4(ob[4], ob[5], ob[6], ob[7]);
                pA[mt] += __shfl_xor_sync(0xffffffffu, pA[mt], 1);
                pA[mt] += __shfl_xor_sync(0xffffffffu, pA[mt], 2);
                pB[mt] += __shfl_xor_sync(0xffffffffu, pB[mt], 1);
                pB[mt] += __shfl_xor_sync(0xffffffffu, pB[mt], 2);
                if (t4 == 0) {
                    int rl = (ww & 1) * 32 + 16 * mt + g4;
                    red_s[hf * 128 + rl * 2 + ((ww >> 1) & 1)] = pA[mt];
                    red_s[hf * 128 + (rl + 8) * 2 + ((ww >> 1) & 1)] = pB[mt];
                }
            }
        }
        BARH(hf);
        if (t7 < 64) {   // att finalize + satt/deg scatter
            float s = red_s[hf * 128 + t7 * 2] + red_s[hf * 128 + t7 * 2 + 1] + g_catt;
            float a = sigmoid_f(s);
            att_s[hf * 64 + t7] = a;
            int d = dst_s[64 * hf + t7];
            red_add_f(g_satt + d, a);
            red_add_f(g_deg + d, 1.0f);
        }
        BARH(hf);

        {   // scatter S += att * hidden (contiguous, 32 lanes/edge)
            int ew0 = 64 * hf + ww * 16;
#pragma unroll
            for (int it = 0; it < 16; it++) {
                int e = ew0 + it;
                int d = dst_s[e];
                float a = att_s[hf * 64 + ww * 16 + it];
                uint2 raw = *(const uint2*)(HsB + (size_t)e * HSTR + lane * 4);
                float2 f0 = __half22float2(*(__half2*)&raw.x);
                float2 f1 = __half22float2(*(__half2*)&raw.y);
                float* p = (float*)g_msg4 + (size_t)d * 128 + lane * 4;
                red_add_v4(p, a * f0.x, a * f0.y, a * f1.x, a * f1.y);
            }
        }

        // GEMM': G = hidden @ Wex; coordw epilogue
#pragma unroll
        for (int mt = 0; mt < 2; mt++)
#pragma unroll
            for (int j = 0; j < 8; j++)
#pragma unroll
                for (int q = 0; q < 4; q++) acc[mt][j][q] = 0.f;
        mma_gemm16<HSTR,KSTR>(HsB, WsB, 128, 0, m0, n0, lane, acc);

#pragma unroll
        for (int mt = 0; mt < 2; mt++) {
            int rl = (ww & 1) * 32 + 16 * mt + g4;
            float aA = att_s[hf * 64 + rl], aB = att_s[hf * 64 + rl + 8];
            pA[mt] = 0.f; pB[mt] = 0.f;
#pragma unroll
            for (int j = 0; j < 8; j++) {
                int c = n0 + 8 * j + 2 * t4;
                float e0 = bex_s[c], e1 = bex_s[c + 1];
                float b0 = bx1_s[c], b1 = bx1_s[c + 1];
                float w0 = wx2_s[c], w1 = wx2_s[c + 1];
                float g0 = silu_f(fmaf(aA, acc[mt][j][0] + e0, b0));
                float g1 = silu_f(fmaf(aA, acc[mt][j][1] + e1, b1));
                float g2 = silu_f(fmaf(aB, acc[mt][j][2] + e0, b0));
                float g3 = silu_f(fmaf(aB, acc[mt][j][3] + e1, b1));
                pA[mt] = fmaf(g0, w0, fmaf(g1, w1, pA[mt]));
                pB[mt] = fmaf(g2, w0, fmaf(g3, w1, pB[mt]));
            }
            pA[mt] += __shfl_xor_sync(0xffffffffu, pA[mt], 1);
            pA[mt] += __shfl_xor_sync(0xffffffffu, pA[mt], 2);
            pB[mt] += __shfl_xor_sync(0xffffffffu, pB[mt], 1);
            pB[mt] += __shfl_xor_sync(0xffffffffu, pB[mt], 2);
            if (t4 == 0) {
                red_s[hf * 128 + rl * 2 + ((ww >> 1) & 1)] = pA[mt];
                red_s[hf * 128 + (rl + 8) * 2 + ((ww >> 1) & 1)] = pB[mt];
            }
        }
        BARH(hf);
        if (t7 < 64) {   // coord finalize
            float s = red_s[hf * 128 + t7 * 2] + red_s[hf * 128 + t7 * 2 + 1] + bx2[0];
            float cw = tanh_ap(s);
            int e = 64 * hf + t7;
            int d = dst_s[e];
            red_add_f(g_coord + (size_t)d * 3 + 0, diff_s[e * 3 + 0] * cw);
            red_add_f(g_coord + (size_t)d * 3 + 1, diff_s[e * 3 + 1] * cw);
            red_add_f(g_coord + (size_t)d * 3 + 2, diff_s[e * 3 + 2] * cw);
        }
    }
}

// =====================================================================
// Kernel C: node update (fp16 mma) with folded msg weights + satt bias
// =====================================================================
__global__ __launch_bounds__(256, 2) void kC(const float* __restrict__ h,
                                             const float* __restrict__ bh1,
                                             const float* __restrict__ bh2,
                                             float* __restrict__ out) {
    extern __shared__ float sm[];
    uint16_t* HsB = (uint16_t*)sm;
    uint16_t* WsB = HsB + 128 * HSTR;
    float* satt_s = (float*)(WsB + 128 * KSTR);  // 128
    float* vcb_s  = satt_s + 128;                // 128
    int tid = threadIdx.x;
    int lane = tid & 31, w = tid >> 5;
    int g4 = lane >> 2, t4 = lane & 3;
    int m0 = (w & 3) * 32, n0 = (w >> 2) * 64;
    int tile0 = blockIdx.x * 128;

    if (tid < 128) {
        int gn = tile0 + tid;
        satt_s[tid] = (gn < NN) ? g_satt[gn] : 0.f;
        vcb_s[tid]  = g_vcb[tid];
    }

    float acc[2][8][4];
#pragma unroll
    for (int mt = 0; mt < 2; mt++)
#pragma unroll
        for (int j = 0; j < 8; j++)
#pragma unroll
            for (int q = 0; q < 4; q++) acc[mt][j][q] = 0.f;

    for (int pass = 0; pass < 2; pass++) {
        const float* src = pass ? (const float*)g_msg4 : h;
        if (pass) __syncthreads();
        {
            int n = tid >> 1, kh = (tid & 1) * 64;
            int gn = tile0 + n;
            uint16_t* d = HsB + (size_t)n * HSTR + kh;
#pragma unroll
            for (int q = 0; q < 8; q++) {
                float4 v0 = make_float4(0.f, 0.f, 0.f, 0.f);
                float4 v1 = make_float4(0.f, 0.f, 0.f, 0.f);
                if (gn < NN) {
                    v0 = *(const float4*)(src + (size_t)gn * 128 + kh + q * 8);
                    v1 = *(const float4*)(src + (size_t)gn * 128 + kh + q * 8 + 4);
                }
                uint4 u;
                u.x = packh2(v0.x, v0.y); u.y = packh2(v0.z, v0.w);
                u.z = packh2(v1.x, v1.y); u.w = packh2(v1.z, v1.w);
                *(uint4*)(d + 8 * q) = u;
            }
        }
        stage_wt(g_Wh1h, 256, pass * 128, WsB, tid);
        __syncthreads();
        mma_gemm16<HSTR,KSTR>(HsB, WsB, 128, 0, m0, n0, lane, acc);
    }

    __syncthreads();
    {   // g = silu(acc + bh1 + satt*vcb) -> HsB
        int off = n0 + 16 * t4;
#pragma unroll
        for (int mt = 0; mt < 2; mt++) {
            int rA = m0 + 16 * mt + g4, rB = rA + 8;
            float sA = satt_s[rA], sB = satt_s[rB];
            uint32_t oa[8], ob[8];
#pragma unroll
            for (int j = 0; j < 8; j++) {
                int c = n0 + 8 * j + 2 * t4;
                float2 bb = *(const float2*)(bh1 + c);
                float vc0 = vcb_s[c], vc1 = vcb_s[c + 1];
                oa[j] = packh2(silu_f(acc[mt][j][0] + bb.x + sA * vc0),
                               silu_f(acc[mt][j][1] + bb.y + sA * vc1));
                ob[j] = packh2(silu_f(acc[mt][j][2] + bb.x + sB * vc0),
                               silu_f(acc[mt][j][3] + bb.y + sB * vc1));
            }
            uint16_t* pa = HsB + (size_t)rA * HSTR + off;
            uint16_t* pb = HsB + (size_t)rB * HSTR + off;
            *(uint4*)pa       = make_uint4(oa[0], oa[1], oa[2], oa[3]);
            *(uint4*)(pa + 8) = make_uint4(oa[4], oa[5], oa[6], oa[7]);
            *(uint4*)pb       = make_uint4(ob[0], ob[1], ob[2], ob[3]);
            *(uint4*)(pb + 8) = make_uint4(ob[4], ob[5], ob[6], ob[7]);
        }
    }
    stage_wt(g_Wh2h, 128, 0, WsB, tid);
    __syncthreads();

#pragma unroll
    for (int mt = 0; mt < 2; mt++)
#pragma unroll
        for (int j = 0; j < 8; j++)
#pragma unroll
            for (int q = 0; q < 4; q++) acc[mt][j][q] = 0.f;
    mma_gemm16<HSTR,KSTR>(HsB, WsB, 128, 0, m0, n0, lane, acc);

#pragma unroll
    for (int mt = 0; mt < 2; mt++) {
        int rA = m0 + 16 * mt + g4;
        int gnA = tile0 + rA, gnB = gnA + 8;
#pragma unroll
        for (int j = 0; j < 8; j++) {
            int c = n0 + 8 * j + 2 * t4;
            float2 bb = *(const float2*)(bh2 + c);
            if (gnA < NN) {
                float2 hv = *(const float2*)(h + (size_t)gnA * 128 + c);
                *(float2*)(out + (size_t)gnA * 128 + c) =
                    make_float2(hv.x + acc[mt][j][0] + bb.x,
                                hv.y + acc[mt][j][1] + bb.y);
            }
            if (gnB < NN) {
                float2 hv = *(const float2*)(h + (size_t)gnB * 128 + c);
                *(float2*)(out + (size_t)gnB * 128 + c) =
                    make_float2(hv.x + acc[mt][j][2] + bb.x,
                                hv.y + acc[mt][j][3] + bb.y);
            }
        }
    }
}

// ---- x_out ----
__global__ void kX(const float* __restrict__ x, float* __restrict__ out) {
    int n = blockIdx.x * blockDim.x + threadIdx.x;
    if (n < NN) {
        float inv = 1.f / (g_deg[n] + 1.f);
        float* o = out + (size_t)NN * 128 + (size_t)n * 3;
        o[0] = x[n * 3 + 0] + g_coord[n * 3 + 0] * inv;
        o[1] = x[n * 3 + 1] + g_coord[n * 3 + 1] * inv;
        o[2] = x[n * 3 + 2] + g_coord[n * 3 + 2] * inv;
    }
}

extern "C" void kernel_launch(void* const* d_in, const int* in_sizes, int n_in,
                              void* d_out, int out_size) {
    const float* h    = (const float*)d_in[0];
    const float* x    = (const float*)d_in[1];
    const float* ea   = (const float*)d_in[2];
    const float* temb = (const float*)d_in[3];
    const float* We1w = (const float*)d_in[4];
    const float* We1b = (const float*)d_in[5];
    const float* We2w = (const float*)d_in[6];
    const float* We2b = (const float*)d_in[7];
    const float* Wattw = (const float*)d_in[8];
    const float* Wattb = (const float*)d_in[9];
    const float* Wx1w = (const float*)d_in[10];
    const float* Wx1b = (const float*)d_in[11];
    const float* Wx2w = (const float*)d_in[12];
    const float* Wx2b = (const float*)d_in[13];
    const float* Wh1w = (const float*)d_in[14];
    const float* Wh1b = (const float*)d_in[15];
    const float* Wh2w = (const float*)d_in[16];
    const float* Wh2b = (const float*)d_in[17];
    const int*   eidx = (const int*)d_in[18];
    float* out = (float*)d_out;

    const int smA = 128 * (HSTR + KSTR + TSTR) * 2;
    const int smB = 128 * (HSTR + KSTR + ESTR) * 2 +
                    (128 * 5 + 256 + 384) * 4 + 256 * 4 + 256;
    const int smC = 128 * (HSTR + KSTR) * 2 + 256 * 4;
    cudaFuncSetAttribute(kA, cudaFuncAttributeMaxDynamicSharedMemorySize, smA);
    cudaFuncSetAttribute(kB, cudaFuncAttributeMaxDynamicSharedMemorySize, smB);
    cudaFuncSetAttribute(kC, cudaFuncAttributeMaxDynamicSharedMemorySize, smC);

    kZero<<<2048, 256>>>();
    kW<<<292, 256>>>(We1w, Wh1w, Wh2w);
    kWx<<<130, 256>>>(We2w, Wx1w, Wh1w, Wattw, We2b, Wattb);
    kA<<<(NN + 127) / 128, 256, smA>>>(h, temb, We1b);
    kB<<<EE / 256, 256, smB>>>(x, ea, eidx, Wx1b, Wx2w, Wx2b);
    kC<<<(NN + 127) / 128, 256, smC>>>(h, Wh1b, Wh2b, out);
    kX<<<(NN + 255) / 256, 256>>>(x, out);
}